// round 3
// baseline (speedup 1.0000x reference)
#include <cuda_runtime.h>

#define NN    50000
#define EE    800000
#define ETOT  (EE + NN)
#define FIN   128
#define H1DIM 128   // HEADS*HID
#define NHEAD 8
#define CLS   40
#define NEG   0.2f

// ---------------- device scratch (static, allocation-free) ----------------
__device__ float g_h1[(size_t)NN * H1DIM];    // layer-1 pre-aggregation features
__device__ float g_hact[(size_t)NN * H1DIM];  // layer-1 output after bias+ELU
__device__ float g_e1s[NN * NHEAD];
__device__ float g_e1d[NN * NHEAD];
__device__ float g_h2[(size_t)NN * CLS];
__device__ float g_e2s[NN];
__device__ float g_e2d[NN];
__device__ int   g_rowptr[NN + 1];
__device__ int   g_counts[NN];
__device__ int   g_fill[NN];
__device__ int   g_srcs[ETOT];     // CSR-ordered sources
__device__ int   g_srcE[ETOT];     // normalized edge list (COO)
__device__ int   g_dstE[ETOT];
__device__ int   g_is64;

// ---------------- edge dtype detection + normalization ----------------
// JAX under default config silently downcasts int64 -> int32; handle both.
__global__ void detect_kernel(const void* ei) {
    const long long* e64 = (const long long*)ei;
    int ok = 1;
    for (int i = 0; i < 1024; i++) {
        long long v = e64[i];
        if (v < 0 || v >= NN) { ok = 0; break; }
    }
    g_is64 = ok;
}

__global__ void convert_kernel(const void* ei) {
    int i = blockIdx.x * blockDim.x + threadIdx.x;
    if (i >= ETOT) return;
    int s, d;
    if (i >= EE) {
        s = d = i - EE;                      // self-loops appended
    } else if (g_is64) {
        const long long* e = (const long long*)ei;
        s = (int)e[i]; d = (int)e[EE + i];
    } else {
        const int* e = (const int*)ei;
        s = e[i]; d = e[EE + i];
    }
    g_srcE[i] = s; g_dstE[i] = d;
}

// ---------------- CSR build ----------------
__global__ void zero_kernel() {
    int i = blockIdx.x * blockDim.x + threadIdx.x;
    if (i < NN) { g_counts[i] = 0; g_fill[i] = 0; }
}

__global__ void hist_kernel() {
    int i = blockIdx.x * blockDim.x + threadIdx.x;
    if (i >= ETOT) return;
    atomicAdd(&g_counts[g_dstE[i]], 1);
}

__global__ void scan_kernel() {
    __shared__ int sh[1024];
    __shared__ int carry;
    int tid = threadIdx.x;
    if (tid == 0) { carry = 0; g_rowptr[0] = 0; }
    __syncthreads();
    for (int base = 0; base < NN; base += 1024) {
        int v = (base + tid < NN) ? g_counts[base + tid] : 0;
        sh[tid] = v;
        __syncthreads();
        for (int off = 1; off < 1024; off <<= 1) {
            int t = (tid >= off) ? sh[tid - off] : 0;
            __syncthreads();
            sh[tid] += t;
            __syncthreads();
        }
        int c = carry;
        if (base + tid < NN) g_rowptr[base + tid + 1] = c + sh[tid];
        __syncthreads();
        if (tid == 0) carry = c + sh[1023];
        __syncthreads();
    }
}

__global__ void scatter_kernel() {
    int i = blockIdx.x * blockDim.x + threadIdx.x;
    if (i >= ETOT) return;
    int d = g_dstE[i];
    int pos = g_rowptr[d] + atomicAdd(&g_fill[d], 1);
    g_srcs[pos] = g_srcE[i];
}

// ---------------- GEMM1: h1 = x @ W1, fused e_src1/e_dst1 ----------------
// block = 128 threads (one per output col), 4 rows per block.
__global__ void gemm1_kernel(const float* __restrict__ x,
                             const float* __restrict__ W1,
                             const float* __restrict__ as1,
                             const float* __restrict__ ad1) {
    const int t = threadIdx.x;           // output column 0..127
    const int row0 = blockIdx.x * 4;     // NN % 4 == 0
    __shared__ float xt[FIN * 4];        // transposed: xt[k*4 + r]

#pragma unroll
    for (int r = 0; r < 4; r++)
        xt[t * 4 + r] = x[(size_t)(row0 + r) * FIN + t];
    __syncthreads();

    float a0 = 0.f, a1 = 0.f, a2 = 0.f, a3 = 0.f;
#pragma unroll 8
    for (int k = 0; k < FIN; k++) {
        float w = __ldg(&W1[k * H1DIM + t]);
        float4 xv = *(const float4*)&xt[k * 4];
        a0 = fmaf(w, xv.x, a0);
        a1 = fmaf(w, xv.y, a1);
        a2 = fmaf(w, xv.z, a2);
        a3 = fmaf(w, xv.w, a3);
    }

    float asv = __ldg(&as1[t]), adv = __ldg(&ad1[t]);
    float accs[4] = {a0, a1, a2, a3};
#pragma unroll
    for (int r = 0; r < 4; r++) {
        g_h1[(size_t)(row0 + r) * H1DIM + t] = accs[r];
        float ps = accs[r] * asv;
        float pd = accs[r] * adv;
#pragma unroll
        for (int off = 8; off > 0; off >>= 1) {
            ps += __shfl_down_sync(0xffffffffu, ps, off, 16);
            pd += __shfl_down_sync(0xffffffffu, pd, off, 16);
        }
        if ((t & 15) == 0) {
            g_e1s[(row0 + r) * NHEAD + (t >> 4)] = ps;
            g_e1d[(row0 + r) * NHEAD + (t >> 4)] = pd;
        }
    }
}

// ---------------- layer-1 aggregation: warp per dst node ----------------
__global__ void agg1_kernel(const float* __restrict__ b1) {
    int gw = (blockIdx.x * blockDim.x + threadIdx.x) >> 5;
    int lane = threadIdx.x & 31;
    if (gw >= NN) return;
    const int node = gw;
    const int beg = g_rowptr[node];
    const int end = g_rowptr[node + 1];

    float ed[8];
    {
        const float4* pd = (const float4*)(g_e1d + node * NHEAD);
        float4 d0 = pd[0], d1 = pd[1];
        ed[0] = d0.x; ed[1] = d0.y; ed[2] = d0.z; ed[3] = d0.w;
        ed[4] = d1.x; ed[5] = d1.y; ed[6] = d1.z; ed[7] = d1.w;
    }

    // pass 1: per-head max over incoming edges (lanes stride edges)
    float m[8];
#pragma unroll
    for (int h = 0; h < 8; h++) m[h] = -1e30f;
    for (int i = beg + lane; i < end; i += 32) {
        int s = g_srcs[i];
        const float4* ps = (const float4*)(g_e1s + s * NHEAD);
        float4 s0 = ps[0], s1 = ps[1];
        float ev[8] = {s0.x, s0.y, s0.z, s0.w, s1.x, s1.y, s1.z, s1.w};
#pragma unroll
        for (int h = 0; h < 8; h++) {
            float a = ev[h] + ed[h];
            a = a > 0.f ? a : NEG * a;
            m[h] = fmaxf(m[h], a);
        }
    }
#pragma unroll
    for (int off = 16; off > 0; off >>= 1)
#pragma unroll
        for (int h = 0; h < 8; h++)
            m[h] = fmaxf(m[h], __shfl_xor_sync(0xffffffffu, m[h], off));

    // pass 2: 4 edges/iter; each lane computes exp for one (edge, head)
    const int eh = lane & 7;       // head this lane computes w for
    const int sub = lane >> 3;     // which of the 4 edges
    const int myhead = lane >> 2;  // head owning this lane's 4 channels
    // select m/ed without dynamic register indexing (avoid local-mem spill)
    float mh = m[0], edh = ed[0];
#pragma unroll
    for (int h = 1; h < 8; h++) {
        mh = (eh == h) ? m[h] : mh;
        edh = (eh == h) ? ed[h] : edh;
    }

    float acc0 = 0.f, acc1 = 0.f, acc2 = 0.f, acc3 = 0.f, ssum = 0.f;
    for (int i = beg; i < end; i += 4) {
        int ei = i + sub;
        int s = 0;
        float w = 0.f;
        if (ei < end) {
            s = g_srcs[ei];
            float a = g_e1s[s * NHEAD + eh] + edh;
            a = a > 0.f ? a : NEG * a;
            w = __expf(a - mh);
        }
#pragma unroll
        for (int j = 0; j < 4; j++) {
            float wj = __shfl_sync(0xffffffffu, w, (j << 3) + myhead);
            int   sj = __shfl_sync(0xffffffffu, s, j << 3);
            if (i + j < end) {
                const float4 hv = *(const float4*)(g_h1 + (size_t)sj * H1DIM + lane * 4);
                acc0 = fmaf(wj, hv.x, acc0);
                acc1 = fmaf(wj, hv.y, acc1);
                acc2 = fmaf(wj, hv.z, acc2);
                acc3 = fmaf(wj, hv.w, acc3);
                ssum += wj;
            }
        }
    }

    float inv = 1.f / (ssum + 1e-16f);
    float4 bv = *(const float4*)(b1 + lane * 4);
    float v0 = acc0 * inv + bv.x;
    float v1 = acc1 * inv + bv.y;
    float v2 = acc2 * inv + bv.z;
    float v3 = acc3 * inv + bv.w;
    // ELU
    v0 = v0 > 0.f ? v0 : (__expf(v0) - 1.f);
    v1 = v1 > 0.f ? v1 : (__expf(v1) - 1.f);
    v2 = v2 > 0.f ? v2 : (__expf(v2) - 1.f);
    v3 = v3 > 0.f ? v3 : (__expf(v3) - 1.f);
    float4 outv = make_float4(v0, v1, v2, v3);
    *(float4*)(g_hact + (size_t)node * H1DIM + lane * 4) = outv;
}

// ---------------- GEMM2: h2 = hact @ W2, fused e_src2/e_dst2 ----------------
// warp per row; W2 transposed into smem per block.
__global__ void gemm2_kernel(const float* __restrict__ W2,
                             const float* __restrict__ as2,
                             const float* __restrict__ ad2) {
    __shared__ float W2T[CLS * FIN];  // 20 KB
    int tid = threadIdx.x;
    for (int i = tid; i < CLS * FIN; i += blockDim.x) {
        int c = i >> 7, k = i & 127;
        W2T[i] = W2[k * CLS + c];
    }
    __syncthreads();

    int gw = blockIdx.x * (blockDim.x >> 5) + (tid >> 5);
    int lane = tid & 31;
    if (gw >= NN) return;
    const int row = gw;

    float4 xv = *(const float4*)(g_hact + (size_t)row * FIN + lane * 4);
    float es = 0.f, edv = 0.f, v0 = 0.f, v1 = 0.f;
#pragma unroll 4
    for (int c = 0; c < CLS; c++) {
        float4 wv = *(const float4*)&W2T[c * FIN + lane * 4];
        float p = xv.x * wv.x + xv.y * wv.y + xv.z * wv.z + xv.w * wv.w;
#pragma unroll
        for (int off = 16; off > 0; off >>= 1)
            p += __shfl_xor_sync(0xffffffffu, p, off);
        es  = fmaf(p, __ldg(&as2[c]), es);
        edv = fmaf(p, __ldg(&ad2[c]), edv);
        if ((c & 31) == lane) { if (c < 32) v0 = p; else v1 = p; }
    }
    g_h2[(size_t)row * CLS + lane] = v0;
    if (lane < 8) g_h2[(size_t)row * CLS + 32 + lane] = v1;
    if (lane == 0) { g_e2s[row] = es; g_e2d[row] = edv; }
}

// ---------------- layer-2 aggregation: warp per dst node ----------------
__global__ void agg2_kernel(const float* __restrict__ b2, float* __restrict__ out) {
    int gw = (blockIdx.x * blockDim.x + threadIdx.x) >> 5;
    int lane = threadIdx.x & 31;
    if (gw >= NN) return;
    const int node = gw;
    const int beg = g_rowptr[node];
    const int end = g_rowptr[node + 1];
    const float edn = g_e2d[node];

    float m = -1e30f;
    for (int i = beg + lane; i < end; i += 32) {
        float a = g_e2s[g_srcs[i]] + edn;
        a = a > 0.f ? a : NEG * a;
        m = fmaxf(m, a);
    }
#pragma unroll
    for (int off = 16; off > 0; off >>= 1)
        m = fmaxf(m, __shfl_xor_sync(0xffffffffu, m, off));

    float acc0 = 0.f, acc1 = 0.f, ss = 0.f;
    for (int i = beg; i < end; i += 32) {
        int ei = i + lane;
        int s = 0;
        float w = 0.f;
        if (ei < end) {
            s = g_srcs[ei];
            float a = g_e2s[s] + edn;
            a = a > 0.f ? a : NEG * a;
            w = __expf(a - m);
        }
        int cnt = min(32, end - i);
        for (int j = 0; j < cnt; j++) {
            float wj = __shfl_sync(0xffffffffu, w, j);
            int   sj = __shfl_sync(0xffffffffu, s, j);
            acc0 = fmaf(wj, g_h2[(size_t)sj * CLS + lane], acc0);
            if (lane < 8)
                acc1 = fmaf(wj, g_h2[(size_t)sj * CLS + 32 + lane], acc1);
            ss += wj;
        }
    }
    float inv = 1.f / (ss + 1e-16f);
    out[(size_t)node * CLS + lane] = acc0 * inv + __ldg(&b2[lane]);
    if (lane < 8)
        out[(size_t)node * CLS + 32 + lane] = acc1 * inv + __ldg(&b2[32 + lane]);
}

// ---------------- launch ----------------
extern "C" void kernel_launch(void* const* d_in, const int* in_sizes, int n_in,
                              void* d_out, int out_size) {
    const float* x   = (const float*)d_in[0];
    const void*  ei  = d_in[1];
    const float* W1  = (const float*)d_in[2];
    const float* as1 = (const float*)d_in[3];
    const float* ad1 = (const float*)d_in[4];
    const float* b1  = (const float*)d_in[5];
    const float* W2  = (const float*)d_in[6];
    const float* as2 = (const float*)d_in[7];
    const float* ad2 = (const float*)d_in[8];
    const float* b2  = (const float*)d_in[9];
    float* out = (float*)d_out;

    detect_kernel<<<1, 1>>>(ei);
    convert_kernel<<<(ETOT + 255) / 256, 256>>>(ei);
    zero_kernel<<<(NN + 255) / 256, 256>>>();
    gemm1_kernel<<<NN / 4, 128>>>(x, W1, as1, ad1);
    hist_kernel<<<(ETOT + 255) / 256, 256>>>();
    scan_kernel<<<1, 1024>>>();
    scatter_kernel<<<(ETOT + 255) / 256, 256>>>();
    agg1_kernel<<<(NN + 7) / 8, 256>>>(b1);
    gemm2_kernel<<<(NN + 7) / 8, 256>>>(W2, as2, ad2);
    agg2_kernel<<<(NN + 7) / 8, 256>>>(b2, out);
}

// round 4
// speedup vs baseline: 1.0003x; 1.0003x over previous
#include <cuda_runtime.h>

#define NN    50000
#define EE    800000
#define ETOT  (EE + NN)
#define FIN   128
#define H1DIM 128   // HEADS*HID
#define NHEAD 8
#define CLS   40
#define NEG   0.2f

// ---------------- device scratch (static, allocation-free) ----------------
__device__ float g_h1[(size_t)NN * H1DIM];    // layer-1 pre-aggregation features
__device__ float g_hact[(size_t)NN * H1DIM];  // layer-1 output after bias+ELU
__device__ float g_e1s[NN * NHEAD];
__device__ float g_e1d[NN * NHEAD];
__device__ float g_h2[(size_t)NN * CLS];
__device__ float g_e2s[NN];
__device__ float g_e2d[NN];
__device__ int   g_rowptr[NN + 1];
__device__ int   g_counts[NN];
__device__ int   g_fill[NN];
__device__ int   g_srcs[ETOT];     // CSR-ordered sources
__device__ int   g_srcE[ETOT];     // normalized edge list (COO)
__device__ int   g_dstE[ETOT];
__device__ int   g_is64;

// ---------------- edge dtype detection + normalization ----------------
// JAX under default config silently downcasts int64 -> int32; handle both.
__global__ void detect_kernel(const void* ei) {
    const long long* e64 = (const long long*)ei;
    int ok = 1;
    for (int i = 0; i < 1024; i++) {
        long long v = e64[i];
        if (v < 0 || v >= NN) { ok = 0; break; }
    }
    g_is64 = ok;
}

__global__ void convert_kernel(const void* ei) {
    int i = blockIdx.x * blockDim.x + threadIdx.x;
    if (i >= ETOT) return;
    int s, d;
    if (i >= EE) {
        s = d = i - EE;                      // self-loops appended
    } else if (g_is64) {
        const long long* e = (const long long*)ei;
        s = (int)e[i]; d = (int)e[EE + i];
    } else {
        const int* e = (const int*)ei;
        s = e[i]; d = e[EE + i];
    }
    g_srcE[i] = s; g_dstE[i] = d;
}

// ---------------- CSR build ----------------
__global__ void zero_kernel() {
    int i = blockIdx.x * blockDim.x + threadIdx.x;
    if (i < NN) { g_counts[i] = 0; g_fill[i] = 0; }
}

__global__ void hist_kernel() {
    int i = blockIdx.x * blockDim.x + threadIdx.x;
    if (i >= ETOT) return;
    atomicAdd(&g_counts[g_dstE[i]], 1);
}

__global__ void scan_kernel() {
    __shared__ int sh[1024];
    __shared__ int carry;
    int tid = threadIdx.x;
    if (tid == 0) { carry = 0; g_rowptr[0] = 0; }
    __syncthreads();
    for (int base = 0; base < NN; base += 1024) {
        int v = (base + tid < NN) ? g_counts[base + tid] : 0;
        sh[tid] = v;
        __syncthreads();
        for (int off = 1; off < 1024; off <<= 1) {
            int t = (tid >= off) ? sh[tid - off] : 0;
            __syncthreads();
            sh[tid] += t;
            __syncthreads();
        }
        int c = carry;
        if (base + tid < NN) g_rowptr[base + tid + 1] = c + sh[tid];
        __syncthreads();
        if (tid == 0) carry = c + sh[1023];
        __syncthreads();
    }
}

__global__ void scatter_kernel() {
    int i = blockIdx.x * blockDim.x + threadIdx.x;
    if (i >= ETOT) return;
    int d = g_dstE[i];
    int pos = g_rowptr[d] + atomicAdd(&g_fill[d], 1);
    g_srcs[pos] = g_srcE[i];
}

// ---------------- GEMM1: h1 = x @ W1, fused e_src1/e_dst1 ----------------
// block = 128 threads (one per output col), 4 rows per block.
__global__ void gemm1_kernel(const float* __restrict__ x,
                             const float* __restrict__ W1,
                             const float* __restrict__ as1,
                             const float* __restrict__ ad1) {
    const int t = threadIdx.x;           // output column 0..127
    const int row0 = blockIdx.x * 4;     // NN % 4 == 0
    __shared__ float xt[FIN * 4];        // transposed: xt[k*4 + r]

#pragma unroll
    for (int r = 0; r < 4; r++)
        xt[t * 4 + r] = x[(size_t)(row0 + r) * FIN + t];
    __syncthreads();

    float a0 = 0.f, a1 = 0.f, a2 = 0.f, a3 = 0.f;
#pragma unroll 8
    for (int k = 0; k < FIN; k++) {
        float w = __ldg(&W1[k * H1DIM + t]);
        float4 xv = *(const float4*)&xt[k * 4];
        a0 = fmaf(w, xv.x, a0);
        a1 = fmaf(w, xv.y, a1);
        a2 = fmaf(w, xv.z, a2);
        a3 = fmaf(w, xv.w, a3);
    }

    float asv = __ldg(&as1[t]), adv = __ldg(&ad1[t]);
    float accs[4] = {a0, a1, a2, a3};
#pragma unroll
    for (int r = 0; r < 4; r++) {
        g_h1[(size_t)(row0 + r) * H1DIM + t] = accs[r];
        float ps = accs[r] * asv;
        float pd = accs[r] * adv;
#pragma unroll
        for (int off = 8; off > 0; off >>= 1) {
            ps += __shfl_down_sync(0xffffffffu, ps, off, 16);
            pd += __shfl_down_sync(0xffffffffu, pd, off, 16);
        }
        if ((t & 15) == 0) {
            g_e1s[(row0 + r) * NHEAD + (t >> 4)] = ps;
            g_e1d[(row0 + r) * NHEAD + (t >> 4)] = pd;
        }
    }
}

// ---------------- layer-1 aggregation: warp per dst node ----------------
__global__ void agg1_kernel(const float* __restrict__ b1) {
    int gw = (blockIdx.x * blockDim.x + threadIdx.x) >> 5;
    int lane = threadIdx.x & 31;
    if (gw >= NN) return;
    const int node = gw;
    const int beg = g_rowptr[node];
    const int end = g_rowptr[node + 1];

    float ed[8];
    {
        const float4* pd = (const float4*)(g_e1d + node * NHEAD);
        float4 d0 = pd[0], d1 = pd[1];
        ed[0] = d0.x; ed[1] = d0.y; ed[2] = d0.z; ed[3] = d0.w;
        ed[4] = d1.x; ed[5] = d1.y; ed[6] = d1.z; ed[7] = d1.w;
    }

    // pass 1: per-head max over incoming edges (lanes stride edges)
    float m[8];
#pragma unroll
    for (int h = 0; h < 8; h++) m[h] = -1e30f;
    for (int i = beg + lane; i < end; i += 32) {
        int s = g_srcs[i];
        const float4* ps = (const float4*)(g_e1s + s * NHEAD);
        float4 s0 = ps[0], s1 = ps[1];
        float ev[8] = {s0.x, s0.y, s0.z, s0.w, s1.x, s1.y, s1.z, s1.w};
#pragma unroll
        for (int h = 0; h < 8; h++) {
            float a = ev[h] + ed[h];
            a = a > 0.f ? a : NEG * a;
            m[h] = fmaxf(m[h], a);
        }
    }
#pragma unroll
    for (int off = 16; off > 0; off >>= 1)
#pragma unroll
        for (int h = 0; h < 8; h++)
            m[h] = fmaxf(m[h], __shfl_xor_sync(0xffffffffu, m[h], off));

    // pass 2: 4 edges/iter; each lane computes exp for one (edge, head)
    const int eh = lane & 7;       // head this lane computes w for
    const int sub = lane >> 3;     // which of the 4 edges
    const int myhead = lane >> 2;  // head owning this lane's 4 channels
    // select m/ed without dynamic register indexing (avoid local-mem spill)
    float mh = m[0], edh = ed[0];
#pragma unroll
    for (int h = 1; h < 8; h++) {
        mh = (eh == h) ? m[h] : mh;
        edh = (eh == h) ? ed[h] : edh;
    }

    float acc0 = 0.f, acc1 = 0.f, acc2 = 0.f, acc3 = 0.f, ssum = 0.f;
    for (int i = beg; i < end; i += 4) {
        int ei = i + sub;
        int s = 0;
        float w = 0.f;
        if (ei < end) {
            s = g_srcs[ei];
            float a = g_e1s[s * NHEAD + eh] + edh;
            a = a > 0.f ? a : NEG * a;
            w = __expf(a - mh);
        }
#pragma unroll
        for (int j = 0; j < 4; j++) {
            float wj = __shfl_sync(0xffffffffu, w, (j << 3) + myhead);
            int   sj = __shfl_sync(0xffffffffu, s, j << 3);
            if (i + j < end) {
                const float4 hv = *(const float4*)(g_h1 + (size_t)sj * H1DIM + lane * 4);
                acc0 = fmaf(wj, hv.x, acc0);
                acc1 = fmaf(wj, hv.y, acc1);
                acc2 = fmaf(wj, hv.z, acc2);
                acc3 = fmaf(wj, hv.w, acc3);
                ssum += wj;
            }
        }
    }

    float inv = 1.f / (ssum + 1e-16f);
    float4 bv = *(const float4*)(b1 + lane * 4);
    float v0 = acc0 * inv + bv.x;
    float v1 = acc1 * inv + bv.y;
    float v2 = acc2 * inv + bv.z;
    float v3 = acc3 * inv + bv.w;
    // ELU
    v0 = v0 > 0.f ? v0 : (__expf(v0) - 1.f);
    v1 = v1 > 0.f ? v1 : (__expf(v1) - 1.f);
    v2 = v2 > 0.f ? v2 : (__expf(v2) - 1.f);
    v3 = v3 > 0.f ? v3 : (__expf(v3) - 1.f);
    float4 outv = make_float4(v0, v1, v2, v3);
    *(float4*)(g_hact + (size_t)node * H1DIM + lane * 4) = outv;
}

// ---------------- GEMM2: h2 = hact @ W2, fused e_src2/e_dst2 ----------------
// warp per row; W2 transposed into smem per block.
__global__ void gemm2_kernel(const float* __restrict__ W2,
                             const float* __restrict__ as2,
                             const float* __restrict__ ad2) {
    __shared__ float W2T[CLS * FIN];  // 20 KB
    int tid = threadIdx.x;
    for (int i = tid; i < CLS * FIN; i += blockDim.x) {
        int c = i >> 7, k = i & 127;
        W2T[i] = W2[k * CLS + c];
    }
    __syncthreads();

    int gw = blockIdx.x * (blockDim.x >> 5) + (tid >> 5);
    int lane = tid & 31;
    if (gw >= NN) return;
    const int row = gw;

    float4 xv = *(const float4*)(g_hact + (size_t)row * FIN + lane * 4);
    float es = 0.f, edv = 0.f, v0 = 0.f, v1 = 0.f;
#pragma unroll 4
    for (int c = 0; c < CLS; c++) {
        float4 wv = *(const float4*)&W2T[c * FIN + lane * 4];
        float p = xv.x * wv.x + xv.y * wv.y + xv.z * wv.z + xv.w * wv.w;
#pragma unroll
        for (int off = 16; off > 0; off >>= 1)
            p += __shfl_xor_sync(0xffffffffu, p, off);
        es  = fmaf(p, __ldg(&as2[c]), es);
        edv = fmaf(p, __ldg(&ad2[c]), edv);
        if ((c & 31) == lane) { if (c < 32) v0 = p; else v1 = p; }
    }
    g_h2[(size_t)row * CLS + lane] = v0;
    if (lane < 8) g_h2[(size_t)row * CLS + 32 + lane] = v1;
    if (lane == 0) { g_e2s[row] = es; g_e2d[row] = edv; }
}

// ---------------- layer-2 aggregation: warp per dst node ----------------
__global__ void agg2_kernel(const float* __restrict__ b2, float* __restrict__ out) {
    int gw = (blockIdx.x * blockDim.x + threadIdx.x) >> 5;
    int lane = threadIdx.x & 31;
    if (gw >= NN) return;
    const int node = gw;
    const int beg = g_rowptr[node];
    const int end = g_rowptr[node + 1];
    const float edn = g_e2d[node];

    float m = -1e30f;
    for (int i = beg + lane; i < end; i += 32) {
        float a = g_e2s[g_srcs[i]] + edn;
        a = a > 0.f ? a : NEG * a;
        m = fmaxf(m, a);
    }
#pragma unroll
    for (int off = 16; off > 0; off >>= 1)
        m = fmaxf(m, __shfl_xor_sync(0xffffffffu, m, off));

    float acc0 = 0.f, acc1 = 0.f, ss = 0.f;
    for (int i = beg; i < end; i += 32) {
        int ei = i + lane;
        int s = 0;
        float w = 0.f;
        if (ei < end) {
            s = g_srcs[ei];
            float a = g_e2s[s] + edn;
            a = a > 0.f ? a : NEG * a;
            w = __expf(a - m);
        }
        int cnt = min(32, end - i);
        for (int j = 0; j < cnt; j++) {
            float wj = __shfl_sync(0xffffffffu, w, j);
            int   sj = __shfl_sync(0xffffffffu, s, j);
            acc0 = fmaf(wj, g_h2[(size_t)sj * CLS + lane], acc0);
            if (lane < 8)
                acc1 = fmaf(wj, g_h2[(size_t)sj * CLS + 32 + lane], acc1);
            ss += wj;
        }
    }
    float inv = 1.f / (ss + 1e-16f);
    out[(size_t)node * CLS + lane] = acc0 * inv + __ldg(&b2[lane]);
    if (lane < 8)
        out[(size_t)node * CLS + 32 + lane] = acc1 * inv + __ldg(&b2[32 + lane]);
}

// ---------------- launch ----------------
extern "C" void kernel_launch(void* const* d_in, const int* in_sizes, int n_in,
                              void* d_out, int out_size) {
    const float* x   = (const float*)d_in[0];
    const void*  ei  = d_in[1];
    const float* W1  = (const float*)d_in[2];
    const float* as1 = (const float*)d_in[3];
    const float* ad1 = (const float*)d_in[4];
    const float* b1  = (const float*)d_in[5];
    const float* W2  = (const float*)d_in[6];
    const float* as2 = (const float*)d_in[7];
    const float* ad2 = (const float*)d_in[8];
    const float* b2  = (const float*)d_in[9];
    float* out = (float*)d_out;

    detect_kernel<<<1, 1>>>(ei);
    convert_kernel<<<(ETOT + 255) / 256, 256>>>(ei);
    zero_kernel<<<(NN + 255) / 256, 256>>>();
    gemm1_kernel<<<NN / 4, 128>>>(x, W1, as1, ad1);
    hist_kernel<<<(ETOT + 255) / 256, 256>>>();
    scan_kernel<<<1, 1024>>>();
    scatter_kernel<<<(ETOT + 255) / 256, 256>>>();
    agg1_kernel<<<(NN + 7) / 8, 256>>>(b1);
    gemm2_kernel<<<(NN + 7) / 8, 256>>>(W2, as2, ad2);
    agg2_kernel<<<(NN + 7) / 8, 256>>>(b2, out);
}

// round 5
// speedup vs baseline: 1.0045x; 1.0042x over previous
#include <cuda_runtime.h>

#define NN    50000
#define EE    800000
#define ETOT  (EE + NN)
#define FIN   128
#define H1DIM 128   // HEADS*HID
#define NHEAD 8
#define CLS   40
#define NEG   0.2f

// ---------------- device scratch (static, allocation-free) ----------------
__device__ float g_h1[(size_t)NN * H1DIM];    // layer-1 pre-aggregation features
__device__ float g_hact[(size_t)NN * H1DIM];  // layer-1 output after bias+ELU
__device__ float g_e1s[NN * NHEAD];
__device__ float g_e1d[NN * NHEAD];
__device__ float g_h2[(size_t)NN * CLS];
__device__ float g_e2s[NN];
__device__ float g_e2d[NN];
__device__ int   g_rowptr[NN + 1];
__device__ int   g_counts[NN];
__device__ int   g_fill[NN];
__device__ int   g_srcs[ETOT];     // CSR-ordered sources
__device__ int   g_srcE[ETOT];     // normalized edge list (COO)
__device__ int   g_dstE[ETOT];
__device__ int   g_is64;

// ---------------- edge dtype detection + normalization ----------------
// JAX under default config silently downcasts int64 -> int32; handle both.
__global__ void detect_kernel(const void* ei) {
    const long long* e64 = (const long long*)ei;
    int ok = 1;
    for (int i = 0; i < 1024; i++) {
        long long v = e64[i];
        if (v < 0 || v >= NN) { ok = 0; break; }
    }
    g_is64 = ok;
}

__global__ void convert_kernel(const void* ei) {
    int i = blockIdx.x * blockDim.x + threadIdx.x;
    if (i >= ETOT) return;
    int s, d;
    if (i >= EE) {
        s = d = i - EE;                      // self-loops appended
    } else if (g_is64) {
        const long long* e = (const long long*)ei;
        s = (int)e[i]; d = (int)e[EE + i];
    } else {
        const int* e = (const int*)ei;
        s = e[i]; d = e[EE + i];
    }
    g_srcE[i] = s; g_dstE[i] = d;
}

// ---------------- CSR build ----------------
__global__ void zero_kernel() {
    int i = blockIdx.x * blockDim.x + threadIdx.x;
    if (i < NN) { g_counts[i] = 0; g_fill[i] = 0; }
}

__global__ void hist_kernel() {
    int i = blockIdx.x * blockDim.x + threadIdx.x;
    if (i >= ETOT) return;
    atomicAdd(&g_counts[g_dstE[i]], 1);
}

__global__ void scan_kernel() {
    __shared__ int sh[1024];
    __shared__ int carry;
    int tid = threadIdx.x;
    if (tid == 0) { carry = 0; g_rowptr[0] = 0; }
    __syncthreads();
    for (int base = 0; base < NN; base += 1024) {
        int v = (base + tid < NN) ? g_counts[base + tid] : 0;
        sh[tid] = v;
        __syncthreads();
        for (int off = 1; off < 1024; off <<= 1) {
            int t = (tid >= off) ? sh[tid - off] : 0;
            __syncthreads();
            sh[tid] += t;
            __syncthreads();
        }
        int c = carry;
        if (base + tid < NN) g_rowptr[base + tid + 1] = c + sh[tid];
        __syncthreads();
        if (tid == 0) carry = c + sh[1023];
        __syncthreads();
    }
}

__global__ void scatter_kernel() {
    int i = blockIdx.x * blockDim.x + threadIdx.x;
    if (i >= ETOT) return;
    int d = g_dstE[i];
    int pos = g_rowptr[d] + atomicAdd(&g_fill[d], 1);
    g_srcs[pos] = g_srcE[i];
}

// ---------------- GEMM1: h1 = x @ W1, fused e_src1/e_dst1 ----------------
// block = 128 threads (one per output col), 4 rows per block.
__global__ void gemm1_kernel(const float* __restrict__ x,
                             const float* __restrict__ W1,
                             const float* __restrict__ as1,
                             const float* __restrict__ ad1) {
    const int t = threadIdx.x;           // output column 0..127
    const int row0 = blockIdx.x * 4;     // NN % 4 == 0
    __shared__ float xt[FIN * 4];        // transposed: xt[k*4 + r]

#pragma unroll
    for (int r = 0; r < 4; r++)
        xt[t * 4 + r] = x[(size_t)(row0 + r) * FIN + t];
    __syncthreads();

    float a0 = 0.f, a1 = 0.f, a2 = 0.f, a3 = 0.f;
#pragma unroll 8
    for (int k = 0; k < FIN; k++) {
        float w = __ldg(&W1[k * H1DIM + t]);
        float4 xv = *(const float4*)&xt[k * 4];
        a0 = fmaf(w, xv.x, a0);
        a1 = fmaf(w, xv.y, a1);
        a2 = fmaf(w, xv.z, a2);
        a3 = fmaf(w, xv.w, a3);
    }

    float asv = __ldg(&as1[t]), adv = __ldg(&ad1[t]);
    float accs[4] = {a0, a1, a2, a3};
#pragma unroll
    for (int r = 0; r < 4; r++) {
        g_h1[(size_t)(row0 + r) * H1DIM + t] = accs[r];
        float ps = accs[r] * asv;
        float pd = accs[r] * adv;
#pragma unroll
        for (int off = 8; off > 0; off >>= 1) {
            ps += __shfl_down_sync(0xffffffffu, ps, off, 16);
            pd += __shfl_down_sync(0xffffffffu, pd, off, 16);
        }
        if ((t & 15) == 0) {
            g_e1s[(row0 + r) * NHEAD + (t >> 4)] = ps;
            g_e1d[(row0 + r) * NHEAD + (t >> 4)] = pd;
        }
    }
}

// ---------------- layer-1 aggregation: warp per dst node ----------------
__global__ void agg1_kernel(const float* __restrict__ b1) {
    int gw = (blockIdx.x * blockDim.x + threadIdx.x) >> 5;
    int lane = threadIdx.x & 31;
    if (gw >= NN) return;
    const int node = gw;
    const int beg = g_rowptr[node];
    const int end = g_rowptr[node + 1];

    float ed[8];
    {
        const float4* pd = (const float4*)(g_e1d + node * NHEAD);
        float4 d0 = pd[0], d1 = pd[1];
        ed[0] = d0.x; ed[1] = d0.y; ed[2] = d0.z; ed[3] = d0.w;
        ed[4] = d1.x; ed[5] = d1.y; ed[6] = d1.z; ed[7] = d1.w;
    }

    // pass 1: per-head max over incoming edges (lanes stride edges)
    float m[8];
#pragma unroll
    for (int h = 0; h < 8; h++) m[h] = -1e30f;
    for (int i = beg + lane; i < end; i += 32) {
        int s = g_srcs[i];
        const float4* ps = (const float4*)(g_e1s + s * NHEAD);
        float4 s0 = ps[0], s1 = ps[1];
        float ev[8] = {s0.x, s0.y, s0.z, s0.w, s1.x, s1.y, s1.z, s1.w};
#pragma unroll
        for (int h = 0; h < 8; h++) {
            float a = ev[h] + ed[h];
            a = a > 0.f ? a : NEG * a;
            m[h] = fmaxf(m[h], a);
        }
    }
#pragma unroll
    for (int off = 16; off > 0; off >>= 1)
#pragma unroll
        for (int h = 0; h < 8; h++)
            m[h] = fmaxf(m[h], __shfl_xor_sync(0xffffffffu, m[h], off));

    // pass 2: 4 edges/iter; each lane computes exp for one (edge, head)
    const int eh = lane & 7;       // head this lane computes w for
    const int sub = lane >> 3;     // which of the 4 edges
    const int myhead = lane >> 2;  // head owning this lane's 4 channels
    // select m/ed without dynamic register indexing (avoid local-mem spill)
    float mh = m[0], edh = ed[0];
#pragma unroll
    for (int h = 1; h < 8; h++) {
        mh = (eh == h) ? m[h] : mh;
        edh = (eh == h) ? ed[h] : edh;
    }

    float acc0 = 0.f, acc1 = 0.f, acc2 = 0.f, acc3 = 0.f, ssum = 0.f;
    for (int i = beg; i < end; i += 4) {
        int ei = i + sub;
        int s = 0;
        float w = 0.f;
        if (ei < end) {
            s = g_srcs[ei];
            float a = g_e1s[s * NHEAD + eh] + edh;
            a = a > 0.f ? a : NEG * a;
            w = __expf(a - mh);
        }
#pragma unroll
        for (int j = 0; j < 4; j++) {
            float wj = __shfl_sync(0xffffffffu, w, (j << 3) + myhead);
            int   sj = __shfl_sync(0xffffffffu, s, j << 3);
            if (i + j < end) {
                const float4 hv = *(const float4*)(g_h1 + (size_t)sj * H1DIM + lane * 4);
                acc0 = fmaf(wj, hv.x, acc0);
                acc1 = fmaf(wj, hv.y, acc1);
                acc2 = fmaf(wj, hv.z, acc2);
                acc3 = fmaf(wj, hv.w, acc3);
                ssum += wj;
            }
        }
    }

    float inv = 1.f / (ssum + 1e-16f);
    float4 bv = *(const float4*)(b1 + lane * 4);
    float v0 = acc0 * inv + bv.x;
    float v1 = acc1 * inv + bv.y;
    float v2 = acc2 * inv + bv.z;
    float v3 = acc3 * inv + bv.w;
    // ELU
    v0 = v0 > 0.f ? v0 : (__expf(v0) - 1.f);
    v1 = v1 > 0.f ? v1 : (__expf(v1) - 1.f);
    v2 = v2 > 0.f ? v2 : (__expf(v2) - 1.f);
    v3 = v3 > 0.f ? v3 : (__expf(v3) - 1.f);
    float4 outv = make_float4(v0, v1, v2, v3);
    *(float4*)(g_hact + (size_t)node * H1DIM + lane * 4) = outv;
}

// ---------------- GEMM2: h2 = hact @ W2, fused e_src2/e_dst2 ----------------
// warp per row; W2 transposed into smem per block.
__global__ void gemm2_kernel(const float* __restrict__ W2,
                             const float* __restrict__ as2,
                             const float* __restrict__ ad2) {
    __shared__ float W2T[CLS * FIN];  // 20 KB
    int tid = threadIdx.x;
    for (int i = tid; i < CLS * FIN; i += blockDim.x) {
        int c = i >> 7, k = i & 127;
        W2T[i] = W2[k * CLS + c];
    }
    __syncthreads();

    int gw = blockIdx.x * (blockDim.x >> 5) + (tid >> 5);
    int lane = tid & 31;
    if (gw >= NN) return;
    const int row = gw;

    float4 xv = *(const float4*)(g_hact + (size_t)row * FIN + lane * 4);
    float es = 0.f, edv = 0.f, v0 = 0.f, v1 = 0.f;
#pragma unroll 4
    for (int c = 0; c < CLS; c++) {
        float4 wv = *(const float4*)&W2T[c * FIN + lane * 4];
        float p = xv.x * wv.x + xv.y * wv.y + xv.z * wv.z + xv.w * wv.w;
#pragma unroll
        for (int off = 16; off > 0; off >>= 1)
            p += __shfl_xor_sync(0xffffffffu, p, off);
        es  = fmaf(p, __ldg(&as2[c]), es);
        edv = fmaf(p, __ldg(&ad2[c]), edv);
        if ((c & 31) == lane) { if (c < 32) v0 = p; else v1 = p; }
    }
    g_h2[(size_t)row * CLS + lane] = v0;
    if (lane < 8) g_h2[(size_t)row * CLS + 32 + lane] = v1;
    if (lane == 0) { g_e2s[row] = es; g_e2d[row] = edv; }
}

// ---------------- layer-2 aggregation: warp per dst node ----------------
__global__ void agg2_kernel(const float* __restrict__ b2, float* __restrict__ out) {
    int gw = (blockIdx.x * blockDim.x + threadIdx.x) >> 5;
    int lane = threadIdx.x & 31;
    if (gw >= NN) return;
    const int node = gw;
    const int beg = g_rowptr[node];
    const int end = g_rowptr[node + 1];
    const float edn = g_e2d[node];

    float m = -1e30f;
    for (int i = beg + lane; i < end; i += 32) {
        float a = g_e2s[g_srcs[i]] + edn;
        a = a > 0.f ? a : NEG * a;
        m = fmaxf(m, a);
    }
#pragma unroll
    for (int off = 16; off > 0; off >>= 1)
        m = fmaxf(m, __shfl_xor_sync(0xffffffffu, m, off));

    float acc0 = 0.f, acc1 = 0.f, ss = 0.f;
    for (int i = beg; i < end; i += 32) {
        int ei = i + lane;
        int s = 0;
        float w = 0.f;
        if (ei < end) {
            s = g_srcs[ei];
            float a = g_e2s[s] + edn;
            a = a > 0.f ? a : NEG * a;
            w = __expf(a - m);
        }
        int cnt = min(32, end - i);
        for (int j = 0; j < cnt; j++) {
            float wj = __shfl_sync(0xffffffffu, w, j);
            int   sj = __shfl_sync(0xffffffffu, s, j);
            acc0 = fmaf(wj, g_h2[(size_t)sj * CLS + lane], acc0);
            if (lane < 8)
                acc1 = fmaf(wj, g_h2[(size_t)sj * CLS + 32 + lane], acc1);
            ss += wj;
        }
    }
    float inv = 1.f / (ss + 1e-16f);
    out[(size_t)node * CLS + lane] = acc0 * inv + __ldg(&b2[lane]);
    if (lane < 8)
        out[(size_t)node * CLS + 32 + lane] = acc1 * inv + __ldg(&b2[32 + lane]);
}

// ---------------- launch ----------------
extern "C" void kernel_launch(void* const* d_in, const int* in_sizes, int n_in,
                              void* d_out, int out_size) {
    const float* x   = (const float*)d_in[0];
    const void*  ei  = d_in[1];
    const float* W1  = (const float*)d_in[2];
    const float* as1 = (const float*)d_in[3];
    const float* ad1 = (const float*)d_in[4];
    const float* b1  = (const float*)d_in[5];
    const float* W2  = (const float*)d_in[6];
    const float* as2 = (const float*)d_in[7];
    const float* ad2 = (const float*)d_in[8];
    const float* b2  = (const float*)d_in[9];
    float* out = (float*)d_out;

    detect_kernel<<<1, 1>>>(ei);
    convert_kernel<<<(ETOT + 255) / 256, 256>>>(ei);
    zero_kernel<<<(NN + 255) / 256, 256>>>();
    gemm1_kernel<<<NN / 4, 128>>>(x, W1, as1, ad1);
    hist_kernel<<<(ETOT + 255) / 256, 256>>>();
    scan_kernel<<<1, 1024>>>();
    scatter_kernel<<<(ETOT + 255) / 256, 256>>>();
    agg1_kernel<<<(NN + 7) / 8, 256>>>(b1);
    gemm2_kernel<<<(NN + 7) / 8, 256>>>(W2, as2, ad2);
    agg2_kernel<<<(NN + 7) / 8, 256>>>(b2, out);
}

// round 6
// speedup vs baseline: 1.5006x; 1.4938x over previous
#include <cuda_runtime.h>

#define NN    50000
#define EE    800000
#define ETOT  (EE + NN)
#define FIN   128
#define H1DIM 128   // HEADS*HID
#define NHEAD 8
#define CLS   40
#define NEG   0.2f
#define G1R   16    // rows per gemm1 block

// ---------------- device scratch (static, allocation-free) ----------------
__device__ float g_h1[(size_t)NN * H1DIM];
__device__ float g_hact[(size_t)NN * H1DIM];
__device__ float g_e1s[NN * NHEAD];
__device__ float g_e1d[NN * NHEAD];
__device__ float g_h2[(size_t)NN * CLS];
__device__ float g_e2s[NN];
__device__ float g_e2d[NN];
__device__ int   g_rowptr[NN + 1];
__device__ int   g_counts[NN];
__device__ int   g_fill[NN];
__device__ int   g_srcs[ETOT];
__device__ int   g_srcE[ETOT];
__device__ int   g_dstE[ETOT];
__device__ int   g_is64;

// ---------------- fast exp: pure FFMA/ALU, no MUFU ----------------
__device__ __forceinline__ float fexp(float x) {
    float t = x * 1.442695041f;
    t = fminf(fmaxf(t, -125.f), 125.f);
    float biased = t + 12582912.f;                    // round-to-nearest via magic
    int   ni = __float_as_int(biased) - 0x4B400000;
    float n  = biased - 12582912.f;
    float f  = fmaf(-n, 0.69314718056f, x);           // f = x - n*ln2, |f| <= 0.347
    float p  = fmaf(f, 8.3333333e-3f, 4.1666667e-2f); // e^f Taylor deg-5
    p = fmaf(p, f, 0.16666667f);
    p = fmaf(p, f, 0.5f);
    p = fmaf(p, f, 1.0f);
    p = fmaf(p, f, 1.0f);
    return p * __int_as_float((ni + 127) << 23);
}

// ---------------- edge dtype detection + normalization (+hist fused) ------
__global__ void detect_kernel(const void* ei) {
    const long long* e64 = (const long long*)ei;
    int ok = 1;
    for (int i = 0; i < 1024; i++) {
        long long v = e64[i];
        if (v < 0 || v >= NN) { ok = 0; break; }
    }
    g_is64 = ok;
}

__global__ void zero_kernel() {
    int i = blockIdx.x * blockDim.x + threadIdx.x;
    if (i < NN) { g_counts[i] = 0; g_fill[i] = 0; }
}

__global__ void convert_kernel(const void* ei) {
    int i = blockIdx.x * blockDim.x + threadIdx.x;
    if (i >= ETOT) return;
    int s, d;
    if (i >= EE) {
        s = d = i - EE;
    } else if (g_is64) {
        const long long* e = (const long long*)ei;
        s = (int)e[i]; d = (int)e[EE + i];
    } else {
        const int* e = (const int*)ei;
        s = e[i]; d = e[EE + i];
    }
    g_srcE[i] = s; g_dstE[i] = d;
    atomicAdd(&g_counts[d], 1);
}

// ---------------- shuffle-based single-block scan ----------------
__global__ void scan_kernel() {
    __shared__ int warp_sums[32];
    __shared__ int s_carry;
    int tid = threadIdx.x, lane = tid & 31, wid = tid >> 5;
    if (tid == 0) { s_carry = 0; g_rowptr[0] = 0; }
    __syncthreads();
    for (int base = 0; base < NN; base += 1024) {
        int idx = base + tid;
        int v = (idx < NN) ? g_counts[idx] : 0;
        int xs = v;
#pragma unroll
        for (int off = 1; off < 32; off <<= 1) {
            int y = __shfl_up_sync(0xffffffffu, xs, off);
            if (lane >= off) xs += y;
        }
        if (lane == 31) warp_sums[wid] = xs;
        __syncthreads();
        if (wid == 0) {
            int ws = warp_sums[lane];
#pragma unroll
            for (int off = 1; off < 32; off <<= 1) {
                int y = __shfl_up_sync(0xffffffffu, ws, off);
                if (lane >= off) ws += y;
            }
            warp_sums[lane] = ws;
        }
        __syncthreads();
        int off = ((wid > 0) ? warp_sums[wid - 1] : 0) + s_carry;
        if (idx < NN) g_rowptr[idx + 1] = xs + off;
        __syncthreads();
        if (tid == 0) s_carry += warp_sums[31];
        __syncthreads();
    }
}

__global__ void scatter_kernel() {
    int i = blockIdx.x * blockDim.x + threadIdx.x;
    if (i >= ETOT) return;
    int d = g_dstE[i];
    int pos = g_rowptr[d] + atomicAdd(&g_fill[d], 1);
    g_srcs[pos] = g_srcE[i];
}

// ---------------- GEMM1: h1 = x @ W1 (16 rows/block), fused e1s/e1d -------
__global__ void gemm1_kernel(const float* __restrict__ x,
                             const float* __restrict__ W1,
                             const float* __restrict__ as1,
                             const float* __restrict__ ad1) {
    const int t = threadIdx.x;             // output column 0..127
    const int row0 = blockIdx.x * G1R;     // 50000 % 16 == 0
    __shared__ float xs[G1R][FIN];         // [r][k], conflict-free writes

#pragma unroll
    for (int r = 0; r < G1R; r++)
        xs[r][t] = x[(size_t)(row0 + r) * FIN + t];
    __syncthreads();

    float acc[G1R];
#pragma unroll
    for (int r = 0; r < G1R; r++) acc[r] = 0.f;

#pragma unroll 4
    for (int k = 0; k < FIN; k += 4) {
        float w0 = __ldg(&W1[(k + 0) * H1DIM + t]);
        float w1 = __ldg(&W1[(k + 1) * H1DIM + t]);
        float w2 = __ldg(&W1[(k + 2) * H1DIM + t]);
        float w3 = __ldg(&W1[(k + 3) * H1DIM + t]);
#pragma unroll
        for (int r = 0; r < G1R; r++) {
            float4 xv = *(const float4*)&xs[r][k];
            acc[r] = fmaf(w0, xv.x, acc[r]);
            acc[r] = fmaf(w1, xv.y, acc[r]);
            acc[r] = fmaf(w2, xv.z, acc[r]);
            acc[r] = fmaf(w3, xv.w, acc[r]);
        }
    }

    float asv = __ldg(&as1[t]), adv = __ldg(&ad1[t]);
#pragma unroll
    for (int r = 0; r < G1R; r++) {
        g_h1[(size_t)(row0 + r) * H1DIM + t] = acc[r];
        float ps = acc[r] * asv;
        float pd = acc[r] * adv;
#pragma unroll
        for (int off = 8; off > 0; off >>= 1) {
            ps += __shfl_down_sync(0xffffffffu, ps, off, 16);
            pd += __shfl_down_sync(0xffffffffu, pd, off, 16);
        }
        if ((t & 15) == 0) {
            g_e1s[(row0 + r) * NHEAD + (t >> 4)] = ps;
            g_e1d[(row0 + r) * NHEAD + (t >> 4)] = pd;
        }
    }
}

// ---------------- layer-1 aggregation: warp per dst, no max pass ----------
__global__ void agg1_kernel(const float* __restrict__ b1) {
    int gw = (blockIdx.x * blockDim.x + threadIdx.x) >> 5;
    int lane = threadIdx.x & 31;
    if (gw >= NN) return;
    const int beg = g_rowptr[gw];
    const int end = g_rowptr[gw + 1];

    const int eh = lane & 7;       // head this lane computes weight for
    const int sub = lane >> 3;     // which of 4 edges
    const int myhead = lane >> 2;  // head owning this lane's 4 channels
    const float edh = g_e1d[gw * NHEAD + eh];

    float acc0 = 0.f, acc1 = 0.f, acc2 = 0.f, acc3 = 0.f, ssum = 0.f;
    for (int i = beg; i < end; i += 4) {
        int ei = i + sub;
        int s = 0;
        float w = 0.f;
        if (ei < end) {
            s = g_srcs[ei];
            float a = g_e1s[s * NHEAD + eh] + edh;
            a = a > 0.f ? a : NEG * a;
            w = fexp(a);
        }
#pragma unroll
        for (int j = 0; j < 4; j++) {
            float wj = __shfl_sync(0xffffffffu, w, (j << 3) + myhead);
            int   sj = __shfl_sync(0xffffffffu, s, j << 3);
            if (i + j < end) {
                const float4 hv = *(const float4*)(g_h1 + (size_t)sj * H1DIM + lane * 4);
                acc0 = fmaf(wj, hv.x, acc0);
                acc1 = fmaf(wj, hv.y, acc1);
                acc2 = fmaf(wj, hv.z, acc2);
                acc3 = fmaf(wj, hv.w, acc3);
                ssum += wj;
            }
        }
    }

    float inv = 1.f / (ssum + 1e-16f);
    float4 bv = *(const float4*)(b1 + lane * 4);
    float v0 = acc0 * inv + bv.x;
    float v1 = acc1 * inv + bv.y;
    float v2 = acc2 * inv + bv.z;
    float v3 = acc3 * inv + bv.w;
    v0 = v0 > 0.f ? v0 : (fexp(v0) - 1.f);
    v1 = v1 > 0.f ? v1 : (fexp(v1) - 1.f);
    v2 = v2 > 0.f ? v2 : (fexp(v2) - 1.f);
    v3 = v3 > 0.f ? v3 : (fexp(v3) - 1.f);
    *(float4*)(g_hact + (size_t)gw * H1DIM + lane * 4) = make_float4(v0, v1, v2, v3);
}

// ---------------- GEMM2: thread-per-row, W2^T in smem ----------------
__global__ void gemm2_kernel(const float* __restrict__ W2,
                             const float* __restrict__ as2,
                             const float* __restrict__ ad2) {
    __shared__ float W2T[CLS][FIN];   // [c][k], 20KB
    __shared__ float sas[CLS], sad[CLS];
    int tid = threadIdx.x;
    for (int i = tid; i < CLS * FIN; i += blockDim.x) {
        int c = i >> 7, k = i & 127;
        W2T[c][k] = W2[k * CLS + c];
    }
    if (tid < CLS) { sas[tid] = as2[tid]; sad[tid] = ad2[tid]; }
    __syncthreads();

    int row = blockIdx.x * blockDim.x + tid;
    if (row >= NN) return;
    const float* xr = g_hact + (size_t)row * FIN;

    float acc[CLS];
#pragma unroll
    for (int c = 0; c < CLS; c++) acc[c] = 0.f;

    for (int k = 0; k < FIN; k += 4) {
        float4 xv = *(const float4*)(xr + k);
#pragma unroll
        for (int c = 0; c < CLS; c++) {
            float4 wv = *(const float4*)&W2T[c][k];
            acc[c] = fmaf(xv.x, wv.x, acc[c]);
            acc[c] = fmaf(xv.y, wv.y, acc[c]);
            acc[c] = fmaf(xv.z, wv.z, acc[c]);
            acc[c] = fmaf(xv.w, wv.w, acc[c]);
        }
    }

    float es = 0.f, edv = 0.f;
#pragma unroll
    for (int c = 0; c < CLS; c++) {
        es  = fmaf(acc[c], sas[c], es);
        edv = fmaf(acc[c], sad[c], edv);
    }
    g_e2s[row] = es;
    g_e2d[row] = edv;
    float* o = g_h2 + (size_t)row * CLS;   // 160B rows -> 16B aligned
#pragma unroll
    for (int c = 0; c < CLS; c += 4)
        *(float4*)(o + c) = make_float4(acc[c], acc[c + 1], acc[c + 2], acc[c + 3]);
}

// ---------------- layer-2 aggregation: warp per dst, no max pass ----------
__global__ void agg2_kernel(const float* __restrict__ b2, float* __restrict__ out) {
    int gw = (blockIdx.x * blockDim.x + threadIdx.x) >> 5;
    int lane = threadIdx.x & 31;
    if (gw >= NN) return;
    const int beg = g_rowptr[gw];
    const int end = g_rowptr[gw + 1];
    const float edn = g_e2d[gw];

    float acc0 = 0.f, acc1 = 0.f, ss = 0.f;
    for (int i = beg; i < end; i += 32) {
        int ei = i + lane;
        int s = 0;
        float w = 0.f;
        if (ei < end) {
            s = g_srcs[ei];
            float a = g_e2s[s] + edn;
            a = a > 0.f ? a : NEG * a;
            w = fexp(a);
        }
        int cnt = min(32, end - i);
        for (int j = 0; j < cnt; j++) {
            float wj = __shfl_sync(0xffffffffu, w, j);
            int   sj = __shfl_sync(0xffffffffu, s, j);
            acc0 = fmaf(wj, g_h2[(size_t)sj * CLS + lane], acc0);
            if (lane < 8)
                acc1 = fmaf(wj, g_h2[(size_t)sj * CLS + 32 + lane], acc1);
            ss += wj;
        }
    }
    float inv = 1.f / (ss + 1e-16f);
    out[(size_t)gw * CLS + lane] = acc0 * inv + __ldg(&b2[lane]);
    if (lane < 8)
        out[(size_t)gw * CLS + 32 + lane] = acc1 * inv + __ldg(&b2[32 + lane]);
}

// ---------------- launch ----------------
extern "C" void kernel_launch(void* const* d_in, const int* in_sizes, int n_in,
                              void* d_out, int out_size) {
    const float* x   = (const float*)d_in[0];
    const void*  ei  = d_in[1];
    const float* W1  = (const float*)d_in[2];
    const float* as1 = (const float*)d_in[3];
    const float* ad1 = (const float*)d_in[4];
    const float* b1  = (const float*)d_in[5];
    const float* W2  = (const float*)d_in[6];
    const float* as2 = (const float*)d_in[7];
    const float* ad2 = (const float*)d_in[8];
    const float* b2  = (const float*)d_in[9];
    float* out = (float*)d_out;

    zero_kernel<<<(NN + 255) / 256, 256>>>();
    detect_kernel<<<1, 1>>>(ei);
    convert_kernel<<<(ETOT + 255) / 256, 256>>>(ei);
    gemm1_kernel<<<NN / G1R, 128>>>(x, W1, as1, ad1);
    scan_kernel<<<1, 1024>>>();
    scatter_kernel<<<(ETOT + 255) / 256, 256>>>();
    agg1_kernel<<<(NN + 7) / 8, 256>>>(b1);
    gemm2_kernel<<<(NN + 127) / 128, 128>>>(W2, as2, ad2);
    agg2_kernel<<<(NN + 7) / 8, 256>>>(b2, out);
}

// round 7
// speedup vs baseline: 1.5507x; 1.0334x over previous
#include <cuda_runtime.h>
#include <cstdint>

#define NN    50000
#define EE    800000
#define ETOT  (EE + NN)
#define FIN   128
#define H1DIM 128   // HEADS*HID
#define NHEAD 8
#define CLS   40
#define NEG   0.2f
#define G1M   64    // rows per gemm1 block

// ---------------- device scratch (static, allocation-free) ----------------
__device__ float g_h1[(size_t)NN * H1DIM];
__device__ float g_hact[(size_t)NN * H1DIM];
__device__ float g_e1s[NN * NHEAD];
__device__ float g_e1d[NN * NHEAD];
__device__ float g_h2[(size_t)NN * CLS];
__device__ float g_e2s[NN];
__device__ float g_e2d[NN];
__device__ int   g_rowptr[NN + 1];
__device__ int   g_counts[NN];
__device__ int   g_fill[NN];
__device__ int   g_srcs[ETOT];
__device__ int   g_srcE[ETOT];
__device__ int   g_dstE[ETOT];
__device__ int   g_is64;

// ---------------- fast exp: pure FFMA/ALU, no MUFU ----------------
__device__ __forceinline__ float fexp(float x) {
    float t = x * 1.442695041f;
    t = fminf(fmaxf(t, -125.f), 125.f);
    float biased = t + 12582912.f;
    int   ni = __float_as_int(biased) - 0x4B400000;
    float n  = biased - 12582912.f;
    float f  = fmaf(-n, 0.69314718056f, x);
    float p  = fmaf(f, 8.3333333e-3f, 4.1666667e-2f);
    p = fmaf(p, f, 0.16666667f);
    p = fmaf(p, f, 0.5f);
    p = fmaf(p, f, 1.0f);
    p = fmaf(p, f, 1.0f);
    return p * __int_as_float((ni + 127) << 23);
}

__device__ __forceinline__ uint32_t f2tf32(float v) {
    uint32_t u;
    asm("cvt.rna.tf32.f32 %0, %1;" : "=r"(u) : "f"(v));
    return u;
}

// ---------------- edge dtype detection + normalization (+hist fused) ------
__global__ void detect_kernel(const void* ei) {
    const long long* e64 = (const long long*)ei;
    int ok = 1;
    for (int i = 0; i < 1024; i++) {
        long long v = e64[i];
        if (v < 0 || v >= NN) { ok = 0; break; }
    }
    g_is64 = ok;
}

__global__ void zero_kernel() {
    int i = blockIdx.x * blockDim.x + threadIdx.x;
    if (i < NN) { g_counts[i] = 0; g_fill[i] = 0; }
}

__global__ void convert_kernel(const void* ei) {
    int i = blockIdx.x * blockDim.x + threadIdx.x;
    if (i >= ETOT) return;
    int s, d;
    if (i >= EE) {
        s = d = i - EE;
    } else if (g_is64) {
        const long long* e = (const long long*)ei;
        s = (int)e[i]; d = (int)e[EE + i];
    } else {
        const int* e = (const int*)ei;
        s = e[i]; d = e[EE + i];
    }
    g_srcE[i] = s; g_dstE[i] = d;
    atomicAdd(&g_counts[d], 1);
}

// ---------------- shuffle-based single-block scan ----------------
__global__ void scan_kernel() {
    __shared__ int warp_sums[32];
    __shared__ int s_carry;
    int tid = threadIdx.x, lane = tid & 31, wid = tid >> 5;
    if (tid == 0) { s_carry = 0; g_rowptr[0] = 0; }
    __syncthreads();
    for (int base = 0; base < NN; base += 1024) {
        int idx = base + tid;
        int v = (idx < NN) ? g_counts[idx] : 0;
        int xs = v;
#pragma unroll
        for (int off = 1; off < 32; off <<= 1) {
            int y = __shfl_up_sync(0xffffffffu, xs, off);
            if (lane >= off) xs += y;
        }
        if (lane == 31) warp_sums[wid] = xs;
        __syncthreads();
        if (wid == 0) {
            int ws = warp_sums[lane];
#pragma unroll
            for (int off = 1; off < 32; off <<= 1) {
                int y = __shfl_up_sync(0xffffffffu, ws, off);
                if (lane >= off) ws += y;
            }
            warp_sums[lane] = ws;
        }
        __syncthreads();
        int off = ((wid > 0) ? warp_sums[wid - 1] : 0) + s_carry;
        if (idx < NN) g_rowptr[idx + 1] = xs + off;
        __syncthreads();
        if (tid == 0) s_carry += warp_sums[31];
        __syncthreads();
    }
}

__global__ void scatter_kernel() {
    int i = blockIdx.x * blockDim.x + threadIdx.x;
    if (i >= ETOT) return;
    int d = g_dstE[i];
    int pos = g_rowptr[d] + atomicAdd(&g_fill[d], 1);
    g_srcs[pos] = g_srcE[i];
}

// ---------------- GEMM1 on tensor cores: tf32 m16n8k8 ----------------
// block = 128 threads (4 warps x m16 rows), 64 rows/block, N=128, K in 4
// chunks of 32. smem padded to stride 36 so fragment LDS bank index is
// (4*row + tk) mod 32 -> conflict-free.
__global__ void __launch_bounds__(128) gemm1_tc_kernel(
        const float* __restrict__ x, const float* __restrict__ W1) {
    __shared__ uint32_t Ws[128 * 36];   // W chunk: [n][k] (n 0..127, k 0..31)
    __shared__ uint32_t Xs[G1M * 36];   // x chunk: [row][k]
    const int tid = threadIdx.x;
    const int wid = tid >> 5, lane = tid & 31;
    const int g = lane >> 2, tk = lane & 3;
    const int m0 = blockIdx.x * G1M;

    float acc[16][4];
#pragma unroll
    for (int nt = 0; nt < 16; nt++)
#pragma unroll
        for (int j = 0; j < 4; j++) acc[nt][j] = 0.f;

    for (int kc = 0; kc < FIN; kc += 32) {
        // stage W1 chunk (transpose to n-major), coalesced global reads
        for (int i = tid; i < 128 * 32; i += 128) {
            int k = i >> 7, n = i & 127;
            Ws[n * 36 + k] = f2tf32(W1[(kc + k) * H1DIM + n]);
        }
        // stage x chunk, coalesced (32 consecutive floats per row-segment)
        for (int i = tid; i < G1M * 32; i += 128) {
            int row = i >> 5, k = i & 31;
            int gr = m0 + row; if (gr >= NN) gr = NN - 1;
            Xs[row * 36 + k] = f2tf32(x[(size_t)gr * FIN + kc + k]);
        }
        __syncthreads();

#pragma unroll
        for (int ks = 0; ks < 4; ks++) {
            const int k = ks * 8;
            const uint32_t* xa = &Xs[(wid * 16 + g) * 36 + k + tk];
            uint32_t a0 = xa[0];
            uint32_t a1 = xa[8 * 36];
            uint32_t a2 = xa[4];
            uint32_t a3 = xa[8 * 36 + 4];
#pragma unroll
            for (int nt = 0; nt < 16; nt++) {
                const uint32_t* wb = &Ws[(nt * 8 + g) * 36 + k + tk];
                uint32_t b0 = wb[0];
                uint32_t b1 = wb[4];
                asm volatile(
                    "mma.sync.aligned.m16n8k8.row.col.f32.tf32.tf32.f32 "
                    "{%0,%1,%2,%3}, {%4,%5,%6,%7}, {%8,%9}, {%0,%1,%2,%3};"
                    : "+f"(acc[nt][0]), "+f"(acc[nt][1]),
                      "+f"(acc[nt][2]), "+f"(acc[nt][3])
                    : "r"(a0), "r"(a1), "r"(a2), "r"(a3), "r"(b0), "r"(b1));
            }
        }
        __syncthreads();
    }

    // epilogue: d0,d1 -> (row0, 2tk..2tk+1), d2,d3 -> (row0+8, ...)
    const int row0 = m0 + wid * 16 + g;
    const int row1 = row0 + 8;
#pragma unroll
    for (int nt = 0; nt < 16; nt++) {
        int col = nt * 8 + 2 * tk;
        if (row0 < NN)
            *(float2*)&g_h1[(size_t)row0 * H1DIM + col] =
                make_float2(acc[nt][0], acc[nt][1]);
        if (row1 < NN)
            *(float2*)&g_h1[(size_t)row1 * H1DIM + col] =
                make_float2(acc[nt][2], acc[nt][3]);
    }
}

// ---------------- e1s/e1d from h1: thread per (node, head) ----------------
__global__ void e1_kernel(const float* __restrict__ as1,
                          const float* __restrict__ ad1) {
    __shared__ float sa[H1DIM], sd[H1DIM];
    int tid = threadIdx.x;
    if (tid < H1DIM) { sa[tid] = as1[tid]; sd[tid] = ad1[tid]; }
    __syncthreads();
    int idx = blockIdx.x * blockDim.x + tid;
    if (idx >= NN * NHEAD) return;
    int node = idx >> 3, head = idx & 7;
    const float* p = g_h1 + (size_t)node * H1DIM + head * 16;
    float es = 0.f, ed = 0.f;
#pragma unroll
    for (int c = 0; c < 16; c += 4) {
        float4 v = *(const float4*)(p + c);
        float4 a = *(const float4*)&sa[head * 16 + c];
        float4 d = *(const float4*)&sd[head * 16 + c];
        es += v.x * a.x + v.y * a.y + v.z * a.z + v.w * a.w;
        ed += v.x * d.x + v.y * d.y + v.z * d.z + v.w * d.w;
    }
    g_e1s[idx] = es;
    g_e1d[idx] = ed;
}

// ---------------- layer-1 aggregation: warp per dst, no max pass ----------
__global__ void agg1_kernel(const float* __restrict__ b1) {
    int gw = (blockIdx.x * blockDim.x + threadIdx.x) >> 5;
    int lane = threadIdx.x & 31;
    if (gw >= NN) return;
    const int beg = g_rowptr[gw];
    const int end = g_rowptr[gw + 1];

    const int eh = lane & 7;
    const int sub = lane >> 3;
    const int myhead = lane >> 2;
    const float edh = g_e1d[gw * NHEAD + eh];

    float acc0 = 0.f, acc1 = 0.f, acc2 = 0.f, acc3 = 0.f, ssum = 0.f;
    for (int i = beg; i < end; i += 4) {
        int ei = i + sub;
        int s = 0;
        float w = 0.f;
        if (ei < end) {
            s = g_srcs[ei];
            float a = g_e1s[s * NHEAD + eh] + edh;
            a = a > 0.f ? a : NEG * a;
            w = fexp(a);
        }
#pragma unroll
        for (int j = 0; j < 4; j++) {
            float wj = __shfl_sync(0xffffffffu, w, (j << 3) + myhead);
            int   sj = __shfl_sync(0xffffffffu, s, j << 3);
            if (i + j < end) {
                const float4 hv = *(const float4*)(g_h1 + (size_t)sj * H1DIM + lane * 4);
                acc0 = fmaf(wj, hv.x, acc0);
                acc1 = fmaf(wj, hv.y, acc1);
                acc2 = fmaf(wj, hv.z, acc2);
                acc3 = fmaf(wj, hv.w, acc3);
                ssum += wj;
            }
        }
    }

    float inv = 1.f / (ssum + 1e-16f);
    float4 bv = *(const float4*)(b1 + lane * 4);
    float v0 = acc0 * inv + bv.x;
    float v1 = acc1 * inv + bv.y;
    float v2 = acc2 * inv + bv.z;
    float v3 = acc3 * inv + bv.w;
    v0 = v0 > 0.f ? v0 : (fexp(v0) - 1.f);
    v1 = v1 > 0.f ? v1 : (fexp(v1) - 1.f);
    v2 = v2 > 0.f ? v2 : (fexp(v2) - 1.f);
    v3 = v3 > 0.f ? v3 : (fexp(v3) - 1.f);
    *(float4*)(g_hact + (size_t)gw * H1DIM + lane * 4) = make_float4(v0, v1, v2, v3);
}

// ---------------- GEMM2: thread-per-row, W2^T in smem ----------------
__global__ void gemm2_kernel(const float* __restrict__ W2,
                             const float* __restrict__ as2,
                             const float* __restrict__ ad2) {
    __shared__ float W2T[CLS][FIN];
    __shared__ float sas[CLS], sad[CLS];
    int tid = threadIdx.x;
    for (int i = tid; i < CLS * FIN; i += blockDim.x) {
        int c = i >> 7, k = i & 127;
        W2T[c][k] = W2[k * CLS + c];
    }
    if (tid < CLS) { sas[tid] = as2[tid]; sad[tid] = ad2[tid]; }
    __syncthreads();

    int row = blockIdx.x * blockDim.x + tid;
    if (row >= NN) return;
    const float* xr = g_hact + (size_t)row * FIN;

    float acc[CLS];
#pragma unroll
    for (int c = 0; c < CLS; c++) acc[c] = 0.f;

    for (int k = 0; k < FIN; k += 4) {
        float4 xv = *(const float4*)(xr + k);
#pragma unroll
        for (int c = 0; c < CLS; c++) {
            float4 wv = *(const float4*)&W2T[c][k];
            acc[c] = fmaf(xv.x, wv.x, acc[c]);
            acc[c] = fmaf(xv.y, wv.y, acc[c]);
            acc[c] = fmaf(xv.z, wv.z, acc[c]);
            acc[c] = fmaf(xv.w, wv.w, acc[c]);
        }
    }

    float es = 0.f, edv = 0.f;
#pragma unroll
    for (int c = 0; c < CLS; c++) {
        es  = fmaf(acc[c], sas[c], es);
        edv = fmaf(acc[c], sad[c], edv);
    }
    g_e2s[row] = es;
    g_e2d[row] = edv;
    float* o = g_h2 + (size_t)row * CLS;
#pragma unroll
    for (int c = 0; c < CLS; c += 4)
        *(float4*)(o + c) = make_float4(acc[c], acc[c + 1], acc[c + 2], acc[c + 3]);
}

// ---------------- layer-2 aggregation: warp per dst, no max pass ----------
__global__ void agg2_kernel(const float* __restrict__ b2, float* __restrict__ out) {
    int gw = (blockIdx.x * blockDim.x + threadIdx.x) >> 5;
    int lane = threadIdx.x & 31;
    if (gw >= NN) return;
    const int beg = g_rowptr[gw];
    const int end = g_rowptr[gw + 1];
    const float edn = g_e2d[gw];

    float acc0 = 0.f, acc1 = 0.f, ss = 0.f;
    for (int i = beg; i < end; i += 32) {
        int ei = i + lane;
        int s = 0;
        float w = 0.f;
        if (ei < end) {
            s = g_srcs[ei];
            float a = g_e2s[s] + edn;
            a = a > 0.f ? a : NEG * a;
            w = fexp(a);
        }
        int cnt = min(32, end - i);
        for (int j = 0; j < cnt; j++) {
            float wj = __shfl_sync(0xffffffffu, w, j);
            int   sj = __shfl_sync(0xffffffffu, s, j);
            acc0 = fmaf(wj, g_h2[(size_t)sj * CLS + lane], acc0);
            if (lane < 8)
                acc1 = fmaf(wj, g_h2[(size_t)sj * CLS + 32 + lane], acc1);
            ss += wj;
        }
    }
    float inv = 1.f / (ss + 1e-16f);
    out[(size_t)gw * CLS + lane] = acc0 * inv + __ldg(&b2[lane]);
    if (lane < 8)
        out[(size_t)gw * CLS + 32 + lane] = acc1 * inv + __ldg(&b2[32 + lane]);
}

// ---------------- launch ----------------
extern "C" void kernel_launch(void* const* d_in, const int* in_sizes, int n_in,
                              void* d_out, int out_size) {
    const float* x   = (const float*)d_in[0];
    const void*  ei  = d_in[1];
    const float* W1  = (const float*)d_in[2];
    const float* as1 = (const float*)d_in[3];
    const float* ad1 = (const float*)d_in[4];
    const float* b1  = (const float*)d_in[5];
    const float* W2  = (const float*)d_in[6];
    const float* as2 = (const float*)d_in[7];
    const float* ad2 = (const float*)d_in[8];
    const float* b2  = (const float*)d_in[9];
    float* out = (float*)d_out;

    zero_kernel<<<(NN + 255) / 256, 256>>>();
    detect_kernel<<<1, 1>>>(ei);
    convert_kernel<<<(ETOT + 255) / 256, 256>>>(ei);
    gemm1_tc_kernel<<<(NN + G1M - 1) / G1M, 128>>>(x, W1);
    e1_kernel<<<(NN * NHEAD + 255) / 256, 256>>>(as1, ad1);
    scan_kernel<<<1, 1024>>>();
    scatter_kernel<<<(ETOT + 255) / 256, 256>>>();
    agg1_kernel<<<(NN + 7) / 8, 256>>>(b1);
    gemm2_kernel<<<(NN + 127) / 128, 128>>>(W2, as2, ad2);
    agg2_kernel<<<(NN + 7) / 8, 256>>>(b2, out);
}

// round 8
// speedup vs baseline: 2.0645x; 1.3314x over previous
#include <cuda_runtime.h>
#include <cstdint>

#define NN    50000
#define EE    800000
#define ETOT  (EE + NN)
#define FIN   128
#define H1DIM 128   // HEADS*HID
#define NHEAD 8
#define CLS   40
#define NEG   0.2f
#define G1M   128   // rows per gemm1 block

// ---------------- device scratch (static, allocation-free) ----------------
__device__ float g_h1[(size_t)NN * H1DIM];
__device__ float g_hact[(size_t)NN * H1DIM];
__device__ float g_e1s[NN * NHEAD];
__device__ float g_e1d[NN * NHEAD];
__device__ float g_h2[(size_t)NN * CLS];
__device__ float g_e2s[NN];
__device__ float g_e2d[NN];
__device__ int   g_rowptr[NN + 1];
__device__ int   g_counts[NN];
__device__ int   g_fill[NN];
__device__ int   g_srcs[ETOT];
__device__ int   g_bsum[64];
__device__ int   g_boff[64];
__device__ int   g_is64;

// ---------------- fast exp: pure FFMA/ALU, no MUFU ----------------
__device__ __forceinline__ float fexp(float x) {
    float t = x * 1.442695041f;
    t = fminf(fmaxf(t, -125.f), 125.f);
    float biased = t + 12582912.f;
    int   ni = __float_as_int(biased) - 0x4B400000;
    float n  = biased - 12582912.f;
    float f  = fmaf(-n, 0.69314718056f, x);
    float p  = fmaf(f, 8.3333333e-3f, 4.1666667e-2f);
    p = fmaf(p, f, 0.16666667f);
    p = fmaf(p, f, 0.5f);
    p = fmaf(p, f, 1.0f);
    p = fmaf(p, f, 1.0f);
    return p * __int_as_float((ni + 127) << 23);
}

__device__ __forceinline__ uint32_t f2tf32(float v) {
    uint32_t u;
    asm("cvt.rna.tf32.f32 %0, %1;" : "=r"(u) : "f"(v));
    return u;
}

// ---------------- edge dtype detection (warp-parallel) ----------------
__global__ void detect_kernel(const void* ei) {
    const long long* e = (const long long*)ei;
    int lane = threadIdx.x;
    int bad = 0;
    for (int i = lane; i < 1024; i += 32) {
        long long v = e[i];
        if (v < 0 || v >= NN) bad = 1;
    }
    unsigned m = __ballot_sync(0xffffffffu, bad);
    if (lane == 0) g_is64 = (m == 0);
}

__global__ void zero_kernel() {
    int i = blockIdx.x * blockDim.x + threadIdx.x;
    if (i < NN) { g_counts[i] = 0; g_fill[i] = 0; }
}

// ---------------- hist directly from edge_index ----------------
__global__ void hist_kernel(const void* ei) {
    int i = blockIdx.x * blockDim.x + threadIdx.x;
    if (i >= ETOT) return;
    int d;
    if (i >= EE)          d = i - EE;
    else if (g_is64)      d = (int)((const long long*)ei)[EE + i];
    else                  d = ((const int*)ei)[EE + i];
    atomicAdd(&g_counts[d], 1);
}

// ---------------- hierarchical scan: 49 chunks of 1024 ----------------
__global__ void scan1_kernel() {
    __shared__ int warp_sums[32];
    int tid = threadIdx.x, lane = tid & 31, wid = tid >> 5;
    int idx = blockIdx.x * 1024 + tid;
    int v = (idx < NN) ? g_counts[idx] : 0;
    int xs = v;
#pragma unroll
    for (int off = 1; off < 32; off <<= 1) {
        int y = __shfl_up_sync(0xffffffffu, xs, off);
        if (lane >= off) xs += y;
    }
    if (lane == 31) warp_sums[wid] = xs;
    __syncthreads();
    if (wid == 0) {
        int ws = warp_sums[lane];
#pragma unroll
        for (int off = 1; off < 32; off <<= 1) {
            int y = __shfl_up_sync(0xffffffffu, ws, off);
            if (lane >= off) ws += y;
        }
        warp_sums[lane] = ws;
    }
    __syncthreads();
    int incl = xs + ((wid > 0) ? warp_sums[wid - 1] : 0);
    if (idx < NN) g_rowptr[idx + 1] = incl;
    if (tid == 1023) g_bsum[blockIdx.x] = incl;
}

__global__ void scan2_kernel(int nblk) {
    int lane = threadIdx.x;              // 32 threads, 2 elems each
    int i0 = 2 * lane, i1 = 2 * lane + 1;
    int a = (i0 < nblk) ? g_bsum[i0] : 0;
    int b = (i1 < nblk) ? g_bsum[i1] : 0;
    int s = a + b, xs = s;
#pragma unroll
    for (int off = 1; off < 32; off <<= 1) {
        int y = __shfl_up_sync(0xffffffffu, xs, off);
        if (lane >= off) xs += y;
    }
    int excl = xs - s;
    if (i0 < nblk) g_boff[i0] = excl;
    if (i1 < nblk) g_boff[i1] = excl + a;
}

__global__ void scan3_kernel() {
    int idx = blockIdx.x * 1024 + threadIdx.x;
    int o = g_boff[blockIdx.x];
    if (idx < NN) g_rowptr[idx + 1] += o;
    if (idx == 0) g_rowptr[0] = 0;
}

__global__ void scatter_kernel(const void* ei) {
    int i = blockIdx.x * blockDim.x + threadIdx.x;
    if (i >= ETOT) return;
    int s, d;
    if (i >= EE) {
        s = d = i - EE;
    } else if (g_is64) {
        const long long* e = (const long long*)ei;
        s = (int)e[i]; d = (int)e[EE + i];
    } else {
        const int* e = (const int*)ei;
        s = e[i]; d = e[EE + i];
    }
    int pos = g_rowptr[d] + atomicAdd(&g_fill[d], 1);
    g_srcs[pos] = s;
}

// ---------------- GEMM1 tensor cores, W resident, fused e1 epilogue -------
// 256 threads (8 warps x m16), 128 rows/block. W1 (128x128 tf32) staged once
// at stride 132 (132 mod 32 == 4 -> fragment loads conflict-free). X staged
// per-32k chunk at stride 36.
__global__ void __launch_bounds__(256, 2) gemm1_tc_kernel(
        const float* __restrict__ x, const float* __restrict__ W1,
        const float* __restrict__ as1, const float* __restrict__ ad1) {
    extern __shared__ uint32_t sm[];
    uint32_t* Ws = sm;                    // [n*132 + k], 16896 words
    uint32_t* Xs = sm + 128 * 132;        // [row*36 + k], 4608 words
    float* sa = (float*)(sm + 128 * 132 + 128 * 36);        // 128
    float* sd = sa + 128;                                    // 128

    const int tid = threadIdx.x;
    const int wid = tid >> 5, lane = tid & 31;
    const int g = lane >> 2, tk = lane & 3;
    const int m0 = blockIdx.x * G1M;

    // stage full W1 (transpose to n-major) + attention vectors
    for (int i = tid; i < 128 * 128; i += 256) {
        int k = i >> 7, n = i & 127;
        Ws[n * 132 + k] = f2tf32(W1[k * H1DIM + n]);
    }
    if (tid < 128) { sa[tid] = as1[tid]; sd[tid] = ad1[tid]; }

    float acc[16][4];
#pragma unroll
    for (int nt = 0; nt < 16; nt++)
#pragma unroll
        for (int j = 0; j < 4; j++) acc[nt][j] = 0.f;

    for (int kc = 0; kc < 4; kc++) {
        // stage X chunk: warp w covers row w+8i, lane = k (conflict-free)
        for (int i = tid; i < G1M * 32; i += 256) {
            int row = i >> 5, k = i & 31;
            int gr = m0 + row; if (gr >= NN) gr = NN - 1;
            Xs[row * 36 + k] = f2tf32(x[(size_t)gr * FIN + kc * 32 + k]);
        }
        __syncthreads();

#pragma unroll
        for (int ks = 0; ks < 4; ks++) {
            const int kx = ks * 8;
            const int kw = kc * 32 + ks * 8;
            const uint32_t* xa = &Xs[(wid * 16 + g) * 36 + kx + tk];
            uint32_t a0 = xa[0];
            uint32_t a1 = xa[8 * 36];
            uint32_t a2 = xa[4];
            uint32_t a3 = xa[8 * 36 + 4];
#pragma unroll
            for (int nt = 0; nt < 16; nt++) {
                const uint32_t* wb = &Ws[(nt * 8 + g) * 132 + kw + tk];
                uint32_t b0 = wb[0];
                uint32_t b1 = wb[4];
                asm volatile(
                    "mma.sync.aligned.m16n8k8.row.col.f32.tf32.tf32.f32 "
                    "{%0,%1,%2,%3}, {%4,%5,%6,%7}, {%8,%9}, {%0,%1,%2,%3};"
                    : "+f"(acc[nt][0]), "+f"(acc[nt][1]),
                      "+f"(acc[nt][2]), "+f"(acc[nt][3])
                    : "r"(a0), "r"(a1), "r"(a2), "r"(a3), "r"(b0), "r"(b1));
            }
        }
        __syncthreads();
    }

    // epilogue: store h1 + fused e1s/e1d (quad-reduce over tk lanes)
    const int row0 = m0 + wid * 16 + g;
    const int row1 = row0 + 8;
#pragma unroll
    for (int nt = 0; nt < 16; nt++) {
        int col = nt * 8 + 2 * tk;
        if (row0 < NN)
            *(float2*)&g_h1[(size_t)row0 * H1DIM + col] =
                make_float2(acc[nt][0], acc[nt][1]);
        if (row1 < NN)
            *(float2*)&g_h1[(size_t)row1 * H1DIM + col] =
                make_float2(acc[nt][2], acc[nt][3]);
    }

#pragma unroll
    for (int h = 0; h < 8; h++) {
        float es0 = 0.f, ed0 = 0.f, es1 = 0.f, ed1 = 0.f;
#pragma unroll
        for (int q = 0; q < 2; q++) {
            int nt = 2 * h + q;
            int col = nt * 8 + 2 * tk;
            float av0 = sa[col], av1 = sa[col + 1];
            float dv0 = sd[col], dv1 = sd[col + 1];
            es0 += acc[nt][0] * av0 + acc[nt][1] * av1;
            ed0 += acc[nt][0] * dv0 + acc[nt][1] * dv1;
            es1 += acc[nt][2] * av0 + acc[nt][3] * av1;
            ed1 += acc[nt][2] * dv0 + acc[nt][3] * dv1;
        }
        es0 += __shfl_down_sync(0xffffffffu, es0, 2);
        es0 += __shfl_down_sync(0xffffffffu, es0, 1);
        ed0 += __shfl_down_sync(0xffffffffu, ed0, 2);
        ed0 += __shfl_down_sync(0xffffffffu, ed0, 1);
        es1 += __shfl_down_sync(0xffffffffu, es1, 2);
        es1 += __shfl_down_sync(0xffffffffu, es1, 1);
        ed1 += __shfl_down_sync(0xffffffffu, ed1, 2);
        ed1 += __shfl_down_sync(0xffffffffu, ed1, 1);
        if (tk == 0) {
            if (row0 < NN) { g_e1s[row0 * NHEAD + h] = es0; g_e1d[row0 * NHEAD + h] = ed0; }
            if (row1 < NN) { g_e1s[row1 * NHEAD + h] = es1; g_e1d[row1 * NHEAD + h] = ed1; }
        }
    }
}

// ---------------- layer-1 aggregation: warp per dst, no max pass ----------
__global__ void agg1_kernel(const float* __restrict__ b1) {
    int gw = (blockIdx.x * blockDim.x + threadIdx.x) >> 5;
    int lane = threadIdx.x & 31;
    if (gw >= NN) return;
    const int beg = g_rowptr[gw];
    const int end = g_rowptr[gw + 1];

    const int eh = lane & 7;
    const int sub = lane >> 3;
    const int myhead = lane >> 2;
    const float edh = g_e1d[gw * NHEAD + eh];

    float acc0 = 0.f, acc1 = 0.f, acc2 = 0.f, acc3 = 0.f, ssum = 0.f;
    for (int i = beg; i < end; i += 4) {
        int ei = i + sub;
        int s = 0;
        float w = 0.f;
        if (ei < end) {
            s = g_srcs[ei];
            float a = g_e1s[s * NHEAD + eh] + edh;
            a = a > 0.f ? a : NEG * a;
            w = fexp(a);
        }
#pragma unroll
        for (int j = 0; j < 4; j++) {
            float wj = __shfl_sync(0xffffffffu, w, (j << 3) + myhead);
            int   sj = __shfl_sync(0xffffffffu, s, j << 3);
            if (i + j < end) {
                const float4 hv = *(const float4*)(g_h1 + (size_t)sj * H1DIM + lane * 4);
                acc0 = fmaf(wj, hv.x, acc0);
                acc1 = fmaf(wj, hv.y, acc1);
                acc2 = fmaf(wj, hv.z, acc2);
                acc3 = fmaf(wj, hv.w, acc3);
                ssum += wj;
            }
        }
    }

    float inv = 1.f / (ssum + 1e-16f);
    float4 bv = *(const float4*)(b1 + lane * 4);
    float v0 = acc0 * inv + bv.x;
    float v1 = acc1 * inv + bv.y;
    float v2 = acc2 * inv + bv.z;
    float v3 = acc3 * inv + bv.w;
    v0 = v0 > 0.f ? v0 : (fexp(v0) - 1.f);
    v1 = v1 > 0.f ? v1 : (fexp(v1) - 1.f);
    v2 = v2 > 0.f ? v2 : (fexp(v2) - 1.f);
    v3 = v3 > 0.f ? v3 : (fexp(v3) - 1.f);
    *(float4*)(g_hact + (size_t)gw * H1DIM + lane * 4) = make_float4(v0, v1, v2, v3);
}

// ---------------- GEMM2: thread-per-row, W2^T in smem ----------------
__global__ void gemm2_kernel(const float* __restrict__ W2,
                             const float* __restrict__ as2,
                             const float* __restrict__ ad2) {
    __shared__ float W2T[CLS][FIN];
    __shared__ float sas[CLS], sad[CLS];
    int tid = threadIdx.x;
    for (int i = tid; i < CLS * FIN; i += blockDim.x) {
        int c = i >> 7, k = i & 127;
        W2T[c][k] = W2[k * CLS + c];
    }
    if (tid < CLS) { sas[tid] = as2[tid]; sad[tid] = ad2[tid]; }
    __syncthreads();

    int row = blockIdx.x * blockDim.x + tid;
    if (row >= NN) return;
    const float* xr = g_hact + (size_t)row * FIN;

    float acc[CLS];
#pragma unroll
    for (int c = 0; c < CLS; c++) acc[c] = 0.f;

    for (int k = 0; k < FIN; k += 4) {
        float4 xv = *(const float4*)(xr + k);
#pragma unroll
        for (int c = 0; c < CLS; c++) {
            float4 wv = *(const float4*)&W2T[c][k];
            acc[c] = fmaf(xv.x, wv.x, acc[c]);
            acc[c] = fmaf(xv.y, wv.y, acc[c]);
            acc[c] = fmaf(xv.z, wv.z, acc[c]);
            acc[c] = fmaf(xv.w, wv.w, acc[c]);
        }
    }

    float es = 0.f, edv = 0.f;
#pragma unroll
    for (int c = 0; c < CLS; c++) {
        es  = fmaf(acc[c], sas[c], es);
        edv = fmaf(acc[c], sad[c], edv);
    }
    g_e2s[row] = es;
    g_e2d[row] = edv;
    float* o = g_h2 + (size_t)row * CLS;
#pragma unroll
    for (int c = 0; c < CLS; c += 4)
        *(float4*)(o + c) = make_float4(acc[c], acc[c + 1], acc[c + 2], acc[c + 3]);
}

// ---------------- layer-2 aggregation: warp per dst, no max pass ----------
__global__ void agg2_kernel(const float* __restrict__ b2, float* __restrict__ out) {
    int gw = (blockIdx.x * blockDim.x + threadIdx.x) >> 5;
    int lane = threadIdx.x & 31;
    if (gw >= NN) return;
    const int beg = g_rowptr[gw];
    const int end = g_rowptr[gw + 1];
    const float edn = g_e2d[gw];

    float acc0 = 0.f, acc1 = 0.f, ss = 0.f;
    for (int i = beg; i < end; i += 32) {
        int ei = i + lane;
        int s = 0;
        float w = 0.f;
        if (ei < end) {
            s = g_srcs[ei];
            float a = g_e2s[s] + edn;
            a = a > 0.f ? a : NEG * a;
            w = fexp(a);
        }
        int cnt = min(32, end - i);
        for (int j = 0; j < cnt; j++) {
            float wj = __shfl_sync(0xffffffffu, w, j);
            int   sj = __shfl_sync(0xffffffffu, s, j);
            acc0 = fmaf(wj, g_h2[(size_t)sj * CLS + lane], acc0);
            if (lane < 8)
                acc1 = fmaf(wj, g_h2[(size_t)sj * CLS + 32 + lane], acc1);
            ss += wj;
        }
    }
    float inv = 1.f / (ss + 1e-16f);
    out[(size_t)gw * CLS + lane] = acc0 * inv + __ldg(&b2[lane]);
    if (lane < 8)
        out[(size_t)gw * CLS + 32 + lane] = acc1 * inv + __ldg(&b2[32 + lane]);
}

// ---------------- launch ----------------
extern "C" void kernel_launch(void* const* d_in, const int* in_sizes, int n_in,
                              void* d_out, int out_size) {
    const float* x   = (const float*)d_in[0];
    const void*  ei  = d_in[1];
    const float* W1  = (const float*)d_in[2];
    const float* as1 = (const float*)d_in[3];
    const float* ad1 = (const float*)d_in[4];
    const float* b1  = (const float*)d_in[5];
    const float* W2  = (const float*)d_in[6];
    const float* as2 = (const float*)d_in[7];
    const float* ad2 = (const float*)d_in[8];
    const float* b2  = (const float*)d_in[9];
    float* out = (float*)d_out;

    static cudaStream_t s2 = nullptr;
    static cudaEvent_t evFork = nullptr, evJoin = nullptr;
    if (s2 == nullptr) {
        cudaFuncSetAttribute(gemm1_tc_kernel,
                             cudaFuncAttributeMaxDynamicSharedMemorySize, 87040);
        cudaStreamCreateWithFlags(&s2, cudaStreamNonBlocking);
        cudaEventCreateWithFlags(&evFork, cudaEventDisableTiming);
        cudaEventCreateWithFlags(&evJoin, cudaEventDisableTiming);
    }

    const int NBLK = (NN + 1023) / 1024;   // 49

    zero_kernel<<<(NN + 255) / 256, 256>>>();
    detect_kernel<<<1, 32>>>(ei);
    cudaEventRecord(evFork, 0);

    // aux stream: CSR build (independent of gemm1 chain)
    cudaStreamWaitEvent(s2, evFork, 0);
    hist_kernel<<<(ETOT + 255) / 256, 256, 0, s2>>>(ei);
    scan1_kernel<<<NBLK, 1024, 0, s2>>>();
    scan2_kernel<<<1, 32, 0, s2>>>(NBLK);
    scan3_kernel<<<NBLK, 1024, 0, s2>>>();
    scatter_kernel<<<(ETOT + 255) / 256, 256, 0, s2>>>(ei);
    cudaEventRecord(evJoin, s2);

    // main stream: feature transform
    gemm1_tc_kernel<<<(NN + G1M - 1) / G1M, 256, 87040>>>(x, W1, as1, ad1);

    cudaStreamWaitEvent(0, evJoin, 0);
    agg1_kernel<<<(NN + 7) / 8, 256>>>(b1);
    gemm2_kernel<<<(NN + 127) / 128, 128>>>(W2, as2, ad2);
    agg2_kernel<<<(NN + 7) / 8, 256>>>(b2, out);
}

// round 9
// speedup vs baseline: 2.1678x; 1.0500x over previous
#include <cuda_runtime.h>
#include <cuda_fp16.h>
#include <cstdint>

#define NN    50000
#define EE    800000
#define ETOT  (EE + NN)
#define FIN   128
#define H1DIM 128   // HEADS*HID
#define NHEAD 8
#define CLS   40
#define NEG   0.2f
#define G1M   128   // rows per gemm1 block

// ---------------- device scratch (static, allocation-free) ----------------
__device__ __half g_h1h[(size_t)NN * H1DIM];   // layer-1 messages, fp16
__device__ float g_hact[(size_t)NN * H1DIM];
__device__ float g_e1s[NN * NHEAD];
__device__ float g_e1d[NN * NHEAD];
__device__ float g_h2[(size_t)NN * CLS];
__device__ float g_e2s[NN];
__device__ float g_e2d[NN];
__device__ int   g_rowptr[NN + 1];
__device__ int   g_counts[NN];
__device__ int   g_fill[NN];
__device__ int   g_srcs[ETOT];
__device__ int   g_bsum[64];
__device__ int   g_boff[64];
__device__ int   g_is64;

// ---------------- fast exp: pure FFMA/ALU, no MUFU ----------------
__device__ __forceinline__ float fexp(float x) {
    float t = x * 1.442695041f;
    t = fminf(fmaxf(t, -125.f), 125.f);
    float biased = t + 12582912.f;
    int   ni = __float_as_int(biased) - 0x4B400000;
    float n  = biased - 12582912.f;
    float f  = fmaf(-n, 0.69314718056f, x);
    float p  = fmaf(f, 8.3333333e-3f, 4.1666667e-2f);
    p = fmaf(p, f, 0.16666667f);
    p = fmaf(p, f, 0.5f);
    p = fmaf(p, f, 1.0f);
    p = fmaf(p, f, 1.0f);
    return p * __int_as_float((ni + 127) << 23);
}

__device__ __forceinline__ uint32_t f2tf32(float v) {
    uint32_t u;
    asm("cvt.rna.tf32.f32 %0, %1;" : "=r"(u) : "f"(v));
    return u;
}

// ---------------- edge dtype detection (warp-parallel) ----------------
__global__ void detect_kernel(const void* ei) {
    const long long* e = (const long long*)ei;
    int lane = threadIdx.x;
    int bad = 0;
    for (int i = lane; i < 1024; i += 32) {
        long long v = e[i];
        if (v < 0 || v >= NN) bad = 1;
    }
    unsigned m = __ballot_sync(0xffffffffu, bad);
    if (lane == 0) g_is64 = (m == 0);
}

__global__ void zero_kernel() {
    int i = blockIdx.x * blockDim.x + threadIdx.x;
    if (i < NN) { g_counts[i] = 0; g_fill[i] = 0; }
}

// ---------------- hist directly from edge_index ----------------
__global__ void hist_kernel(const void* ei) {
    int i = blockIdx.x * blockDim.x + threadIdx.x;
    if (i >= ETOT) return;
    int d;
    if (i >= EE)          d = i - EE;
    else if (g_is64)      d = (int)((const long long*)ei)[EE + i];
    else                  d = ((const int*)ei)[EE + i];
    atomicAdd(&g_counts[d], 1);
}

// ---------------- hierarchical scan: 49 chunks of 1024 ----------------
__global__ void scan1_kernel() {
    __shared__ int warp_sums[32];
    int tid = threadIdx.x, lane = tid & 31, wid = tid >> 5;
    int idx = blockIdx.x * 1024 + tid;
    int v = (idx < NN) ? g_counts[idx] : 0;
    int xs = v;
#pragma unroll
    for (int off = 1; off < 32; off <<= 1) {
        int y = __shfl_up_sync(0xffffffffu, xs, off);
        if (lane >= off) xs += y;
    }
    if (lane == 31) warp_sums[wid] = xs;
    __syncthreads();
    if (wid == 0) {
        int ws = warp_sums[lane];
#pragma unroll
        for (int off = 1; off < 32; off <<= 1) {
            int y = __shfl_up_sync(0xffffffffu, ws, off);
            if (lane >= off) ws += y;
        }
        warp_sums[lane] = ws;
    }
    __syncthreads();
    int incl = xs + ((wid > 0) ? warp_sums[wid - 1] : 0);
    if (idx < NN) g_rowptr[idx + 1] = incl;
    if (tid == 1023) g_bsum[blockIdx.x] = incl;
}

__global__ void scan2_kernel(int nblk) {
    int lane = threadIdx.x;
    int i0 = 2 * lane, i1 = 2 * lane + 1;
    int a = (i0 < nblk) ? g_bsum[i0] : 0;
    int b = (i1 < nblk) ? g_bsum[i1] : 0;
    int s = a + b, xs = s;
#pragma unroll
    for (int off = 1; off < 32; off <<= 1) {
        int y = __shfl_up_sync(0xffffffffu, xs, off);
        if (lane >= off) xs += y;
    }
    int excl = xs - s;
    if (i0 < nblk) g_boff[i0] = excl;
    if (i1 < nblk) g_boff[i1] = excl + a;
}

__global__ void scan3_kernel() {
    int idx = blockIdx.x * 1024 + threadIdx.x;
    int o = g_boff[blockIdx.x];
    if (idx < NN) g_rowptr[idx + 1] += o;
    if (idx == 0) g_rowptr[0] = 0;
}

__global__ void scatter_kernel(const void* ei) {
    int i = blockIdx.x * blockDim.x + threadIdx.x;
    if (i >= ETOT) return;
    int s, d;
    if (i >= EE) {
        s = d = i - EE;
    } else if (g_is64) {
        const long long* e = (const long long*)ei;
        s = (int)e[i]; d = (int)e[EE + i];
    } else {
        const int* e = (const int*)ei;
        s = e[i]; d = e[EE + i];
    }
    int pos = g_rowptr[d] + atomicAdd(&g_fill[d], 1);
    g_srcs[pos] = s;
}

// ---------------- GEMM1 tensor cores, W resident, fused e1 epilogue -------
__global__ void __launch_bounds__(256, 2) gemm1_tc_kernel(
        const float* __restrict__ x, const float* __restrict__ W1,
        const float* __restrict__ as1, const float* __restrict__ ad1) {
    extern __shared__ uint32_t sm[];
    uint32_t* Ws = sm;                    // [n*132 + k]
    uint32_t* Xs = sm + 128 * 132;        // [row*36 + k]
    float* sa = (float*)(sm + 128 * 132 + 128 * 36);
    float* sd = sa + 128;

    const int tid = threadIdx.x;
    const int wid = tid >> 5, lane = tid & 31;
    const int g = lane >> 2, tk = lane & 3;
    const int m0 = blockIdx.x * G1M;

    for (int i = tid; i < 128 * 128; i += 256) {
        int k = i >> 7, n = i & 127;
        Ws[n * 132 + k] = f2tf32(W1[k * H1DIM + n]);
    }
    if (tid < 128) { sa[tid] = as1[tid]; sd[tid] = ad1[tid]; }

    float acc[16][4];
#pragma unroll
    for (int nt = 0; nt < 16; nt++)
#pragma unroll
        for (int j = 0; j < 4; j++) acc[nt][j] = 0.f;

    for (int kc = 0; kc < 4; kc++) {
        for (int i = tid; i < G1M * 32; i += 256) {
            int row = i >> 5, k = i & 31;
            int gr = m0 + row; if (gr >= NN) gr = NN - 1;
            Xs[row * 36 + k] = f2tf32(x[(size_t)gr * FIN + kc * 32 + k]);
        }
        __syncthreads();

#pragma unroll
        for (int ks = 0; ks < 4; ks++) {
            const int kx = ks * 8;
            const int kw = kc * 32 + ks * 8;
            const uint32_t* xa = &Xs[(wid * 16 + g) * 36 + kx + tk];
            uint32_t a0 = xa[0];
            uint32_t a1 = xa[8 * 36];
            uint32_t a2 = xa[4];
            uint32_t a3 = xa[8 * 36 + 4];
#pragma unroll
            for (int nt = 0; nt < 16; nt++) {
                const uint32_t* wb = &Ws[(nt * 8 + g) * 132 + kw + tk];
                uint32_t b0 = wb[0];
                uint32_t b1 = wb[4];
                asm volatile(
                    "mma.sync.aligned.m16n8k8.row.col.f32.tf32.tf32.f32 "
                    "{%0,%1,%2,%3}, {%4,%5,%6,%7}, {%8,%9}, {%0,%1,%2,%3};"
                    : "+f"(acc[nt][0]), "+f"(acc[nt][1]),
                      "+f"(acc[nt][2]), "+f"(acc[nt][3])
                    : "r"(a0), "r"(a1), "r"(a2), "r"(a3), "r"(b0), "r"(b1));
            }
        }
        __syncthreads();
    }

    // epilogue: store h1 (fp16) + fused e1s/e1d
    const int row0 = m0 + wid * 16 + g;
    const int row1 = row0 + 8;
#pragma unroll
    for (int nt = 0; nt < 16; nt++) {
        int col = nt * 8 + 2 * tk;
        if (row0 < NN)
            *(__half2*)&g_h1h[(size_t)row0 * H1DIM + col] =
                __floats2half2_rn(acc[nt][0], acc[nt][1]);
        if (row1 < NN)
            *(__half2*)&g_h1h[(size_t)row1 * H1DIM + col] =
                __floats2half2_rn(acc[nt][2], acc[nt][3]);
    }

#pragma unroll
    for (int h = 0; h < 8; h++) {
        float es0 = 0.f, ed0 = 0.f, es1 = 0.f, ed1 = 0.f;
#pragma unroll
        for (int q = 0; q < 2; q++) {
            int nt = 2 * h + q;
            int col = nt * 8 + 2 * tk;
            float av0 = sa[col], av1 = sa[col + 1];
            float dv0 = sd[col], dv1 = sd[col + 1];
            es0 += acc[nt][0] * av0 + acc[nt][1] * av1;
            ed0 += acc[nt][0] * dv0 + acc[nt][1] * dv1;
            es1 += acc[nt][2] * av0 + acc[nt][3] * av1;
            ed1 += acc[nt][2] * dv0 + acc[nt][3] * dv1;
        }
        es0 += __shfl_down_sync(0xffffffffu, es0, 2);
        es0 += __shfl_down_sync(0xffffffffu, es0, 1);
        ed0 += __shfl_down_sync(0xffffffffu, ed0, 2);
        ed0 += __shfl_down_sync(0xffffffffu, ed0, 1);
        es1 += __shfl_down_sync(0xffffffffu, es1, 2);
        es1 += __shfl_down_sync(0xffffffffu, es1, 1);
        ed1 += __shfl_down_sync(0xffffffffu, ed1, 2);
        ed1 += __shfl_down_sync(0xffffffffu, ed1, 1);
        if (tk == 0) {
            if (row0 < NN) { g_e1s[row0 * NHEAD + h] = es0; g_e1d[row0 * NHEAD + h] = ed0; }
            if (row1 < NN) { g_e1s[row1 * NHEAD + h] = es1; g_e1d[row1 * NHEAD + h] = ed1; }
        }
    }
}

// ---------------- layer-1 aggregation: warp per dst, fp16 gather ----------
__global__ void agg1_kernel(const float* __restrict__ b1) {
    int gw = (blockIdx.x * blockDim.x + threadIdx.x) >> 5;
    int lane = threadIdx.x & 31;
    if (gw >= NN) return;
    const int beg = g_rowptr[gw];
    const int end = g_rowptr[gw + 1];

    const int eh = lane & 7;
    const int sub = lane >> 3;
    const int myhead = lane >> 2;
    const float edh = g_e1d[gw * NHEAD + eh];

    float acc0 = 0.f, acc1 = 0.f, acc2 = 0.f, acc3 = 0.f, ssum = 0.f;
    for (int i = beg; i < end; i += 4) {
        int ei = i + sub;
        int s = 0;
        float w = 0.f;
        if (ei < end) {
            s = g_srcs[ei];
            float a = g_e1s[s * NHEAD + eh] + edh;
            a = a > 0.f ? a : NEG * a;
            w = fexp(a);
        }
#pragma unroll
        for (int j = 0; j < 4; j++) {
            float wj = __shfl_sync(0xffffffffu, w, (j << 3) + myhead);
            int   sj = __shfl_sync(0xffffffffu, s, j << 3);
            if (i + j < end) {
                // 4 fp16 channels per lane: one 8B load
                uint2 hraw = *(const uint2*)(g_h1h + (size_t)sj * H1DIM + lane * 4);
                float2 p0 = __half22float2(*(__half2*)&hraw.x);
                float2 p1 = __half22float2(*(__half2*)&hraw.y);
                acc0 = fmaf(wj, p0.x, acc0);
                acc1 = fmaf(wj, p0.y, acc1);
                acc2 = fmaf(wj, p1.x, acc2);
                acc3 = fmaf(wj, p1.y, acc3);
                ssum += wj;
            }
        }
    }

    float inv = 1.f / (ssum + 1e-16f);
    float4 bv = *(const float4*)(b1 + lane * 4);
    float v0 = acc0 * inv + bv.x;
    float v1 = acc1 * inv + bv.y;
    float v2 = acc2 * inv + bv.z;
    float v3 = acc3 * inv + bv.w;
    v0 = v0 > 0.f ? v0 : (fexp(v0) - 1.f);
    v1 = v1 > 0.f ? v1 : (fexp(v1) - 1.f);
    v2 = v2 > 0.f ? v2 : (fexp(v2) - 1.f);
    v3 = v3 > 0.f ? v3 : (fexp(v3) - 1.f);
    *(float4*)(g_hact + (size_t)gw * H1DIM + lane * 4) = make_float4(v0, v1, v2, v3);
}

// ---------------- GEMM2: thread-per-row, W2^T in smem ----------------
__global__ void gemm2_kernel(const float* __restrict__ W2,
                             const float* __restrict__ as2,
                             const float* __restrict__ ad2) {
    __shared__ float W2T[CLS][FIN];
    __shared__ float sas[CLS], sad[CLS];
    int tid = threadIdx.x;
    for (int i = tid; i < CLS * FIN; i += blockDim.x) {
        int c = i >> 7, k = i & 127;
        W2T[c][k] = W2[k * CLS + c];
    }
    if (tid < CLS) { sas[tid] = as2[tid]; sad[tid] = ad2[tid]; }
    __syncthreads();

    int row = blockIdx.x * blockDim.x + tid;
    if (row >= NN) return;
    const float* xr = g_hact + (size_t)row * FIN;

    float acc[CLS];
#pragma unroll
    for (int c = 0; c < CLS; c++) acc[c] = 0.f;

    for (int k = 0; k < FIN; k += 4) {
        float4 xv = *(const float4*)(xr + k);
#pragma unroll
        for (int c = 0; c < CLS; c++) {
            float4 wv = *(const float4*)&W2T[c][k];
            acc[c] = fmaf(xv.x, wv.x, acc[c]);
            acc[c] = fmaf(xv.y, wv.y, acc[c]);
            acc[c] = fmaf(xv.z, wv.z, acc[c]);
            acc[c] = fmaf(xv.w, wv.w, acc[c]);
        }
    }

    float es = 0.f, edv = 0.f;
#pragma unroll
    for (int c = 0; c < CLS; c++) {
        es  = fmaf(acc[c], sas[c], es);
        edv = fmaf(acc[c], sad[c], edv);
    }
    g_e2s[row] = es;
    g_e2d[row] = edv;
    float* o = g_h2 + (size_t)row * CLS;
#pragma unroll
    for (int c = 0; c < CLS; c += 4)
        *(float4*)(o + c) = make_float4(acc[c], acc[c + 1], acc[c + 2], acc[c + 3]);
}

// ---------------- layer-2 aggregation: warp per dst ----------------
__global__ void agg2_kernel(const float* __restrict__ b2, float* __restrict__ out) {
    int gw = (blockIdx.x * blockDim.x + threadIdx.x) >> 5;
    int lane = threadIdx.x & 31;
    if (gw >= NN) return;
    const int beg = g_rowptr[gw];
    const int end = g_rowptr[gw + 1];
    const float edn = g_e2d[gw];

    float acc0 = 0.f, acc1 = 0.f, ss = 0.f;
    for (int i = beg; i < end; i += 32) {
        int ei = i + lane;
        int s = 0;
        float w = 0.f;
        if (ei < end) {
            s = g_srcs[ei];
            float a = g_e2s[s] + edn;
            a = a > 0.f ? a : NEG * a;
            w = fexp(a);
        }
        int cnt = min(32, end - i);
        for (int j = 0; j < cnt; j++) {
            float wj = __shfl_sync(0xffffffffu, w, j);
            int   sj = __shfl_sync(0xffffffffu, s, j);
            acc0 = fmaf(wj, g_h2[(size_t)sj * CLS + lane], acc0);
            if (lane < 8)
                acc1 = fmaf(wj, g_h2[(size_t)sj * CLS + 32 + lane], acc1);
            ss += wj;
        }
    }
    float inv = 1.f / (ss + 1e-16f);
    out[(size_t)gw * CLS + lane] = acc0 * inv + __ldg(&b2[lane]);
    if (lane < 8)
        out[(size_t)gw * CLS + 32 + lane] = acc1 * inv + __ldg(&b2[32 + lane]);
}

// ---------------- launch ----------------
extern "C" void kernel_launch(void* const* d_in, const int* in_sizes, int n_in,
                              void* d_out, int out_size) {
    const float* x   = (const float*)d_in[0];
    const void*  ei  = d_in[1];
    const float* W1  = (const float*)d_in[2];
    const float* as1 = (const float*)d_in[3];
    const float* ad1 = (const float*)d_in[4];
    const float* b1  = (const float*)d_in[5];
    const float* W2  = (const float*)d_in[6];
    const float* as2 = (const float*)d_in[7];
    const float* ad2 = (const float*)d_in[8];
    const float* b2  = (const float*)d_in[9];
    float* out = (float*)d_out;

    static cudaStream_t s2 = nullptr;
    static cudaEvent_t evFork = nullptr, evJoin = nullptr;
    if (s2 == nullptr) {
        cudaFuncSetAttribute(gemm1_tc_kernel,
                             cudaFuncAttributeMaxDynamicSharedMemorySize, 87040);
        cudaStreamCreateWithFlags(&s2, cudaStreamNonBlocking);
        cudaEventCreateWithFlags(&evFork, cudaEventDisableTiming);
        cudaEventCreateWithFlags(&evJoin, cudaEventDisableTiming);
    }

    const int NBLK = (NN + 1023) / 1024;   // 49

    zero_kernel<<<(NN + 255) / 256, 256>>>();
    detect_kernel<<<1, 32>>>(ei);
    cudaEventRecord(evFork, 0);

    // aux stream: CSR build (independent of gemm1 chain)
    cudaStreamWaitEvent(s2, evFork, 0);
    hist_kernel<<<(ETOT + 255) / 256, 256, 0, s2>>>(ei);
    scan1_kernel<<<NBLK, 1024, 0, s2>>>();
    scan2_kernel<<<1, 32, 0, s2>>>(NBLK);
    scan3_kernel<<<NBLK, 1024, 0, s2>>>();
    scatter_kernel<<<(ETOT + 255) / 256, 256, 0, s2>>>(ei);
    cudaEventRecord(evJoin, s2);

    // main stream: feature transform
    gemm1_tc_kernel<<<(NN + G1M - 1) / G1M, 256, 87040>>>(x, W1, as1, ad1);

    cudaStreamWaitEvent(0, evJoin, 0);
    agg1_kernel<<<(NN + 7) / 8, 256>>>(b1);
    gemm2_kernel<<<(NN + 127) / 128, 128>>>(W2, as2, ad2);
    agg2_kernel<<<(NN + 7) / 8, 256>>>(b2, out);
}

// round 10
// speedup vs baseline: 2.1896x; 1.0101x over previous
#include <cuda_runtime.h>
#include <cuda_fp16.h>
#include <cstdint>

#define NN    50000
#define EE    800000
#define ETOT  (EE + NN)
#define FIN   128
#define H1DIM 128   // HEADS*HID
#define NHEAD 8
#define CLS   40
#define NEG   0.2f
#define G1M   128   // rows per gemm block

// ---------------- device scratch (static, allocation-free) ----------------
__device__ __half g_h1h[(size_t)NN * H1DIM];   // layer-1 messages, fp16
__device__ float g_hact[(size_t)NN * H1DIM];
__device__ float g_e1s[NN * NHEAD];
__device__ float g_e1d[NN * NHEAD];
__device__ float g_h2[(size_t)NN * CLS];
__device__ float g_e2s[NN];
__device__ float g_e2d[NN];
__device__ int   g_rowptr[NN + 1];
__device__ int   g_counts[NN];
__device__ int   g_fill[NN];
__device__ int   g_srcs[ETOT];
__device__ int   g_bsum[64];
__device__ int   g_boff[64];
__device__ int   g_is64;

// ---------------- fast exp: pure FFMA/ALU, no MUFU ----------------
__device__ __forceinline__ float fexp(float x) {
    float t = x * 1.442695041f;
    t = fminf(fmaxf(t, -125.f), 125.f);
    float biased = t + 12582912.f;
    int   ni = __float_as_int(biased) - 0x4B400000;
    float n  = biased - 12582912.f;
    float f  = fmaf(-n, 0.69314718056f, x);
    float p  = fmaf(f, 8.3333333e-3f, 4.1666667e-2f);
    p = fmaf(p, f, 0.16666667f);
    p = fmaf(p, f, 0.5f);
    p = fmaf(p, f, 1.0f);
    p = fmaf(p, f, 1.0f);
    return p * __int_as_float((ni + 127) << 23);
}

__device__ __forceinline__ uint32_t f2tf32(float v) {
    uint32_t u;
    asm("cvt.rna.tf32.f32 %0, %1;" : "=r"(u) : "f"(v));
    return u;
}

// ---------------- edge dtype detection (warp-parallel) ----------------
__global__ void detect_kernel(const void* ei) {
    const long long* e = (const long long*)ei;
    int lane = threadIdx.x;
    int bad = 0;
    for (int i = lane; i < 1024; i += 32) {
        long long v = e[i];
        if (v < 0 || v >= NN) bad = 1;
    }
    unsigned m = __ballot_sync(0xffffffffu, bad);
    if (lane == 0) g_is64 = (m == 0);
}

__global__ void zero_kernel() {
    int i = blockIdx.x * blockDim.x + threadIdx.x;
    if (i < NN) { g_counts[i] = 0; g_fill[i] = 0; }
}

// ---------------- hist directly from edge_index ----------------
__global__ void hist_kernel(const void* ei) {
    int i = blockIdx.x * blockDim.x + threadIdx.x;
    if (i >= ETOT) return;
    int d;
    if (i >= EE)          d = i - EE;
    else if (g_is64)      d = (int)((const long long*)ei)[EE + i];
    else                  d = ((const int*)ei)[EE + i];
    atomicAdd(&g_counts[d], 1);
}

// ---------------- hierarchical scan ----------------
__global__ void scan1_kernel() {
    __shared__ int warp_sums[32];
    int tid = threadIdx.x, lane = tid & 31, wid = tid >> 5;
    int idx = blockIdx.x * 1024 + tid;
    int v = (idx < NN) ? g_counts[idx] : 0;
    int xs = v;
#pragma unroll
    for (int off = 1; off < 32; off <<= 1) {
        int y = __shfl_up_sync(0xffffffffu, xs, off);
        if (lane >= off) xs += y;
    }
    if (lane == 31) warp_sums[wid] = xs;
    __syncthreads();
    if (wid == 0) {
        int ws = warp_sums[lane];
#pragma unroll
        for (int off = 1; off < 32; off <<= 1) {
            int y = __shfl_up_sync(0xffffffffu, ws, off);
            if (lane >= off) ws += y;
        }
        warp_sums[lane] = ws;
    }
    __syncthreads();
    int incl = xs + ((wid > 0) ? warp_sums[wid - 1] : 0);
    if (idx < NN) g_rowptr[idx + 1] = incl;
    if (tid == 1023) g_bsum[blockIdx.x] = incl;
}

__global__ void scan2_kernel(int nblk) {
    int lane = threadIdx.x;
    int i0 = 2 * lane, i1 = 2 * lane + 1;
    int a = (i0 < nblk) ? g_bsum[i0] : 0;
    int b = (i1 < nblk) ? g_bsum[i1] : 0;
    int s = a + b, xs = s;
#pragma unroll
    for (int off = 1; off < 32; off <<= 1) {
        int y = __shfl_up_sync(0xffffffffu, xs, off);
        if (lane >= off) xs += y;
    }
    int excl = xs - s;
    if (i0 < nblk) g_boff[i0] = excl;
    if (i1 < nblk) g_boff[i1] = excl + a;
}

__global__ void scan3_kernel() {
    int idx = blockIdx.x * 1024 + threadIdx.x;
    int o = g_boff[blockIdx.x];
    if (idx < NN) g_rowptr[idx + 1] += o;
    if (idx == 0) g_rowptr[0] = 0;
}

__global__ void scatter_kernel(const void* ei) {
    int i = blockIdx.x * blockDim.x + threadIdx.x;
    if (i >= ETOT) return;
    int s, d;
    if (i >= EE) {
        s = d = i - EE;
    } else if (g_is64) {
        const long long* e = (const long long*)ei;
        s = (int)e[i]; d = (int)e[EE + i];
    } else {
        const int* e = (const int*)ei;
        s = e[i]; d = e[EE + i];
    }
    int pos = g_rowptr[d] + atomicAdd(&g_fill[d], 1);
    g_srcs[pos] = s;
}

// ---------------- GEMM1 tensor cores, W resident, fused e1 epilogue -------
__global__ void __launch_bounds__(256, 2) gemm1_tc_kernel(
        const float* __restrict__ x, const float* __restrict__ W1,
        const float* __restrict__ as1, const float* __restrict__ ad1) {
    extern __shared__ uint32_t sm[];
    uint32_t* Ws = sm;                    // [n*132 + k]
    uint32_t* Xs = sm + 128 * 132;        // [row*36 + k]
    float* sa = (float*)(sm + 128 * 132 + 128 * 36);
    float* sd = sa + 128;

    const int tid = threadIdx.x;
    const int wid = tid >> 5, lane = tid & 31;
    const int g = lane >> 2, tk = lane & 3;
    const int m0 = blockIdx.x * G1M;

    for (int i = tid; i < 128 * 128; i += 256) {
        int k = i >> 7, n = i & 127;
        Ws[n * 132 + k] = f2tf32(W1[k * H1DIM + n]);
    }
    if (tid < 128) { sa[tid] = as1[tid]; sd[tid] = ad1[tid]; }

    float acc[16][4];
#pragma unroll
    for (int nt = 0; nt < 16; nt++)
#pragma unroll
        for (int j = 0; j < 4; j++) acc[nt][j] = 0.f;

    for (int kc = 0; kc < 4; kc++) {
        for (int i = tid; i < G1M * 32; i += 256) {
            int row = i >> 5, k = i & 31;
            int gr = m0 + row; if (gr >= NN) gr = NN - 1;
            Xs[row * 36 + k] = f2tf32(x[(size_t)gr * FIN + kc * 32 + k]);
        }
        __syncthreads();

#pragma unroll
        for (int ks = 0; ks < 4; ks++) {
            const int kx = ks * 8;
            const int kw = kc * 32 + ks * 8;
            const uint32_t* xa = &Xs[(wid * 16 + g) * 36 + kx + tk];
            uint32_t a0 = xa[0];
            uint32_t a1 = xa[8 * 36];
            uint32_t a2 = xa[4];
            uint32_t a3 = xa[8 * 36 + 4];
#pragma unroll
            for (int nt = 0; nt < 16; nt++) {
                const uint32_t* wb = &Ws[(nt * 8 + g) * 132 + kw + tk];
                uint32_t b0 = wb[0];
                uint32_t b1 = wb[4];
                asm volatile(
                    "mma.sync.aligned.m16n8k8.row.col.f32.tf32.tf32.f32 "
                    "{%0,%1,%2,%3}, {%4,%5,%6,%7}, {%8,%9}, {%0,%1,%2,%3};"
                    : "+f"(acc[nt][0]), "+f"(acc[nt][1]),
                      "+f"(acc[nt][2]), "+f"(acc[nt][3])
                    : "r"(a0), "r"(a1), "r"(a2), "r"(a3), "r"(b0), "r"(b1));
            }
        }
        __syncthreads();
    }

    const int row0 = m0 + wid * 16 + g;
    const int row1 = row0 + 8;
#pragma unroll
    for (int nt = 0; nt < 16; nt++) {
        int col = nt * 8 + 2 * tk;
        if (row0 < NN)
            *(__half2*)&g_h1h[(size_t)row0 * H1DIM + col] =
                __floats2half2_rn(acc[nt][0], acc[nt][1]);
        if (row1 < NN)
            *(__half2*)&g_h1h[(size_t)row1 * H1DIM + col] =
                __floats2half2_rn(acc[nt][2], acc[nt][3]);
    }

#pragma unroll
    for (int h = 0; h < 8; h++) {
        float es0 = 0.f, ed0 = 0.f, es1 = 0.f, ed1 = 0.f;
#pragma unroll
        for (int q = 0; q < 2; q++) {
            int nt = 2 * h + q;
            int col = nt * 8 + 2 * tk;
            float av0 = sa[col], av1 = sa[col + 1];
            float dv0 = sd[col], dv1 = sd[col + 1];
            es0 += acc[nt][0] * av0 + acc[nt][1] * av1;
            ed0 += acc[nt][0] * dv0 + acc[nt][1] * dv1;
            es1 += acc[nt][2] * av0 + acc[nt][3] * av1;
            ed1 += acc[nt][2] * dv0 + acc[nt][3] * dv1;
        }
        es0 += __shfl_down_sync(0xffffffffu, es0, 2);
        es0 += __shfl_down_sync(0xffffffffu, es0, 1);
        ed0 += __shfl_down_sync(0xffffffffu, ed0, 2);
        ed0 += __shfl_down_sync(0xffffffffu, ed0, 1);
        es1 += __shfl_down_sync(0xffffffffu, es1, 2);
        es1 += __shfl_down_sync(0xffffffffu, es1, 1);
        ed1 += __shfl_down_sync(0xffffffffu, ed1, 2);
        ed1 += __shfl_down_sync(0xffffffffu, ed1, 1);
        if (tk == 0) {
            if (row0 < NN) { g_e1s[row0 * NHEAD + h] = es0; g_e1d[row0 * NHEAD + h] = ed0; }
            if (row1 < NN) { g_e1s[row1 * NHEAD + h] = es1; g_e1d[row1 * NHEAD + h] = ed1; }
        }
    }
}

// ---------------- layer-1 aggregation: warp per dst, fp16 gather ----------
__global__ void agg1_kernel(const float* __restrict__ b1) {
    int gw = (blockIdx.x * blockDim.x + threadIdx.x) >> 5;
    int lane = threadIdx.x & 31;
    if (gw >= NN) return;
    const int beg = g_rowptr[gw];
    const int end = g_rowptr[gw + 1];

    const int eh = lane & 7;
    const int sub = lane >> 3;
    const int myhead = lane >> 2;
    const float edh = g_e1d[gw * NHEAD + eh];

    float acc0 = 0.f, acc1 = 0.f, acc2 = 0.f, acc3 = 0.f, ssum = 0.f;
    for (int i = beg; i < end; i += 4) {
        int ei = i + sub;
        int s = 0;
        float w = 0.f;
        if (ei < end) {
            s = g_srcs[ei];
            float a = g_e1s[s * NHEAD + eh] + edh;
            a = a > 0.f ? a : NEG * a;
            w = fexp(a);
        }
#pragma unroll
        for (int j = 0; j < 4; j++) {
            float wj = __shfl_sync(0xffffffffu, w, (j << 3) + myhead);
            int   sj = __shfl_sync(0xffffffffu, s, j << 3);
            if (i + j < end) {
                uint2 hraw = *(const uint2*)(g_h1h + (size_t)sj * H1DIM + lane * 4);
                float2 p0 = __half22float2(*(__half2*)&hraw.x);
                float2 p1 = __half22float2(*(__half2*)&hraw.y);
                acc0 = fmaf(wj, p0.x, acc0);
                acc1 = fmaf(wj, p0.y, acc1);
                acc2 = fmaf(wj, p1.x, acc2);
                acc3 = fmaf(wj, p1.y, acc3);
                ssum += wj;
            }
        }
    }

    float inv = 1.f / (ssum + 1e-16f);
    float4 bv = *(const float4*)(b1 + lane * 4);
    float v0 = acc0 * inv + bv.x;
    float v1 = acc1 * inv + bv.y;
    float v2 = acc2 * inv + bv.z;
    float v3 = acc3 * inv + bv.w;
    v0 = v0 > 0.f ? v0 : (fexp(v0) - 1.f);
    v1 = v1 > 0.f ? v1 : (fexp(v1) - 1.f);
    v2 = v2 > 0.f ? v2 : (fexp(v2) - 1.f);
    v3 = v3 > 0.f ? v3 : (fexp(v3) - 1.f);
    *(float4*)(g_hact + (size_t)gw * H1DIM + lane * 4) = make_float4(v0, v1, v2, v3);
}

// ---------------- GEMM2 tensor cores: h2 = hact @ W2, fused e2 epilogue ---
// 256 threads (8 warps x m16), 128 rows/block, N=40 (5 n-tiles), K=128.
__global__ void __launch_bounds__(256, 2) gemm2_tc_kernel(
        const float* __restrict__ W2,
        const float* __restrict__ as2, const float* __restrict__ ad2) {
    __shared__ uint32_t Ws[CLS * 132];     // [n*132 + k], ~21KB
    __shared__ uint32_t Xs[G1M * 36];      // [row*36 + k], 18KB
    __shared__ float sas[CLS], sad[CLS];

    const int tid = threadIdx.x;
    const int wid = tid >> 5, lane = tid & 31;
    const int g = lane >> 2, tk = lane & 3;
    const int m0 = blockIdx.x * G1M;

    // stage W2 (transpose to n-major)
    for (int i = tid; i < CLS * 128; i += 256) {
        int k = i >> 5 >> 2;                 // i / 128... careful: use div
        k = i / CLS;                          // overwritten below
        // simpler: iterate n-major
        ;
    }
    // (re-do cleanly)
    for (int i = tid; i < CLS * 128; i += 256) {
        int n = i / 128, k = i % 128;
        Ws[n * 132 + k] = f2tf32(W2[k * CLS + n]);
    }
    if (tid < CLS) { sas[tid] = as2[tid]; sad[tid] = ad2[tid]; }

    float acc[5][4];
#pragma unroll
    for (int nt = 0; nt < 5; nt++)
#pragma unroll
        for (int j = 0; j < 4; j++) acc[nt][j] = 0.f;

    for (int kc = 0; kc < 4; kc++) {
        for (int i = tid; i < G1M * 32; i += 256) {
            int row = i >> 5, k = i & 31;
            int gr = m0 + row; if (gr >= NN) gr = NN - 1;
            Xs[row * 36 + k] = f2tf32(g_hact[(size_t)gr * FIN + kc * 32 + k]);
        }
        __syncthreads();

#pragma unroll
        for (int ks = 0; ks < 4; ks++) {
            const int kx = ks * 8;
            const int kw = kc * 32 + ks * 8;
            const uint32_t* xa = &Xs[(wid * 16 + g) * 36 + kx + tk];
            uint32_t a0 = xa[0];
            uint32_t a1 = xa[8 * 36];
            uint32_t a2 = xa[4];
            uint32_t a3 = xa[8 * 36 + 4];
#pragma unroll
            for (int nt = 0; nt < 5; nt++) {
                const uint32_t* wb = &Ws[(nt * 8 + g) * 132 + kw + tk];
                uint32_t b0 = wb[0];
                uint32_t b1 = wb[4];
                asm volatile(
                    "mma.sync.aligned.m16n8k8.row.col.f32.tf32.tf32.f32 "
                    "{%0,%1,%2,%3}, {%4,%5,%6,%7}, {%8,%9}, {%0,%1,%2,%3};"
                    : "+f"(acc[nt][0]), "+f"(acc[nt][1]),
                      "+f"(acc[nt][2]), "+f"(acc[nt][3])
                    : "r"(a0), "r"(a1), "r"(a2), "r"(a3), "r"(b0), "r"(b1));
            }
        }
        __syncthreads();
    }

    // epilogue: store h2 + fused e2s/e2d
    const int row0 = m0 + wid * 16 + g;
    const int row1 = row0 + 8;
#pragma unroll
    for (int nt = 0; nt < 5; nt++) {
        int col = nt * 8 + 2 * tk;
        if (row0 < NN)
            *(float2*)&g_h2[(size_t)row0 * CLS + col] =
                make_float2(acc[nt][0], acc[nt][1]);
        if (row1 < NN)
            *(float2*)&g_h2[(size_t)row1 * CLS + col] =
                make_float2(acc[nt][2], acc[nt][3]);
    }

    float es0 = 0.f, ed0 = 0.f, es1 = 0.f, ed1 = 0.f;
#pragma unroll
    for (int nt = 0; nt < 5; nt++) {
        int col = nt * 8 + 2 * tk;
        float av0 = sas[col], av1 = sas[col + 1];
        float dv0 = sad[col], dv1 = sad[col + 1];
        es0 += acc[nt][0] * av0 + acc[nt][1] * av1;
        ed0 += acc[nt][0] * dv0 + acc[nt][1] * dv1;
        es1 += acc[nt][2] * av0 + acc[nt][3] * av1;
        ed1 += acc[nt][2] * dv0 + acc[nt][3] * dv1;
    }
    es0 += __shfl_down_sync(0xffffffffu, es0, 2);
    es0 += __shfl_down_sync(0xffffffffu, es0, 1);
    ed0 += __shfl_down_sync(0xffffffffu, ed0, 2);
    ed0 += __shfl_down_sync(0xffffffffu, ed0, 1);
    es1 += __shfl_down_sync(0xffffffffu, es1, 2);
    es1 += __shfl_down_sync(0xffffffffu, es1, 1);
    ed1 += __shfl_down_sync(0xffffffffu, ed1, 2);
    ed1 += __shfl_down_sync(0xffffffffu, ed1, 1);
    if (tk == 0) {
        if (row0 < NN) { g_e2s[row0] = es0; g_e2d[row0] = ed0; }
        if (row1 < NN) { g_e2s[row1] = es1; g_e2d[row1] = ed1; }
    }
}

// ---------------- layer-2 aggregation: warp per dst, 4-edge batched -------
__global__ void agg2_kernel(const float* __restrict__ b2, float* __restrict__ out) {
    int gw = (blockIdx.x * blockDim.x + threadIdx.x) >> 5;
    int lane = threadIdx.x & 31;
    if (gw >= NN) return;
    const int beg = g_rowptr[gw];
    const int end = g_rowptr[gw + 1];
    const float edn = g_e2d[gw];

    float acc0 = 0.f, acc1 = 0.f, ss = 0.f;
    for (int i = beg; i < end; i += 4) {
        int ei = i + (lane & 3);
        int s = 0;
        float w = 0.f;
        if (ei < end) {
            s = g_srcs[ei];
            float a = g_e2s[s] + edn;
            a = a > 0.f ? a : NEG * a;
            w = fexp(a);
        }
#pragma unroll
        for (int j = 0; j < 4; j++) {
            float wj = __shfl_sync(0xffffffffu, w, j);
            int   sj = __shfl_sync(0xffffffffu, s, j);
            if (i + j < end) {
                acc0 = fmaf(wj, g_h2[(size_t)sj * CLS + lane], acc0);
                if (lane < 8)
                    acc1 = fmaf(wj, g_h2[(size_t)sj * CLS + 32 + lane], acc1);
                ss += wj;
            }
        }
    }
    float inv = 1.f / (ss + 1e-16f);
    out[(size_t)gw * CLS + lane] = acc0 * inv + __ldg(&b2[lane]);
    if (lane < 8)
        out[(size_t)gw * CLS + 32 + lane] = acc1 * inv + __ldg(&b2[32 + lane]);
}

// ---------------- launch ----------------
extern "C" void kernel_launch(void* const* d_in, const int* in_sizes, int n_in,
                              void* d_out, int out_size) {
    const float* x   = (const float*)d_in[0];
    const void*  ei  = d_in[1];
    const float* W1  = (const float*)d_in[2];
    const float* as1 = (const float*)d_in[3];
    const float* ad1 = (const float*)d_in[4];
    const float* b1  = (const float*)d_in[5];
    const float* W2  = (const float*)d_in[6];
    const float* as2 = (const float*)d_in[7];
    const float* ad2 = (const float*)d_in[8];
    const float* b2  = (const float*)d_in[9];
    float* out = (float*)d_out;

    static cudaStream_t s2 = nullptr;
    static cudaEvent_t evFork = nullptr, evJoin = nullptr;
    if (s2 == nullptr) {
        cudaFuncSetAttribute(gemm1_tc_kernel,
                             cudaFuncAttributeMaxDynamicSharedMemorySize, 87040);
        cudaStreamCreateWithFlags(&s2, cudaStreamNonBlocking);
        cudaEventCreateWithFlags(&evFork, cudaEventDisableTiming);
        cudaEventCreateWithFlags(&evJoin, cudaEventDisableTiming);
    }

    const int NBLK = (NN + 1023) / 1024;   // 49

    zero_kernel<<<(NN + 255) / 256, 256>>>();
    detect_kernel<<<1, 32>>>(ei);
    cudaEventRecord(evFork, 0);

    // aux stream: CSR build (independent of gemm1 chain)
    cudaStreamWaitEvent(s2, evFork, 0);
    hist_kernel<<<(ETOT + 255) / 256, 256, 0, s2>>>(ei);
    scan1_kernel<<<NBLK, 1024, 0, s2>>>();
    scan2_kernel<<<1, 32, 0, s2>>>(NBLK);
    scan3_kernel<<<NBLK, 1024, 0, s2>>>();
    scatter_kernel<<<(ETOT + 255) / 256, 256, 0, s2>>>(ei);
    cudaEventRecord(evJoin, s2);

    // main stream: feature transform
    gemm1_tc_kernel<<<(NN + G1M - 1) / G1M, 256, 87040>>>(x, W1, as1, ad1);

    cudaStreamWaitEvent(0, evJoin, 0);
    agg1_kernel<<<(NN + 7) / 8, 256>>>(b1);
    gemm2_tc_kernel<<<(NN + G1M - 1) / G1M, 256>>>(W2, as2, ad2);
    agg2_kernel<<<(NN + 7) / 8, 256>>>(b2, out);
}

// round 11
// speedup vs baseline: 2.5354x; 1.1579x over previous
#include <cuda_runtime.h>
#include <cuda_fp16.h>
#include <cstdint>

#define NN    50000
#define EE    800000
#define ETOT  (EE + NN)
#define FIN   128
#define H1DIM 128   // HEADS*HID
#define NHEAD 8
#define CLS   40
#define NEG   0.2f
#define G1M   128   // rows per gemm block
#define NBLK  49    // scan blocks

// ---------------- device scratch (static, allocation-free) ----------------
__device__ __half   g_h1h[(size_t)NN * H1DIM];   // layer-1 messages, fp16
__device__ float    g_hact[(size_t)NN * H1DIM];
__device__ float    g_e1s[NN * NHEAD];
__device__ float    g_e1d[NN * NHEAD];
__device__ float    g_h2[(size_t)NN * CLS];
__device__ float    g_e2s[NN];
__device__ float    g_e2d[NN];
__device__ int      g_rowptr[NN + 1];
__device__ int      g_counts[NN];
__device__ int      g_fill[NN];
__device__ int      g_srcs[ETOT];
__device__ int      g_bsum[64];
__device__ uint32_t g_w1t[FIN * H1DIM];          // tf32 W1, n-major [n*128+k]
__device__ int      g_is64;

// ---------------- fast exp: pure FFMA/ALU, no MUFU ----------------
__device__ __forceinline__ float fexp(float x) {
    float t = x * 1.442695041f;
    t = fminf(fmaxf(t, -125.f), 125.f);
    float biased = t + 12582912.f;
    int   ni = __float_as_int(biased) - 0x4B400000;
    float n  = biased - 12582912.f;
    float f  = fmaf(-n, 0.69314718056f, x);
    float p  = fmaf(f, 8.3333333e-3f, 4.1666667e-2f);
    p = fmaf(p, f, 0.16666667f);
    p = fmaf(p, f, 0.5f);
    p = fmaf(p, f, 1.0f);
    p = fmaf(p, f, 1.0f);
    return p * __int_as_float((ni + 127) << 23);
}

__device__ __forceinline__ uint32_t f2tf32(float v) {
    uint32_t u;
    asm("cvt.rna.tf32.f32 %0, %1;" : "=r"(u) : "f"(v));
    return u;
}

// ---------------- zero + edge dtype detect (fused) ----------------
__global__ void zero_detect_kernel(const void* ei) {
    int i = blockIdx.x * blockDim.x + threadIdx.x;
    if (i < NN) { g_counts[i] = 0; g_fill[i] = 0; }
    if (blockIdx.x == 0 && threadIdx.x < 32) {
        const long long* e = (const long long*)ei;
        int lane = threadIdx.x;
        int bad = 0;
        for (int j = lane; j < 1024; j += 32) {
            long long v = e[j];
            if (v < 0 || v >= NN) bad = 1;
        }
        unsigned m = __ballot_sync(0xffffffffu, bad);
        if (lane == 0) g_is64 = (m == 0);
    }
}

// ---------------- precompute tf32 n-major W1 ----------------
__global__ void wt_kernel(const float* __restrict__ W1) {
    int i = blockIdx.x * blockDim.x + threadIdx.x;   // 16384 threads
    if (i >= FIN * H1DIM) return;
    int n = i >> 7, k = i & 127;
    g_w1t[i] = f2tf32(W1[k * H1DIM + n]);
}

// ---------------- hist directly from edge_index ----------------
__global__ void hist_kernel(const void* ei) {
    int i = blockIdx.x * blockDim.x + threadIdx.x;
    if (i >= ETOT) return;
    int d;
    if (i >= EE)          d = i - EE;
    else if (g_is64)      d = (int)((const long long*)ei)[EE + i];
    else                  d = ((const int*)ei)[EE + i];
    atomicAdd(&g_counts[d], 1);
}

// ---------------- hierarchical scan ----------------
__global__ void scan1_kernel() {
    __shared__ int warp_sums[32];
    int tid = threadIdx.x, lane = tid & 31, wid = tid >> 5;
    int idx = blockIdx.x * 1024 + tid;
    int v = (idx < NN) ? g_counts[idx] : 0;
    int xs = v;
#pragma unroll
    for (int off = 1; off < 32; off <<= 1) {
        int y = __shfl_up_sync(0xffffffffu, xs, off);
        if (lane >= off) xs += y;
    }
    if (lane == 31) warp_sums[wid] = xs;
    __syncthreads();
    if (wid == 0) {
        int ws = warp_sums[lane];
#pragma unroll
        for (int off = 1; off < 32; off <<= 1) {
            int y = __shfl_up_sync(0xffffffffu, ws, off);
            if (lane >= off) ws += y;
        }
        warp_sums[lane] = ws;
    }
    __syncthreads();
    int incl = xs + ((wid > 0) ? warp_sums[wid - 1] : 0);
    if (idx < NN) g_rowptr[idx + 1] = incl;
    if (tid == 1023) g_bsum[blockIdx.x] = incl;
}

// scan2+scan3 fused: each block computes its own offset from g_bsum
__global__ void scan23_kernel() {
    __shared__ int soff;
    int tid = threadIdx.x;
    if (tid < 32) {
        int b = blockIdx.x;
        int c = 0;
        if (tid < b)      c += g_bsum[tid];
        if (tid + 32 < b) c += g_bsum[tid + 32];
#pragma unroll
        for (int off = 16; off > 0; off >>= 1)
            c += __shfl_down_sync(0xffffffffu, c, off);
        if (tid == 0) soff = c;
    }
    __syncthreads();
    int idx = blockIdx.x * 1024 + tid;
    if (idx < NN) g_rowptr[idx + 1] += soff;
    if (idx == 0) g_rowptr[0] = 0;
}

__global__ void scatter_kernel(const void* ei) {
    int i = blockIdx.x * blockDim.x + threadIdx.x;
    if (i >= ETOT) return;
    int s, d;
    if (i >= EE) {
        s = d = i - EE;
    } else if (g_is64) {
        const long long* e = (const long long*)ei;
        s = (int)e[i]; d = (int)e[EE + i];
    } else {
        const int* e = (const int*)ei;
        s = e[i]; d = e[EE + i];
    }
    int pos = g_rowptr[d] + atomicAdd(&g_fill[d], 1);
    g_srcs[pos] = s;
}

// ---------------- GEMM1 tensor cores, prefetched X, fused e1 epilogue -----
__global__ void __launch_bounds__(256, 2) gemm1_tc_kernel(
        const float* __restrict__ x,
        const float* __restrict__ as1, const float* __restrict__ ad1) {
    extern __shared__ uint32_t sm[];
    uint32_t* Ws = sm;                    // [n*132 + k]
    uint32_t* Xs = sm + 128 * 132;        // [row*36 + k]
    float* sa = (float*)(sm + 128 * 132 + 128 * 36);
    float* sd = sa + 128;

    const int tid = threadIdx.x;
    const int wid = tid >> 5, lane = tid & 31;
    const int g = lane >> 2, tk = lane & 3;
    const int m0 = blockIdx.x * G1M;

    // stage precomputed tf32 W1: pure LDG.128 -> STS.128
    {
        const uint4* wt4 = (const uint4*)g_w1t;
        for (int i = tid; i < 4096; i += 256) {
            uint4 v = wt4[i];
            int n = i >> 5, k = (i & 31) * 4;
            *(uint4*)&Ws[n * 132 + k] = v;
        }
    }
    if (tid < 128) { sa[tid] = as1[tid]; sd[tid] = ad1[tid]; }

    float acc[16][4];
#pragma unroll
    for (int nt = 0; nt < 16; nt++)
#pragma unroll
        for (int j = 0; j < 4; j++) acc[nt][j] = 0.f;

    // register double-buffer for X chunks (each thread: 4 float4 = 16 vals)
    float4 xp[4];
#pragma unroll
    for (int j = 0; j < 4; j++) {
        int idx = tid + j * 256;
        int row = idx >> 3, k4 = (idx & 7) * 4;
        int gr = m0 + row; if (gr >= NN) gr = NN - 1;
        xp[j] = *(const float4*)&x[(size_t)gr * FIN + k4];
    }

    for (int kc = 0; kc < 4; kc++) {
        // store current chunk to smem (cvt to tf32)
#pragma unroll
        for (int j = 0; j < 4; j++) {
            int idx = tid + j * 256;
            int row = idx >> 3, k4 = (idx & 7) * 4;
            uint4 t;
            t.x = f2tf32(xp[j].x); t.y = f2tf32(xp[j].y);
            t.z = f2tf32(xp[j].z); t.w = f2tf32(xp[j].w);
            *(uint4*)&Xs[row * 36 + k4] = t;
        }
        __syncthreads();

        // prefetch next chunk while MMAs run
        if (kc < 3) {
#pragma unroll
            for (int j = 0; j < 4; j++) {
                int idx = tid + j * 256;
                int row = idx >> 3, k4 = (idx & 7) * 4;
                int gr = m0 + row; if (gr >= NN) gr = NN - 1;
                xp[j] = *(const float4*)&x[(size_t)gr * FIN + (kc + 1) * 32 + k4];
            }
        }

#pragma unroll
        for (int ks = 0; ks < 4; ks++) {
            const int kx = ks * 8;
            const int kw = kc * 32 + ks * 8;
            const uint32_t* xa = &Xs[(wid * 16 + g) * 36 + kx + tk];
            uint32_t a0 = xa[0];
            uint32_t a1 = xa[8 * 36];
            uint32_t a2 = xa[4];
            uint32_t a3 = xa[8 * 36 + 4];
#pragma unroll
            for (int nt = 0; nt < 16; nt++) {
                const uint32_t* wb = &Ws[(nt * 8 + g) * 132 + kw + tk];
                uint32_t b0 = wb[0];
                uint32_t b1 = wb[4];
                asm volatile(
                    "mma.sync.aligned.m16n8k8.row.col.f32.tf32.tf32.f32 "
                    "{%0,%1,%2,%3}, {%4,%5,%6,%7}, {%8,%9}, {%0,%1,%2,%3};"
                    : "+f"(acc[nt][0]), "+f"(acc[nt][1]),
                      "+f"(acc[nt][2]), "+f"(acc[nt][3])
                    : "r"(a0), "r"(a1), "r"(a2), "r"(a3), "r"(b0), "r"(b1));
            }
        }
        __syncthreads();
    }

    const int row0 = m0 + wid * 16 + g;
    const int row1 = row0 + 8;
#pragma unroll
    for (int nt = 0; nt < 16; nt++) {
        int col = nt * 8 + 2 * tk;
        if (row0 < NN)
            *(__half2*)&g_h1h[(size_t)row0 * H1DIM + col] =
                __floats2half2_rn(acc[nt][0], acc[nt][1]);
        if (row1 < NN)
            *(__half2*)&g_h1h[(size_t)row1 * H1DIM + col] =
                __floats2half2_rn(acc[nt][2], acc[nt][3]);
    }

#pragma unroll
    for (int h = 0; h < 8; h++) {
        float es0 = 0.f, ed0 = 0.f, es1 = 0.f, ed1 = 0.f;
#pragma unroll
        for (int q = 0; q < 2; q++) {
            int nt = 2 * h + q;
            int col = nt * 8 + 2 * tk;
            float av0 = sa[col], av1 = sa[col + 1];
            float dv0 = sd[col], dv1 = sd[col + 1];
            es0 += acc[nt][0] * av0 + acc[nt][1] * av1;
            ed0 += acc[nt][0] * dv0 + acc[nt][1] * dv1;
            es1 += acc[nt][2] * av0 + acc[nt][3] * av1;
            ed1 += acc[nt][2] * dv0 + acc[nt][3] * dv1;
        }
        es0 += __shfl_down_sync(0xffffffffu, es0, 2);
        es0 += __shfl_down_sync(0xffffffffu, es0, 1);
        ed0 += __shfl_down_sync(0xffffffffu, ed0, 2);
        ed0 += __shfl_down_sync(0xffffffffu, ed0, 1);
        es1 += __shfl_down_sync(0xffffffffu, es1, 2);
        es1 += __shfl_down_sync(0xffffffffu, es1, 1);
        ed1 += __shfl_down_sync(0xffffffffu, ed1, 2);
        ed1 += __shfl_down_sync(0xffffffffu, ed1, 1);
        if (tk == 0) {
            if (row0 < NN) { g_e1s[row0 * NHEAD + h] = es0; g_e1d[row0 * NHEAD + h] = ed0; }
            if (row1 < NN) { g_e1s[row1 * NHEAD + h] = es1; g_e1d[row1 * NHEAD + h] = ed1; }
        }
    }
}

// ---------------- layer-1 aggregation: warp per dst, fp16 gather ----------
__global__ void agg1_kernel(const float* __restrict__ b1) {
    int gw = (blockIdx.x * blockDim.x + threadIdx.x) >> 5;
    int lane = threadIdx.x & 31;
    if (gw >= NN) return;
    const int beg = g_rowptr[gw];
    const int end = g_rowptr[gw + 1];

    const int eh = lane & 7;
    const int sub = lane >> 3;
    const int myhead = lane >> 2;
    const float edh = g_e1d[gw * NHEAD + eh];

    float acc0 = 0.f, acc1 = 0.f, acc2 = 0.f, acc3 = 0.f, ssum = 0.f;
    for (int i = beg; i < end; i += 4) {
        int ei = i + sub;
        int s = 0;
        float w = 0.f;
        if (ei < end) {
            s = g_srcs[ei];
            float a = g_e1s[s * NHEAD + eh] + edh;
            a = a > 0.f ? a : NEG * a;
            w = fexp(a);
        }
#pragma unroll
        for (int j = 0; j < 4; j++) {
            float wj = __shfl_sync(0xffffffffu, w, (j << 3) + myhead);
            int   sj = __shfl_sync(0xffffffffu, s, j << 3);
            if (i + j < end) {
                uint2 hraw = *(const uint2*)(g_h1h + (size_t)sj * H1DIM + lane * 4);
                float2 p0 = __half22float2(*(__half2*)&hraw.x);
                float2 p1 = __half22float2(*(__half2*)&hraw.y);
                acc0 = fmaf(wj, p0.x, acc0);
                acc1 = fmaf(wj, p0.y, acc1);
                acc2 = fmaf(wj, p1.x, acc2);
                acc3 = fmaf(wj, p1.y, acc3);
                ssum += wj;
            }
        }
    }

    float inv = 1.f / (ssum + 1e-16f);
    float4 bv = *(const float4*)(b1 + lane * 4);
    float v0 = acc0 * inv + bv.x;
    float v1 = acc1 * inv + bv.y;
    float v2 = acc2 * inv + bv.z;
    float v3 = acc3 * inv + bv.w;
    v0 = v0 > 0.f ? v0 : (fexp(v0) - 1.f);
    v1 = v1 > 0.f ? v1 : (fexp(v1) - 1.f);
    v2 = v2 > 0.f ? v2 : (fexp(v2) - 1.f);
    v3 = v3 > 0.f ? v3 : (fexp(v3) - 1.f);
    *(float4*)(g_hact + (size_t)gw * H1DIM + lane * 4) = make_float4(v0, v1, v2, v3);
}

// ---------------- GEMM2 tensor cores: h2 = hact @ W2, fused e2 epilogue ---
__global__ void __launch_bounds__(256, 2) gemm2_tc_kernel(
        const float* __restrict__ W2,
        const float* __restrict__ as2, const float* __restrict__ ad2) {
    __shared__ uint32_t Ws[CLS * 132];
    __shared__ uint32_t Xs[G1M * 36];
    __shared__ float sas[CLS], sad[CLS];

    const int tid = threadIdx.x;
    const int wid = tid >> 5, lane = tid & 31;
    const int g = lane >> 2, tk = lane & 3;
    const int m0 = blockIdx.x * G1M;

    for (int i = tid; i < CLS * 128; i += 256) {
        int n = i / 128, k = i % 128;
        Ws[n * 132 + k] = f2tf32(W2[k * CLS + n]);
    }
    if (tid < CLS) { sas[tid] = as2[tid]; sad[tid] = ad2[tid]; }

    float acc[5][4];
#pragma unroll
    for (int nt = 0; nt < 5; nt++)
#pragma unroll
        for (int j = 0; j < 4; j++) acc[nt][j] = 0.f;

    float4 xp[4];
#pragma unroll
    for (int j = 0; j < 4; j++) {
        int idx = tid + j * 256;
        int row = idx >> 3, k4 = (idx & 7) * 4;
        int gr = m0 + row; if (gr >= NN) gr = NN - 1;
        xp[j] = *(const float4*)&g_hact[(size_t)gr * FIN + k4];
    }

    for (int kc = 0; kc < 4; kc++) {
#pragma unroll
        for (int j = 0; j < 4; j++) {
            int idx = tid + j * 256;
            int row = idx >> 3, k4 = (idx & 7) * 4;
            uint4 t;
            t.x = f2tf32(xp[j].x); t.y = f2tf32(xp[j].y);
            t.z = f2tf32(xp[j].z); t.w = f2tf32(xp[j].w);
            *(uint4*)&Xs[row * 36 + k4] = t;
        }
        __syncthreads();

        if (kc < 3) {
#pragma unroll
            for (int j = 0; j < 4; j++) {
                int idx = tid + j * 256;
                int row = idx >> 3, k4 = (idx & 7) * 4;
                int gr = m0 + row; if (gr >= NN) gr = NN - 1;
                xp[j] = *(const float4*)&g_hact[(size_t)gr * FIN + (kc + 1) * 32 + k4];
            }
        }

#pragma unroll
        for (int ks = 0; ks < 4; ks++) {
            const int kx = ks * 8;
            const int kw = kc * 32 + ks * 8;
            const uint32_t* xa = &Xs[(wid * 16 + g) * 36 + kx + tk];
            uint32_t a0 = xa[0];
            uint32_t a1 = xa[8 * 36];
            uint32_t a2 = xa[4];
            uint32_t a3 = xa[8 * 36 + 4];
#pragma unroll
            for (int nt = 0; nt < 5; nt++) {
                const uint32_t* wb = &Ws[(nt * 8 + g) * 132 + kw + tk];
                uint32_t b0 = wb[0];
                uint32_t b1 = wb[4];
                asm volatile(
                    "mma.sync.aligned.m16n8k8.row.col.f32.tf32.tf32.f32 "
                    "{%0,%1,%2,%3}, {%4,%5,%6,%7}, {%8,%9}, {%0,%1,%2,%3};"
                    : "+f"(acc[nt][0]), "+f"(acc[nt][1]),
                      "+f"(acc[nt][2]), "+f"(acc[nt][3])
                    : "r"(a0), "r"(a1), "r"(a2), "r"(a3), "r"(b0), "r"(b1));
            }
        }
        __syncthreads();
    }

    const int row0 = m0 + wid * 16 + g;
    const int row1 = row0 + 8;
#pragma unroll
    for (int nt = 0; nt < 5; nt++) {
        int col = nt * 8 + 2 * tk;
        if (row0 < NN)
            *(float2*)&g_h2[(size_t)row0 * CLS + col] =
                make_float2(acc[nt][0], acc[nt][1]);
        if (row1 < NN)
            *(float2*)&g_h2[(size_t)row1 * CLS + col] =
                make_float2(acc[nt][2], acc[nt][3]);
    }

    float es0 = 0.f, ed0 = 0.f, es1 = 0.f, ed1 = 0.f;
#pragma unroll
    for (int nt = 0; nt < 5; nt++) {
        int col = nt * 8 + 2 * tk;
        float av0 = sas[col], av1 = sas[col + 1];
        float dv0 = sad[col], dv1 = sad[col + 1];
        es0 += acc[nt][0] * av0 + acc[nt][1] * av1;
        ed0 += acc[nt][0] * dv0 + acc[nt][1] * dv1;
        es1 += acc[nt][2] * av0 + acc[nt][3] * av1;
        ed1 += acc[nt][2] * dv0 + acc[nt][3] * dv1;
    }
    es0 += __shfl_down_sync(0xffffffffu, es0, 2);
    es0 += __shfl_down_sync(0xffffffffu, es0, 1);
    ed0 += __shfl_down_sync(0xffffffffu, ed0, 2);
    ed0 += __shfl_down_sync(0xffffffffu, ed0, 1);
    es1 += __shfl_down_sync(0xffffffffu, es1, 2);
    es1 += __shfl_down_sync(0xffffffffu, es1, 1);
    ed1 += __shfl_down_sync(0xffffffffu, ed1, 2);
    ed1 += __shfl_down_sync(0xffffffffu, ed1, 1);
    if (tk == 0) {
        if (row0 < NN) { g_e2s[row0] = es0; g_e2d[row0] = ed0; }
        if (row1 < NN) { g_e2s[row1] = es1; g_e2d[row1] = ed1; }
    }
}

// ---------------- layer-2 aggregation: warp per dst, 4-edge batched -------
__global__ void agg2_kernel(const float* __restrict__ b2, float* __restrict__ out) {
    int gw = (blockIdx.x * blockDim.x + threadIdx.x) >> 5;
    int lane = threadIdx.x & 31;
    if (gw >= NN) return;
    const int beg = g_rowptr[gw];
    const int end = g_rowptr[gw + 1];
    const float edn = g_e2d[gw];

    float acc0 = 0.f, acc1 = 0.f, ss = 0.f;
    for (int i = beg; i < end; i += 4) {
        int ei = i + (lane & 3);
        int s = 0;
        float w = 0.f;
        if (ei < end) {
            s = g_srcs[ei];
            float a = g_e2s[s] + edn;
            a = a > 0.f ? a : NEG * a;
            w = fexp(a);
        }
#pragma unroll
        for (int j = 0; j < 4; j++) {
            float wj = __shfl_sync(0xffffffffu, w, j);
            int   sj = __shfl_sync(0xffffffffu, s, j);
            if (i + j < end) {
                acc0 = fmaf(wj, g_h2[(size_t)sj * CLS + lane], acc0);
                if (lane < 8)
                    acc1 = fmaf(wj, g_h2[(size_t)sj * CLS + 32 + lane], acc1);
                ss += wj;
            }
        }
    }
    float inv = 1.f / (ss + 1e-16f);
    out[(size_t)gw * CLS + lane] = acc0 * inv + __ldg(&b2[lane]);
    if (lane < 8)
        out[(size_t)gw * CLS + 32 + lane] = acc1 * inv + __ldg(&b2[32 + lane]);
}

// ---------------- launch ----------------
extern "C" void kernel_launch(void* const* d_in, const int* in_sizes, int n_in,
                              void* d_out, int out_size) {
    const float* x   = (const float*)d_in[0];
    const void*  ei  = d_in[1];
    const float* W1  = (const float*)d_in[2];
    const float* as1 = (const float*)d_in[3];
    const float* ad1 = (const float*)d_in[4];
    const float* b1  = (const float*)d_in[5];
    const float* W2  = (const float*)d_in[6];
    const float* as2 = (const float*)d_in[7];
    const float* ad2 = (const float*)d_in[8];
    const float* b2  = (const float*)d_in[9];
    float* out = (float*)d_out;

    static cudaStream_t s2 = nullptr;
    static cudaEvent_t evFork = nullptr, evJoin = nullptr;
    if (s2 == nullptr) {
        cudaFuncSetAttribute(gemm1_tc_kernel,
                             cudaFuncAttributeMaxDynamicSharedMemorySize, 87040);
        cudaStreamCreateWithFlags(&s2, cudaStreamNonBlocking);
        cudaEventCreateWithFlags(&evFork, cudaEventDisableTiming);
        cudaEventCreateWithFlags(&evJoin, cudaEventDisableTiming);
    }

    // submission order chosen so gemm1_tc is the 4th kernel (ncu -s5 -c1 target)
    zero_detect_kernel<<<(NN + 255) / 256, 256>>>(ei);          // 1
    cudaEventRecord(evFork, 0);
    wt_kernel<<<(FIN * H1DIM + 255) / 256, 256>>>(W1);          // 2 (main)
    cudaStreamWaitEvent(s2, evFork, 0);
    hist_kernel<<<(ETOT + 255) / 256, 256, 0, s2>>>(ei);        // 3 (aux)
    gemm1_tc_kernel<<<(NN + G1M - 1) / G1M, 256, 87040>>>(x, as1, ad1);  // 4 (main)
    scan1_kernel<<<NBLK, 1024, 0, s2>>>();                      // 5 (aux)
    scan23_kernel<<<NBLK, 1024, 0, s2>>>();                     // 6 (aux)
    scatter_kernel<<<(ETOT + 255) / 256, 256, 0, s2>>>(ei);     // 7 (aux)
    cudaEventRecord(evJoin, s2);

    cudaStreamWaitEvent(0, evJoin, 0);
    agg1_kernel<<<(NN + 7) / 8, 256>>>(b1);                     // 8
    gemm2_tc_kernel<<<(NN + G1M - 1) / G1M, 256>>>(W2, as2, ad2);  // 9
    agg2_kernel<<<(NN + 7) / 8, 256>>>(b2, out);                // 10
}

// round 12
// speedup vs baseline: 2.5705x; 1.0138x over previous
#include <cuda_runtime.h>
#include <cuda_fp16.h>
#include <cstdint>

#define NN    50000
#define EE    800000
#define ETOT  (EE + NN)
#define FIN   128
#define H1DIM 128   // HEADS*HID
#define NHEAD 8
#define CLS   40
#define NEG   0.2f
#define G1M   128   // rows per gemm block
#define NBLK  49    // scan blocks

// ---------------- device scratch (static, allocation-free) ----------------
__device__ __half   g_h1h[(size_t)NN * H1DIM];   // layer-1 messages, fp16
__device__ float    g_hact[(size_t)NN * H1DIM];
__device__ float    g_e1s[NN * NHEAD];
__device__ float    g_e1d[NN * NHEAD];
__device__ float    g_h2[(size_t)NN * CLS];
__device__ float    g_e2s[NN];
__device__ float    g_e2d[NN];
__device__ int      g_rowptr[NN + 1];
__device__ int      g_counts[NN];
__device__ int      g_fill[NN];
__device__ int      g_srcs[ETOT];
__device__ int      g_bsum[64];
__device__ uint32_t g_w1t[FIN * H1DIM];          // tf32 W1, n-major [n*128+k]
__device__ uint32_t g_w2t[CLS * FIN];            // tf32 W2, n-major [n*128+k]
__device__ int      g_is64;

// ---------------- fast exp: pure FFMA/ALU, no MUFU ----------------
__device__ __forceinline__ float fexp(float x) {
    float t = x * 1.442695041f;
    t = fminf(fmaxf(t, -125.f), 125.f);
    float biased = t + 12582912.f;
    int   ni = __float_as_int(biased) - 0x4B400000;
    float n  = biased - 12582912.f;
    float f  = fmaf(-n, 0.69314718056f, x);
    float p  = fmaf(f, 8.3333333e-3f, 4.1666667e-2f);
    p = fmaf(p, f, 0.16666667f);
    p = fmaf(p, f, 0.5f);
    p = fmaf(p, f, 1.0f);
    p = fmaf(p, f, 1.0f);
    return p * __int_as_float((ni + 127) << 23);
}

__device__ __forceinline__ uint32_t f2tf32(float v) {
    uint32_t u;
    asm("cvt.rna.tf32.f32 %0, %1;" : "=r"(u) : "f"(v));
    return u;
}

// ---------------- zero + edge dtype detect (fused) ----------------
__global__ void zero_detect_kernel(const void* ei) {
    int i = blockIdx.x * blockDim.x + threadIdx.x;
    if (i < NN) { g_counts[i] = 0; g_fill[i] = 0; }
    if (blockIdx.x == 0 && threadIdx.x < 32) {
        const long long* e = (const long long*)ei;
        int lane = threadIdx.x;
        int bad = 0;
        for (int j = lane; j < 1024; j += 32) {
            long long v = e[j];
            if (v < 0 || v >= NN) bad = 1;
        }
        unsigned m = __ballot_sync(0xffffffffu, bad);
        if (lane == 0) g_is64 = (m == 0);
    }
}

// ---------------- precompute tf32 n-major W1 and W2 ----------------
__global__ void wt_kernel(const float* __restrict__ W1,
                          const float* __restrict__ W2) {
    int i = blockIdx.x * blockDim.x + threadIdx.x;
    if (i < FIN * H1DIM) {
        int n = i >> 7, k = i & 127;
        g_w1t[i] = f2tf32(W1[k * H1DIM + n]);
    } else if (i < FIN * H1DIM + CLS * FIN) {
        int j = i - FIN * H1DIM;
        int n = j >> 7, k = j & 127;
        g_w2t[j] = f2tf32(W2[k * CLS + n]);
    }
}

// ---------------- hist directly from edge_index ----------------
__global__ void hist_kernel(const void* ei) {
    int i = blockIdx.x * blockDim.x + threadIdx.x;
    if (i >= ETOT) return;
    int d;
    if (i >= EE)          d = i - EE;
    else if (g_is64)      d = (int)((const long long*)ei)[EE + i];
    else                  d = ((const int*)ei)[EE + i];
    atomicAdd(&g_counts[d], 1);
}

// ---------------- hierarchical scan ----------------
__global__ void scan1_kernel() {
    __shared__ int warp_sums[32];
    int tid = threadIdx.x, lane = tid & 31, wid = tid >> 5;
    int idx = blockIdx.x * 1024 + tid;
    int v = (idx < NN) ? g_counts[idx] : 0;
    int xs = v;
#pragma unroll
    for (int off = 1; off < 32; off <<= 1) {
        int y = __shfl_up_sync(0xffffffffu, xs, off);
        if (lane >= off) xs += y;
    }
    if (lane == 31) warp_sums[wid] = xs;
    __syncthreads();
    if (wid == 0) {
        int ws = warp_sums[lane];
#pragma unroll
        for (int off = 1; off < 32; off <<= 1) {
            int y = __shfl_up_sync(0xffffffffu, ws, off);
            if (lane >= off) ws += y;
        }
        warp_sums[lane] = ws;
    }
    __syncthreads();
    int incl = xs + ((wid > 0) ? warp_sums[wid - 1] : 0);
    if (idx < NN) g_rowptr[idx + 1] = incl;
    if (tid == 1023) g_bsum[blockIdx.x] = incl;
}

__global__ void scan23_kernel() {
    __shared__ int soff;
    int tid = threadIdx.x;
    if (tid < 32) {
        int b = blockIdx.x;
        int c = 0;
        if (tid < b)      c += g_bsum[tid];
        if (tid + 32 < b) c += g_bsum[tid + 32];
#pragma unroll
        for (int off = 16; off > 0; off >>= 1)
            c += __shfl_down_sync(0xffffffffu, c, off);
        if (tid == 0) soff = c;
    }
    __syncthreads();
    int idx = blockIdx.x * 1024 + tid;
    if (idx < NN) g_rowptr[idx + 1] += soff;
    if (idx == 0) g_rowptr[0] = 0;
}

__global__ void scatter_kernel(const void* ei) {
    int i = blockIdx.x * blockDim.x + threadIdx.x;
    if (i >= ETOT) return;
    int s, d;
    if (i >= EE) {
        s = d = i - EE;
    } else if (g_is64) {
        const long long* e = (const long long*)ei;
        s = (int)e[i]; d = (int)e[EE + i];
    } else {
        const int* e = (const int*)ei;
        s = e[i]; d = e[EE + i];
    }
    int pos = g_rowptr[d] + atomicAdd(&g_fill[d], 1);
    g_srcs[pos] = s;
}

// ---------------- GEMM1 tensor cores, N-split halves, fused e1 ------------
// grid = 782: blockIdx>>1 = row tile (128 rows), blockIdx&1 = N-half (64 cols)
__global__ void __launch_bounds__(256, 3) gemm1_tc_kernel(
        const float* __restrict__ x,
        const float* __restrict__ as1, const float* __restrict__ ad1) {
    extern __shared__ uint32_t sm[];
    uint32_t* Ws = sm;                    // [n*132 + k], 64 rows
    uint32_t* Xs = sm + 64 * 132;         // [row*36 + k]
    float* sa = (float*)(sm + 64 * 132 + 128 * 36);   // 64
    float* sd = sa + 64;

    const int tid = threadIdx.x;
    const int wid = tid >> 5, lane = tid & 31;
    const int g = lane >> 2, tk = lane & 3;
    const int tile = blockIdx.x >> 1;
    const int nh = blockIdx.x & 1;
    const int m0 = tile * G1M;
    const int ncol0 = nh * 64;

    // stage W half: pure LDG.128 -> STS.128 (64 n-rows x 128 k)
    {
        const uint4* wt4 = (const uint4*)(g_w1t + ncol0 * FIN);
        for (int i = tid; i < 2048; i += 256) {
            uint4 v = wt4[i];
            int n = i >> 5, k = (i & 31) * 4;
            *(uint4*)&Ws[n * 132 + k] = v;
        }
    }
    if (tid < 64) { sa[tid] = as1[ncol0 + tid]; sd[tid] = ad1[ncol0 + tid]; }

    float acc[8][4];
#pragma unroll
    for (int nt = 0; nt < 8; nt++)
#pragma unroll
        for (int j = 0; j < 4; j++) acc[nt][j] = 0.f;

    // register double-buffer for X chunks
    float4 xp[4];
#pragma unroll
    for (int j = 0; j < 4; j++) {
        int idx = tid + j * 256;
        int row = idx >> 3, k4 = (idx & 7) * 4;
        int gr = m0 + row; if (gr >= NN) gr = NN - 1;
        xp[j] = *(const float4*)&x[(size_t)gr * FIN + k4];
    }

    for (int kc = 0; kc < 4; kc++) {
#pragma unroll
        for (int j = 0; j < 4; j++) {
            int idx = tid + j * 256;
            int row = idx >> 3, k4 = (idx & 7) * 4;
            uint4 t;
            t.x = f2tf32(xp[j].x); t.y = f2tf32(xp[j].y);
            t.z = f2tf32(xp[j].z); t.w = f2tf32(xp[j].w);
            *(uint4*)&Xs[row * 36 + k4] = t;
        }
        __syncthreads();

        if (kc < 3) {
#pragma unroll
            for (int j = 0; j < 4; j++) {
                int idx = tid + j * 256;
                int row = idx >> 3, k4 = (idx & 7) * 4;
                int gr = m0 + row; if (gr >= NN) gr = NN - 1;
                xp[j] = *(const float4*)&x[(size_t)gr * FIN + (kc + 1) * 32 + k4];
            }
        }

#pragma unroll
        for (int ks = 0; ks < 4; ks++) {
            const int kx = ks * 8;
            const int kw = kc * 32 + ks * 8;
            const uint32_t* xa = &Xs[(wid * 16 + g) * 36 + kx + tk];
            uint32_t a0 = xa[0];
            uint32_t a1 = xa[8 * 36];
            uint32_t a2 = xa[4];
            uint32_t a3 = xa[8 * 36 + 4];
#pragma unroll
            for (int nt = 0; nt < 8; nt++) {
                const uint32_t* wb = &Ws[(nt * 8 + g) * 132 + kw + tk];
                uint32_t b0 = wb[0];
                uint32_t b1 = wb[4];
                asm volatile(
                    "mma.sync.aligned.m16n8k8.row.col.f32.tf32.tf32.f32 "
                    "{%0,%1,%2,%3}, {%4,%5,%6,%7}, {%8,%9}, {%0,%1,%2,%3};"
                    : "+f"(acc[nt][0]), "+f"(acc[nt][1]),
                      "+f"(acc[nt][2]), "+f"(acc[nt][3])
                    : "r"(a0), "r"(a1), "r"(a2), "r"(a3), "r"(b0), "r"(b1));
            }
        }
        __syncthreads();
    }

    const int row0 = m0 + wid * 16 + g;
    const int row1 = row0 + 8;
#pragma unroll
    for (int nt = 0; nt < 8; nt++) {
        int col = ncol0 + nt * 8 + 2 * tk;
        if (row0 < NN)
            *(__half2*)&g_h1h[(size_t)row0 * H1DIM + col] =
                __floats2half2_rn(acc[nt][0], acc[nt][1]);
        if (row1 < NN)
            *(__half2*)&g_h1h[(size_t)row1 * H1DIM + col] =
                __floats2half2_rn(acc[nt][2], acc[nt][3]);
    }

#pragma unroll
    for (int hh = 0; hh < 4; hh++) {
        const int h = nh * 4 + hh;
        float es0 = 0.f, ed0 = 0.f, es1 = 0.f, ed1 = 0.f;
#pragma unroll
        for (int q = 0; q < 2; q++) {
            int nt = 2 * hh + q;
            int col = nt * 8 + 2 * tk;     // local column in this half
            float av0 = sa[col], av1 = sa[col + 1];
            float dv0 = sd[col], dv1 = sd[col + 1];
            es0 += acc[nt][0] * av0 + acc[nt][1] * av1;
            ed0 += acc[nt][0] * dv0 + acc[nt][1] * dv1;
            es1 += acc[nt][2] * av0 + acc[nt][3] * av1;
            ed1 += acc[nt][2] * dv0 + acc[nt][3] * dv1;
        }
        es0 += __shfl_down_sync(0xffffffffu, es0, 2);
        es0 += __shfl_down_sync(0xffffffffu, es0, 1);
        ed0 += __shfl_down_sync(0xffffffffu, ed0, 2);
        ed0 += __shfl_down_sync(0xffffffffu, ed0, 1);
        es1 += __shfl_down_sync(0xffffffffu, es1, 2);
        es1 += __shfl_down_sync(0xffffffffu, es1, 1);
        ed1 += __shfl_down_sync(0xffffffffu, ed1, 2);
        ed1 += __shfl_down_sync(0xffffffffu, ed1, 1);
        if (tk == 0) {
            if (row0 < NN) { g_e1s[row0 * NHEAD + h] = es0; g_e1d[row0 * NHEAD + h] = ed0; }
            if (row1 < NN) { g_e1s[row1 * NHEAD + h] = es1; g_e1d[row1 * NHEAD + h] = ed1; }
        }
    }
}

// ---------------- layer-1 aggregation: warp per dst, fp16 gather ----------
__global__ void agg1_kernel(const float* __restrict__ b1) {
    int gw = (blockIdx.x * blockDim.x + threadIdx.x) >> 5;
    int lane = threadIdx.x & 31;
    if (gw >= NN) return;
    const int beg = g_rowptr[gw];
    const int end = g_rowptr[gw + 1];

    const int eh = lane & 7;
    const int sub = lane >> 3;
    const int myhead = lane >> 2;
    const float edh = g_e1d[gw * NHEAD + eh];

    float acc0 = 0.f, acc1 = 0.f, acc2 = 0.f, acc3 = 0.f, ssum = 0.f;
    for (int i = beg; i < end; i += 4) {
        int ei = i + sub;
        int s = 0;
        float w = 0.f;
        if (ei < end) {
            s = g_srcs[ei];
            float a = g_e1s[s * NHEAD + eh] + edh;
            a = a > 0.f ? a : NEG * a;
            w = fexp(a);
        }
#pragma unroll
        for (int j = 0; j < 4; j++) {
            float wj = __shfl_sync(0xffffffffu, w, (j << 3) + myhead);
            int   sj = __shfl_sync(0xffffffffu, s, j << 3);
            if (i + j < end) {
                uint2 hraw = *(const uint2*)(g_h1h + (size_t)sj * H1DIM + lane * 4);
                float2 p0 = __half22float2(*(__half2*)&hraw.x);
                float2 p1 = __half22float2(*(__half2*)&hraw.y);
                acc0 = fmaf(wj, p0.x, acc0);
                acc1 = fmaf(wj, p0.y, acc1);
                acc2 = fmaf(wj, p1.x, acc2);
                acc3 = fmaf(wj, p1.y, acc3);
                ssum += wj;
            }
        }
    }

    float inv = 1.f / (ssum + 1e-16f);
    float4 bv = *(const float4*)(b1 + lane * 4);
    float v0 = acc0 * inv + bv.x;
    float v1 = acc1 * inv + bv.y;
    float v2 = acc2 * inv + bv.z;
    float v3 = acc3 * inv + bv.w;
    v0 = v0 > 0.f ? v0 : (fexp(v0) - 1.f);
    v1 = v1 > 0.f ? v1 : (fexp(v1) - 1.f);
    v2 = v2 > 0.f ? v2 : (fexp(v2) - 1.f);
    v3 = v3 > 0.f ? v3 : (fexp(v3) - 1.f);
    *(float4*)(g_hact + (size_t)gw * H1DIM + lane * 4) = make_float4(v0, v1, v2, v3);
}

// ---------------- GEMM2 tensor cores: h2 = hact @ W2, fused e2 epilogue ---
__global__ void __launch_bounds__(256, 2) gemm2_tc_kernel(
        const float* __restrict__ as2, const float* __restrict__ ad2) {
    __shared__ uint32_t Ws[CLS * 132];
    __shared__ uint32_t Xs[G1M * 36];
    __shared__ float sas[CLS], sad[CLS];

    const int tid = threadIdx.x;
    const int wid = tid >> 5, lane = tid & 31;
    const int g = lane >> 2, tk = lane & 3;
    const int m0 = blockIdx.x * G1M;

    // stage precomputed tf32 W2: pure LDG.128 -> STS.128
    {
        const uint4* wt4 = (const uint4*)g_w2t;
        for (int i = tid; i < 1280; i += 256) {
            uint4 v = wt4[i];
            int n = i >> 5, k = (i & 31) * 4;
            *(uint4*)&Ws[n * 132 + k] = v;
        }
    }
    if (tid < CLS) { sas[tid] = as2[tid]; sad[tid] = ad2[tid]; }

    float acc[5][4];
#pragma unroll
    for (int nt = 0; nt < 5; nt++)
#pragma unroll
        for (int j = 0; j < 4; j++) acc[nt][j] = 0.f;

    float4 xp[4];
#pragma unroll
    for (int j = 0; j < 4; j++) {
        int idx = tid + j * 256;
        int row = idx >> 3, k4 = (idx & 7) * 4;
        int gr = m0 + row; if (gr >= NN) gr = NN - 1;
        xp[j] = *(const float4*)&g_hact[(size_t)gr * FIN + k4];
    }

    for (int kc = 0; kc < 4; kc++) {
#pragma unroll
        for (int j = 0; j < 4; j++) {
            int idx = tid + j * 256;
            int row = idx >> 3, k4 = (idx & 7) * 4;
            uint4 t;
            t.x = f2tf32(xp[j].x); t.y = f2tf32(xp[j].y);
            t.z = f2tf32(xp[j].z); t.w = f2tf32(xp[j].w);
            *(uint4*)&Xs[row * 36 + k4] = t;
        }
        __syncthreads();

        if (kc < 3) {
#pragma unroll
            for (int j = 0; j < 4; j++) {
                int idx = tid + j * 256;
                int row = idx >> 3, k4 = (idx & 7) * 4;
                int gr = m0 + row; if (gr >= NN) gr = NN - 1;
                xp[j] = *(const float4*)&g_hact[(size_t)gr * FIN + (kc + 1) * 32 + k4];
            }
        }

#pragma unroll
        for (int ks = 0; ks < 4; ks++) {
            const int kx = ks * 8;
            const int kw = kc * 32 + ks * 8;
            const uint32_t* xa = &Xs[(wid * 16 + g) * 36 + kx + tk];
            uint32_t a0 = xa[0];
            uint32_t a1 = xa[8 * 36];
            uint32_t a2 = xa[4];
            uint32_t a3 = xa[8 * 36 + 4];
#pragma unroll
            for (int nt = 0; nt < 5; nt++) {
                const uint32_t* wb = &Ws[(nt * 8 + g) * 132 + kw + tk];
                uint32_t b0 = wb[0];
                uint32_t b1 = wb[4];
                asm volatile(
                    "mma.sync.aligned.m16n8k8.row.col.f32.tf32.tf32.f32 "
                    "{%0,%1,%2,%3}, {%4,%5,%6,%7}, {%8,%9}, {%0,%1,%2,%3};"
                    : "+f"(acc[nt][0]), "+f"(acc[nt][1]),
                      "+f"(acc[nt][2]), "+f"(acc[nt][3])
                    : "r"(a0), "r"(a1), "r"(a2), "r"(a3), "r"(b0), "r"(b1));
            }
        }
        __syncthreads();
    }

    const int row0 = m0 + wid * 16 + g;
    const int row1 = row0 + 8;
#pragma unroll
    for (int nt = 0; nt < 5; nt++) {
        int col = nt * 8 + 2 * tk;
        if (row0 < NN)
            *(float2*)&g_h2[(size_t)row0 * CLS + col] =
                make_float2(acc[nt][0], acc[nt][1]);
        if (row1 < NN)
            *(float2*)&g_h2[(size_t)row1 * CLS + col] =
                make_float2(acc[nt][2], acc[nt][3]);
    }

    float es0 = 0.f, ed0 = 0.f, es1 = 0.f, ed1 = 0.f;
#pragma unroll
    for (int nt = 0; nt < 5; nt++) {
        int col = nt * 8 + 2 * tk;
        float av0 = sas[col], av1 = sas[col + 1];
        float dv0 = sad[col], dv1 = sad[col + 1];
        es0 += acc[nt][0] * av0 + acc[nt][1] * av1;
        ed0 += acc[nt][0] * dv0 + acc[nt][1] * dv1;
        es1 += acc[nt][2] * av0 + acc[nt][3] * av1;
        ed1 += acc[nt][2] * dv0 + acc[nt][3] * dv1;
    }
    es0 += __shfl_down_sync(0xffffffffu, es0, 2);
    es0 += __shfl_down_sync(0xffffffffu, es0, 1);
    ed0 += __shfl_down_sync(0xffffffffu, ed0, 2);
    ed0 += __shfl_down_sync(0xffffffffu, ed0, 1);
    es1 += __shfl_down_sync(0xffffffffu, es1, 2);
    es1 += __shfl_down_sync(0xffffffffu, es1, 1);
    ed1 += __shfl_down_sync(0xffffffffu, ed1, 2);
    ed1 += __shfl_down_sync(0xffffffffu, ed1, 1);
    if (tk == 0) {
        if (row0 < NN) { g_e2s[row0] = es0; g_e2d[row0] = ed0; }
        if (row1 < NN) { g_e2s[row1] = es1; g_e2d[row1] = ed1; }
    }
}

// ---------------- layer-2 aggregation: warp per dst, 4-edge batched -------
__global__ void agg2_kernel(const float* __restrict__ b2, float* __restrict__ out) {
    int gw = (blockIdx.x * blockDim.x + threadIdx.x) >> 5;
    int lane = threadIdx.x & 31;
    if (gw >= NN) return;
    const int beg = g_rowptr[gw];
    const int end = g_rowptr[gw + 1];
    const float edn = g_e2d[gw];

    float acc0 = 0.f, acc1 = 0.f, ss = 0.f;
    for (int i = beg; i < end; i += 4) {
        int ei = i + (lane & 3);
        int s = 0;
        float w = 0.f;
        if (ei < end) {
            s = g_srcs[ei];
            float a = g_e2s[s] + edn;
            a = a > 0.f ? a : NEG * a;
            w = fexp(a);
        }
#pragma unroll
        for (int j = 0; j < 4; j++) {
            float wj = __shfl_sync(0xffffffffu, w, j);
            int   sj = __shfl_sync(0xffffffffu, s, j);
            if (i + j < end) {
                acc0 = fmaf(wj, g_h2[(size_t)sj * CLS + lane], acc0);
                if (lane < 8)
                    acc1 = fmaf(wj, g_h2[(size_t)sj * CLS + 32 + lane], acc1);
                ss += wj;
            }
        }
    }
    float inv = 1.f / (ss + 1e-16f);
    out[(size_t)gw * CLS + lane] = acc0 * inv + __ldg(&b2[lane]);
    if (lane < 8)
        out[(size_t)gw * CLS + 32 + lane] = acc1 * inv + __ldg(&b2[32 + lane]);
}

// ---------------- launch ----------------
extern "C" void kernel_launch(void* const* d_in, const int* in_sizes, int n_in,
                              void* d_out, int out_size) {
    const float* x   = (const float*)d_in[0];
    const void*  ei  = d_in[1];
    const float* W1  = (const float*)d_in[2];
    const float* as1 = (const float*)d_in[3];
    const float* ad1 = (const float*)d_in[4];
    const float* b1  = (const float*)d_in[5];
    const float* W2  = (const float*)d_in[6];
    const float* as2 = (const float*)d_in[7];
    const float* ad2 = (const float*)d_in[8];
    const float* b2  = (const float*)d_in[9];
    float* out = (float*)d_out;

    static cudaStream_t s2 = nullptr;
    static cudaEvent_t evFork = nullptr, evJoin = nullptr;
    if (s2 == nullptr) {
        cudaFuncSetAttribute(gemm1_tc_kernel,
                             cudaFuncAttributeMaxDynamicSharedMemorySize, 53248);
        cudaStreamCreateWithFlags(&s2, cudaStreamNonBlocking);
        cudaEventCreateWithFlags(&evFork, cudaEventDisableTiming);
        cudaEventCreateWithFlags(&evJoin, cudaEventDisableTiming);
    }

    // submission order keeps gemm1_tc as the 4th kernel (ncu -s5 -c1 target)
    zero_detect_kernel<<<(NN + 255) / 256, 256>>>(ei);          // 1
    cudaEventRecord(evFork, 0);
    wt_kernel<<<(FIN * H1DIM + CLS * FIN + 255) / 256, 256>>>(W1, W2);  // 2
    cudaStreamWaitEvent(s2, evFork, 0);
    hist_kernel<<<(ETOT + 255) / 256, 256, 0, s2>>>(ei);        // 3 (aux)
    gemm1_tc_kernel<<<2 * ((NN + G1M - 1) / G1M), 256, 53248>>>(x, as1, ad1);  // 4
    scan1_kernel<<<NBLK, 1024, 0, s2>>>();                      // 5 (aux)
    scan23_kernel<<<NBLK, 1024, 0, s2>>>();                     // 6 (aux)
    scatter_kernel<<<(ETOT + 255) / 256, 256, 0, s2>>>(ei);     // 7 (aux)
    cudaEventRecord(evJoin, s2);

    cudaStreamWaitEvent(0, evJoin, 0);
    agg1_kernel<<<(NN + 7) / 8, 256>>>(b1);                     // 8
    gemm2_tc_kernel<<<(NN + G1M - 1) / G1M, 256>>>(as2, ad2);   // 9
    agg2_kernel<<<(NN + 7) / 8, 256>>>(b2, out);                // 10
}

// round 13
// speedup vs baseline: 2.7607x; 1.0740x over previous
#include <cuda_runtime.h>
#include <cuda_fp16.h>
#include <cstdint>

#define NN    50000
#define EE    800000
#define ETOT  (EE + NN)
#define FIN   128
#define H1DIM 128   // HEADS*HID
#define NHEAD 8
#define CLS   40
#define NEG   0.2f
#define G1M   128   // rows per gemm block
#define NBLK  49    // scan blocks
#define WPAD  68    // smem word stride (68 mod 32 == 4 -> conflict-free frags)

// ---------------- device scratch (static, allocation-free) ----------------
__device__ __half   g_h1h[(size_t)NN * H1DIM];    // layer-1 messages, fp16
__device__ __half   g_hacth[(size_t)NN * H1DIM];  // ELU output, fp16
__device__ float    g_e1s[NN * NHEAD];
__device__ float    g_e1d[NN * NHEAD];
__device__ float    g_h2[(size_t)NN * CLS];
__device__ float    g_e2s[NN];
__device__ float    g_e2d[NN];
__device__ int      g_rowptr[NN + 1];
__device__ int      g_counts[NN];
__device__ int      g_fill[NN];
__device__ int      g_srcs[ETOT];
__device__ int      g_bsum[64];
__device__ uint32_t g_w1h[H1DIM * 64];   // W1 half2-packed, n-major: [n*64 + k/2]
__device__ uint32_t g_w2h[CLS * 64];     // W2 half2-packed, n-major
__device__ int      g_is64;

// ---------------- fast exp: pure FFMA/ALU, no MUFU ----------------
__device__ __forceinline__ float fexp(float x) {
    float t = x * 1.442695041f;
    t = fminf(fmaxf(t, -125.f), 125.f);
    float biased = t + 12582912.f;
    int   ni = __float_as_int(biased) - 0x4B400000;
    float n  = biased - 12582912.f;
    float f  = fmaf(-n, 0.69314718056f, x);
    float p  = fmaf(f, 8.3333333e-3f, 4.1666667e-2f);
    p = fmaf(p, f, 0.16666667f);
    p = fmaf(p, f, 0.5f);
    p = fmaf(p, f, 1.0f);
    p = fmaf(p, f, 1.0f);
    return p * __int_as_float((ni + 127) << 23);
}

__device__ __forceinline__ uint32_t pack_h2(float a, float b) {
    __half2 h = __floats2half2_rn(a, b);
    return *(uint32_t*)&h;
}

// ---------------- zero + edge dtype detect (fused) ----------------
__global__ void zero_detect_kernel(const void* ei) {
    int i = blockIdx.x * blockDim.x + threadIdx.x;
    if (i < NN) { g_counts[i] = 0; g_fill[i] = 0; }
    if (blockIdx.x == 0 && threadIdx.x < 32) {
        const long long* e = (const long long*)ei;
        int lane = threadIdx.x;
        int bad = 0;
        for (int j = lane; j < 1024; j += 32) {
            long long v = e[j];
            if (v < 0 || v >= NN) bad = 1;
        }
        unsigned m = __ballot_sync(0xffffffffu, bad);
        if (lane == 0) g_is64 = (m == 0);
    }
}

// ---------------- precompute half2-packed n-major W1 and W2 ----------------
__global__ void wt_kernel(const float* __restrict__ W1,
                          const float* __restrict__ W2) {
    int i = blockIdx.x * blockDim.x + threadIdx.x;
    if (i < H1DIM * 64) {
        int n = i >> 6, j = i & 63;
        g_w1h[i] = pack_h2(W1[(2 * j) * H1DIM + n], W1[(2 * j + 1) * H1DIM + n]);
    } else if (i < H1DIM * 64 + CLS * 64) {
        int q = i - H1DIM * 64;
        int n = q >> 6, j = q & 63;
        g_w2h[q] = pack_h2(W2[(2 * j) * CLS + n], W2[(2 * j + 1) * CLS + n]);
    }
}

// ---------------- hist directly from edge_index ----------------
__global__ void hist_kernel(const void* ei) {
    int i = blockIdx.x * blockDim.x + threadIdx.x;
    if (i >= ETOT) return;
    int d;
    if (i >= EE)          d = i - EE;
    else if (g_is64)      d = (int)((const long long*)ei)[EE + i];
    else                  d = ((const int*)ei)[EE + i];
    atomicAdd(&g_counts[d], 1);
}

// ---------------- hierarchical scan ----------------
__global__ void scan1_kernel() {
    __shared__ int warp_sums[32];
    int tid = threadIdx.x, lane = tid & 31, wid = tid >> 5;
    int idx = blockIdx.x * 1024 + tid;
    int v = (idx < NN) ? g_counts[idx] : 0;
    int xs = v;
#pragma unroll
    for (int off = 1; off < 32; off <<= 1) {
        int y = __shfl_up_sync(0xffffffffu, xs, off);
        if (lane >= off) xs += y;
    }
    if (lane == 31) warp_sums[wid] = xs;
    __syncthreads();
    if (wid == 0) {
        int ws = warp_sums[lane];
#pragma unroll
        for (int off = 1; off < 32; off <<= 1) {
            int y = __shfl_up_sync(0xffffffffu, ws, off);
            if (lane >= off) ws += y;
        }
        warp_sums[lane] = ws;
    }
    __syncthreads();
    int incl = xs + ((wid > 0) ? warp_sums[wid - 1] : 0);
    if (idx < NN) g_rowptr[idx + 1] = incl;
    if (tid == 1023) g_bsum[blockIdx.x] = incl;
}

__global__ void scan23_kernel() {
    __shared__ int soff;
    int tid = threadIdx.x;
    if (tid < 32) {
        int b = blockIdx.x;
        int c = 0;
        if (tid < b)      c += g_bsum[tid];
        if (tid + 32 < b) c += g_bsum[tid + 32];
#pragma unroll
        for (int off = 16; off > 0; off >>= 1)
            c += __shfl_down_sync(0xffffffffu, c, off);
        if (tid == 0) soff = c;
    }
    __syncthreads();
    int idx = blockIdx.x * 1024 + tid;
    if (idx < NN) g_rowptr[idx + 1] += soff;
    if (idx == 0) g_rowptr[0] = 0;
}

__global__ void scatter_kernel(const void* ei) {
    int i = blockIdx.x * blockDim.x + threadIdx.x;
    if (i >= ETOT) return;
    int s, d;
    if (i >= EE) {
        s = d = i - EE;
    } else if (g_is64) {
        const long long* e = (const long long*)ei;
        s = (int)e[i]; d = (int)e[EE + i];
    } else {
        const int* e = (const int*)ei;
        s = e[i]; d = e[EE + i];
    }
    int pos = g_rowptr[d] + atomicAdd(&g_fill[d], 1);
    g_srcs[pos] = s;
}

// ---------------- GEMM1 fp16 tensor cores, N-split, full-K resident -------
// grid = 782: blockIdx>>1 = row tile (128 rows), blockIdx&1 = N-half (64 cols)
// mma.m16n8k16: per k-step j0=8*ks words. A word (row, j0+tk | +4),
// B word (n, j0+tk | +4). Stride WPAD=68 -> bank (4*row+tk) conflict-free.
__global__ void __launch_bounds__(256, 3) gemm1_tc_kernel(
        const float* __restrict__ x,
        const float* __restrict__ as1, const float* __restrict__ ad1) {
    extern __shared__ uint32_t sm[];
    uint32_t* Ws = sm;                     // [n*68 + j], 64 n-rows
    uint32_t* Xs = sm + 64 * WPAD;         // [row*68 + j], 128 rows
    float* sa = (float*)(sm + 64 * WPAD + 128 * WPAD);   // 64
    float* sd = sa + 64;

    const int tid = threadIdx.x;
    const int wid = tid >> 5, lane = tid & 31;
    const int g = lane >> 2, tk = lane & 3;
    const int tile = blockIdx.x >> 1;
    const int nh = blockIdx.x & 1;
    const int m0 = tile * G1M;
    const int ncol0 = nh * 64;

    // stage W half (precomputed half2 n-major): pure LDG.128 -> STS.128
    {
        const uint4* wt4 = (const uint4*)(g_w1h + ncol0 * 64);
        for (int i = tid; i < 64 * 16; i += 256) {
            uint4 v = wt4[i];
            int n = i >> 4, j = (i & 15) * 4;
            *(uint4*)&Ws[n * WPAD + j] = v;
        }
    }
    if (tid < 64) { sa[tid] = as1[ncol0 + tid]; sd[tid] = ad1[ncol0 + tid]; }

    // stage X full K=128 (f32 -> half2 on the fly): 128 rows x 64 words
    for (int i = tid; i < 2048; i += 256) {        // uint4 units
        int row = i >> 4, j4 = (i & 15) * 4;       // words j4..j4+3 = k 2*j4..
        int gr = m0 + row; if (gr >= NN) gr = NN - 1;
        const float4* xr = (const float4*)&x[(size_t)gr * FIN + j4 * 2];
        float4 lo = xr[0], hi = xr[1];
        uint4 t;
        t.x = pack_h2(lo.x, lo.y); t.y = pack_h2(lo.z, lo.w);
        t.z = pack_h2(hi.x, hi.y); t.w = pack_h2(hi.z, hi.w);
        *(uint4*)&Xs[row * WPAD + j4] = t;
    }
    __syncthreads();

    float acc[8][4];
#pragma unroll
    for (int nt = 0; nt < 8; nt++)
#pragma unroll
        for (int j = 0; j < 4; j++) acc[nt][j] = 0.f;

#pragma unroll
    for (int ks = 0; ks < 8; ks++) {
        const int j0 = ks * 8;
        const uint32_t* xa = &Xs[(wid * 16 + g) * WPAD + j0 + tk];
        uint32_t a0 = xa[0];
        uint32_t a1 = xa[8 * WPAD];
        uint32_t a2 = xa[4];
        uint32_t a3 = xa[8 * WPAD + 4];
#pragma unroll
        for (int nt = 0; nt < 8; nt++) {
            const uint32_t* wb = &Ws[(nt * 8 + g) * WPAD + j0 + tk];
            uint32_t b0 = wb[0];
            uint32_t b1 = wb[4];
            asm volatile(
                "mma.sync.aligned.m16n8k16.row.col.f32.f16.f16.f32 "
                "{%0,%1,%2,%3}, {%4,%5,%6,%7}, {%8,%9}, {%0,%1,%2,%3};"
                : "+f"(acc[nt][0]), "+f"(acc[nt][1]),
                  "+f"(acc[nt][2]), "+f"(acc[nt][3])
                : "r"(a0), "r"(a1), "r"(a2), "r"(a3), "r"(b0), "r"(b1));
        }
    }

    const int row0 = m0 + wid * 16 + g;
    const int row1 = row0 + 8;
#pragma unroll
    for (int nt = 0; nt < 8; nt++) {
        int col = ncol0 + nt * 8 + 2 * tk;
        if (row0 < NN) {
            uint32_t p = pack_h2(acc[nt][0], acc[nt][1]);
            *(uint32_t*)&g_h1h[(size_t)row0 * H1DIM + col] = p;
        }
        if (row1 < NN) {
            uint32_t p = pack_h2(acc[nt][2], acc[nt][3]);
            *(uint32_t*)&g_h1h[(size_t)row1 * H1DIM + col] = p;
        }
    }

#pragma unroll
    for (int hh = 0; hh < 4; hh++) {
        const int h = nh * 4 + hh;
        float es0 = 0.f, ed0 = 0.f, es1 = 0.f, ed1 = 0.f;
#pragma unroll
        for (int q = 0; q < 2; q++) {
            int nt = 2 * hh + q;
            int col = nt * 8 + 2 * tk;
            float av0 = sa[col], av1 = sa[col + 1];
            float dv0 = sd[col], dv1 = sd[col + 1];
            es0 += acc[nt][0] * av0 + acc[nt][1] * av1;
            ed0 += acc[nt][0] * dv0 + acc[nt][1] * dv1;
            es1 += acc[nt][2] * av0 + acc[nt][3] * av1;
            ed1 += acc[nt][2] * dv0 + acc[nt][3] * dv1;
        }
        es0 += __shfl_down_sync(0xffffffffu, es0, 2);
        es0 += __shfl_down_sync(0xffffffffu, es0, 1);
        ed0 += __shfl_down_sync(0xffffffffu, ed0, 2);
        ed0 += __shfl_down_sync(0xffffffffu, ed0, 1);
        es1 += __shfl_down_sync(0xffffffffu, es1, 2);
        es1 += __shfl_down_sync(0xffffffffu, es1, 1);
        ed1 += __shfl_down_sync(0xffffffffu, ed1, 2);
        ed1 += __shfl_down_sync(0xffffffffu, ed1, 1);
        if (tk == 0) {
            if (row0 < NN) { g_e1s[row0 * NHEAD + h] = es0; g_e1d[row0 * NHEAD + h] = ed0; }
            if (row1 < NN) { g_e1s[row1 * NHEAD + h] = es1; g_e1d[row1 * NHEAD + h] = ed1; }
        }
    }
}

// ---------------- layer-1 aggregation: warp per dst, fp16 gather ----------
__global__ void agg1_kernel(const float* __restrict__ b1) {
    int gw = (blockIdx.x * blockDim.x + threadIdx.x) >> 5;
    int lane = threadIdx.x & 31;
    if (gw >= NN) return;
    const int beg = g_rowptr[gw];
    const int end = g_rowptr[gw + 1];

    const int eh = lane & 7;
    const int sub = lane >> 3;
    const int myhead = lane >> 2;
    const float edh = g_e1d[gw * NHEAD + eh];

    float acc0 = 0.f, acc1 = 0.f, acc2 = 0.f, acc3 = 0.f, ssum = 0.f;
    for (int i = beg; i < end; i += 4) {
        int ei = i + sub;
        int s = 0;
        float w = 0.f;
        if (ei < end) {
            s = g_srcs[ei];
            float a = g_e1s[s * NHEAD + eh] + edh;
            a = a > 0.f ? a : NEG * a;
            w = fexp(a);
        }
#pragma unroll
        for (int j = 0; j < 4; j++) {
            float wj = __shfl_sync(0xffffffffu, w, (j << 3) + myhead);
            int   sj = __shfl_sync(0xffffffffu, s, j << 3);
            if (i + j < end) {
                uint2 hraw = *(const uint2*)(g_h1h + (size_t)sj * H1DIM + lane * 4);
                float2 p0 = __half22float2(*(__half2*)&hraw.x);
                float2 p1 = __half22float2(*(__half2*)&hraw.y);
                acc0 = fmaf(wj, p0.x, acc0);
                acc1 = fmaf(wj, p0.y, acc1);
                acc2 = fmaf(wj, p1.x, acc2);
                acc3 = fmaf(wj, p1.y, acc3);
                ssum += wj;
            }
        }
    }

    float inv = 1.f / (ssum + 1e-16f);
    float4 bv = *(const float4*)(b1 + lane * 4);
    float v0 = acc0 * inv + bv.x;
    float v1 = acc1 * inv + bv.y;
    float v2 = acc2 * inv + bv.z;
    float v3 = acc3 * inv + bv.w;
    v0 = v0 > 0.f ? v0 : (fexp(v0) - 1.f);
    v1 = v1 > 0.f ? v1 : (fexp(v1) - 1.f);
    v2 = v2 > 0.f ? v2 : (fexp(v2) - 1.f);
    v3 = v3 > 0.f ? v3 : (fexp(v3) - 1.f);
    uint2 o;
    o.x = pack_h2(v0, v1);
    o.y = pack_h2(v2, v3);
    *(uint2*)&g_hacth[(size_t)gw * H1DIM + lane * 4] = o;
}

// ---------------- GEMM2 fp16 tensor cores, full-K resident, fused e2 ------
__global__ void __launch_bounds__(256, 3) gemm2_tc_kernel(
        const float* __restrict__ as2, const float* __restrict__ ad2) {
    __shared__ uint32_t Ws[CLS * WPAD];    // ~10.9KB
    __shared__ uint32_t Xs[G1M * WPAD];    // ~34.8KB
    __shared__ float sas[CLS], sad[CLS];

    const int tid = threadIdx.x;
    const int wid = tid >> 5, lane = tid & 31;
    const int g = lane >> 2, tk = lane & 3;
    const int m0 = blockIdx.x * G1M;

    // stage W2 (precomputed half2 n-major)
    {
        const uint4* wt4 = (const uint4*)g_w2h;
        for (int i = tid; i < CLS * 16; i += 256) {
            uint4 v = wt4[i];
            int n = i >> 4, j = (i & 15) * 4;
            *(uint4*)&Ws[n * WPAD + j] = v;
        }
    }
    if (tid < CLS) { sas[tid] = as2[tid]; sad[tid] = ad2[tid]; }

    // stage X: pure LDG.128 -> STS.128 (hact already fp16)
    for (int i = tid; i < 2048; i += 256) {
        int row = i >> 4, j4 = (i & 15) * 4;
        int gr = m0 + row; if (gr >= NN) gr = NN - 1;
        uint4 v = *(const uint4*)&g_hacth[(size_t)gr * FIN + j4 * 2];
        *(uint4*)&Xs[row * WPAD + j4] = v;
    }
    __syncthreads();

    float acc[5][4];
#pragma unroll
    for (int nt = 0; nt < 5; nt++)
#pragma unroll
        for (int j = 0; j < 4; j++) acc[nt][j] = 0.f;

#pragma unroll
    for (int ks = 0; ks < 8; ks++) {
        const int j0 = ks * 8;
        const uint32_t* xa = &Xs[(wid * 16 + g) * WPAD + j0 + tk];
        uint32_t a0 = xa[0];
        uint32_t a1 = xa[8 * WPAD];
        uint32_t a2 = xa[4];
        uint32_t a3 = xa[8 * WPAD + 4];
#pragma unroll
        for (int nt = 0; nt < 5; nt++) {
            const uint32_t* wb = &Ws[(nt * 8 + g) * WPAD + j0 + tk];
            uint32_t b0 = wb[0];
            uint32_t b1 = wb[4];
            asm volatile(
                "mma.sync.aligned.m16n8k16.row.col.f32.f16.f16.f32 "
                "{%0,%1,%2,%3}, {%4,%5,%6,%7}, {%8,%9}, {%0,%1,%2,%3};"
                : "+f"(acc[nt][0]), "+f"(acc[nt][1]),
                  "+f"(acc[nt][2]), "+f"(acc[nt][3])
                : "r"(a0), "r"(a1), "r"(a2), "r"(a3), "r"(b0), "r"(b1));
        }
    }

    const int row0 = m0 + wid * 16 + g;
    const int row1 = row0 + 8;
#pragma unroll
    for (int nt = 0; nt < 5; nt++) {
        int col = nt * 8 + 2 * tk;
        if (row0 < NN)
            *(float2*)&g_h2[(size_t)row0 * CLS + col] =
                make_float2(acc[nt][0], acc[nt][1]);
        if (row1 < NN)
            *(float2*)&g_h2[(size_t)row1 * CLS + col] =
                make_float2(acc[nt][2], acc[nt][3]);
    }

    float es0 = 0.f, ed0 = 0.f, es1 = 0.f, ed1 = 0.f;
#pragma unroll
    for (int nt = 0; nt < 5; nt++) {
        int col = nt * 8 + 2 * tk;
        float av0 = sas[col], av1 = sas[col + 1];
        float dv0 = sad[col], dv1 = sad[col + 1];
        es0 += acc[nt][0] * av0 + acc[nt][1] * av1;
        ed0 += acc[nt][0] * dv0 + acc[nt][1] * dv1;
        es1 += acc[nt][2] * av0 + acc[nt][3] * av1;
        ed1 += acc[nt][2] * dv0 + acc[nt][3] * dv1;
    }
    es0 += __shfl_down_sync(0xffffffffu, es0, 2);
    es0 += __shfl_down_sync(0xffffffffu, es0, 1);
    ed0 += __shfl_down_sync(0xffffffffu, ed0, 2);
    ed0 += __shfl_down_sync(0xffffffffu, ed0, 1);
    es1 += __shfl_down_sync(0xffffffffu, es1, 2);
    es1 += __shfl_down_sync(0xffffffffu, es1, 1);
    ed1 += __shfl_down_sync(0xffffffffu, ed1, 2);
    ed1 += __shfl_down_sync(0xffffffffu, ed1, 1);
    if (tk == 0) {
        if (row0 < NN) { g_e2s[row0] = es0; g_e2d[row0] = ed0; }
        if (row1 < NN) { g_e2s[row1] = es1; g_e2d[row1] = ed1; }
    }
}

// ---------------- layer-2 aggregation: warp per dst, 4-edge batched -------
__global__ void agg2_kernel(const float* __restrict__ b2, float* __restrict__ out) {
    int gw = (blockIdx.x * blockDim.x + threadIdx.x) >> 5;
    int lane = threadIdx.x & 31;
    if (gw >= NN) return;
    const int beg = g_rowptr[gw];
    const int end = g_rowptr[gw + 1];
    const float edn = g_e2d[gw];

    float acc0 = 0.f, acc1 = 0.f, ss = 0.f;
    for (int i = beg; i < end; i += 4) {
        int ei = i + (lane & 3);
        int s = 0;
        float w = 0.f;
        if (ei < end) {
            s = g_srcs[ei];
            float a = g_e2s[s] + edn;
            a = a > 0.f ? a : NEG * a;
            w = fexp(a);
        }
#pragma unroll
        for (int j = 0; j < 4; j++) {
            float wj = __shfl_sync(0xffffffffu, w, j);
            int   sj = __shfl_sync(0xffffffffu, s, j);
            if (i + j < end) {
                acc0 = fmaf(wj, g_h2[(size_t)sj * CLS + lane], acc0);
                if (lane < 8)
                    acc1 = fmaf(wj, g_h2[(size_t)sj * CLS + 32 + lane], acc1);
                ss += wj;
            }
        }
    }
    float inv = 1.f / (ss + 1e-16f);
    out[(size_t)gw * CLS + lane] = acc0 * inv + __ldg(&b2[lane]);
    if (lane < 8)
        out[(size_t)gw * CLS + 32 + lane] = acc1 * inv + __ldg(&b2[32 + lane]);
}

// ---------------- launch ----------------
extern "C" void kernel_launch(void* const* d_in, const int* in_sizes, int n_in,
                              void* d_out, int out_size) {
    const float* x   = (const float*)d_in[0];
    const void*  ei  = d_in[1];
    const float* W1  = (const float*)d_in[2];
    const float* as1 = (const float*)d_in[3];
    const float* ad1 = (const float*)d_in[4];
    const float* b1  = (const float*)d_in[5];
    const float* W2  = (const float*)d_in[6];
    const float* as2 = (const float*)d_in[7];
    const float* ad2 = (const float*)d_in[8];
    const float* b2  = (const float*)d_in[9];
    float* out = (float*)d_out;

    static cudaStream_t s2 = nullptr;
    static cudaEvent_t evFork = nullptr, evJoin = nullptr;
    if (s2 == nullptr) {
        cudaFuncSetAttribute(gemm1_tc_kernel,
                             cudaFuncAttributeMaxDynamicSharedMemorySize, 53248);
        cudaStreamCreateWithFlags(&s2, cudaStreamNonBlocking);
        cudaEventCreateWithFlags(&evFork, cudaEventDisableTiming);
        cudaEventCreateWithFlags(&evJoin, cudaEventDisableTiming);
    }

    // submission order keeps gemm1_tc as the 4th kernel (ncu -s5 -c1 target)
    zero_detect_kernel<<<(NN + 255) / 256, 256>>>(ei);          // 1
    cudaEventRecord(evFork, 0);
    wt_kernel<<<(H1DIM * 64 + CLS * 64 + 255) / 256, 256>>>(W1, W2);  // 2
    cudaStreamWaitEvent(s2, evFork, 0);
    hist_kernel<<<(ETOT + 255) / 256, 256, 0, s2>>>(ei);        // 3 (aux)
    gemm1_tc_kernel<<<2 * ((NN + G1M - 1) / G1M), 256, 53248>>>(x, as1, ad1);  // 4
    scan1_kernel<<<NBLK, 1024, 0, s2>>>();                      // 5 (aux)
    scan23_kernel<<<NBLK, 1024, 0, s2>>>();                     // 6 (aux)
    scatter_kernel<<<(ETOT + 255) / 256, 256, 0, s2>>>(ei);     // 7 (aux)
    cudaEventRecord(evJoin, s2);

    cudaStreamWaitEvent(0, evJoin, 0);
    agg1_kernel<<<(NN + 7) / 8, 256>>>(b1);                     // 8
    gemm2_tc_kernel<<<(NN + G1M - 1) / G1M, 256>>>(as2, ad2);   // 9
    agg2_kernel<<<(NN + 7) / 8, 256>>>(b2, out);                // 10
}